// round 12
// baseline (speedup 1.0000x reference)
#include <cuda_runtime.h>
#include <cuda_bf16.h>
#include <cuda_fp16.h>
#include <math.h>
#include <cstdint>

#define NN 35000
#define NM 80000
#define NBR 6
#define IND 128
#define HD 256
#define DEPTH 5
#define NNP 35072

// ---------------- scratch (__device__ globals; no allocs) ----------------
__device__ float g_hA  [(size_t)NM*HD];
__device__ float g_nei [(size_t)NNP*HD];
__device__ __align__(16) __half g_fz16 [(size_t)NM*HD];
__device__ __align__(16) __half g_fh16 [(size_t)NM*HD];
__device__ __align__(16) __half g_hU16[(size_t)NM*HD];
__device__ __align__(16) __half g_rx16[(size_t)NM*HD];
// fp16 transposed weights for the GRU-step GEMMs: [256,256]
__device__ __align__(16) __half g_wz16[65536];
__device__ __align__(16) __half g_wh16[65536];

// transposed+split bf16 weights (hi/lo planes): inv3 / hU / mode2
#define OFF_WZT 0
#define OFF_WHT 32768
#define OFF_WR  65536
#define OFF_WOT 98304
#define OFF_UR  131072
#define OFF_WOB 196608
__device__ __align__(16) __nv_bfloat16 g_bh[262144];
__device__ __align__(16) __nv_bfloat16 g_bl[262144];

__device__ __forceinline__ float sigm(float x){ return 1.0f/(1.0f+expf(-x)); }

// ---------------- mma / ldmatrix / cp.async helpers ----------------------
__device__ __forceinline__ uint32_t smem_addr(const void* p){
    return (uint32_t)__cvta_generic_to_shared(p);
}
__device__ __forceinline__ void ldsm4(uint32_t a, uint32_t& r0, uint32_t& r1,
                                      uint32_t& r2, uint32_t& r3){
    asm volatile("ldmatrix.sync.aligned.m8n8.x4.shared.b16 {%0,%1,%2,%3}, [%4];"
                 : "=r"(r0), "=r"(r1), "=r"(r2), "=r"(r3) : "r"(a));
}
__device__ __forceinline__ void mma16816(float* c, const uint32_t* a, const uint32_t* b){
    asm volatile(
        "mma.sync.aligned.m16n8k16.row.col.f32.bf16.bf16.f32 "
        "{%0,%1,%2,%3}, {%4,%5,%6,%7}, {%8,%9}, {%0,%1,%2,%3};"
        : "+f"(c[0]), "+f"(c[1]), "+f"(c[2]), "+f"(c[3])
        : "r"(a[0]), "r"(a[1]), "r"(a[2]), "r"(a[3]), "r"(b[0]), "r"(b[1]));
}
__device__ __forceinline__ void mma16816h(float* c, const uint32_t* a, const uint32_t* b){
    asm volatile(
        "mma.sync.aligned.m16n8k16.row.col.f32.f16.f16.f32 "
        "{%0,%1,%2,%3}, {%4,%5,%6,%7}, {%8,%9}, {%0,%1,%2,%3};"
        : "+f"(c[0]), "+f"(c[1]), "+f"(c[2]), "+f"(c[3])
        : "r"(a[0]), "r"(a[1]), "r"(a[2]), "r"(a[3]), "r"(b[0]), "r"(b[1]));
}
#define CPA16(dst, src) \
    asm volatile("cp.async.cg.shared.global [%0], [%1], 16;" :: "r"(dst), "l"(src))
#define CP_COMMIT() asm volatile("cp.async.commit_group;" ::: "memory")
#define CP_WAIT0()  asm volatile("cp.async.wait_group 0;" ::: "memory")
#define CP_WAIT1()  asm volatile("cp.async.wait_group 1;" ::: "memory")

__device__ __forceinline__ void cvt_split8(float4 v0, float4 v1, uint4& hi, uint4& lo){
    float f[8] = {v0.x,v0.y,v0.z,v0.w,v1.x,v1.y,v1.z,v1.w};
    uint32_t hh[8], ll[8];
    #pragma unroll
    for (int j = 0; j < 8; ++j) {
        __nv_bfloat16 h = __float2bfloat16_rn(f[j]);
        float hf = __bfloat162float(h);
        __nv_bfloat16 l = __float2bfloat16_rn(f[j] - hf);
        hh[j] = (uint32_t)__bfloat16_as_ushort(h);
        ll[j] = (uint32_t)__bfloat16_as_ushort(l);
    }
    hi = make_uint4(hh[0]|(hh[1]<<16), hh[2]|(hh[3]<<16), hh[4]|(hh[5]<<16), hh[6]|(hh[7]<<16));
    lo = make_uint4(ll[0]|(ll[1]<<16), ll[2]|(ll[3]<<16), ll[4]|(ll[5]<<16), ll[6]|(ll[7]<<16));
}
__device__ __forceinline__ uint4 cvt_hi8(float4 v0, float4 v1){
    float f[8] = {v0.x,v0.y,v0.z,v0.w,v1.x,v1.y,v1.z,v1.w};
    uint32_t hh[8];
    #pragma unroll
    for (int j = 0; j < 8; ++j)
        hh[j] = (uint32_t)__bfloat16_as_ushort(__float2bfloat16_rn(f[j]));
    return make_uint4(hh[0]|(hh[1]<<16), hh[2]|(hh[3]<<16), hh[4]|(hh[5]<<16), hh[6]|(hh[7]<<16));
}
__device__ __forceinline__ uint32_t h2u(__half2 v){ return *(uint32_t*)&v; }

#define PADK 40

// ================= 3-pass bf16 phase (mode2 only) =========================
template<int MT, int NA>
__device__ __forceinline__ void run_phase(
    const float* __restrict__ A1, const float* __restrict__ A2, int K,
    const __nv_bfloat16* __restrict__ B1h, const __nv_bfloat16* __restrict__ B1l,
    const __nv_bfloat16* __restrict__ B2h, const __nv_bfloat16* __restrict__ B2l,
    float* acc, char* sm, int tid, int rowBase, int M)
{
    constexpr int WM = MT/32;
    constexpr int WN = 16/WM;
    constexpr int NSPAN = 256/WN;
    constexpr int NFR = NSPAN/8;
    constexpr uint32_t APL = MT*80u;
    constexpr uint32_t A_BYTES = NA*2u*APL;
    constexpr uint32_t BPL = 20480u;
    constexpr uint32_t STAGE_ = A_BYTES + NA*2u*BPL;
    constexpr int NB = NA*4;
    const int lane = tid & 31, wid = tid >> 5;
    const int wm = wid / WN, wn = wid % WN;
    const int g = lane >> 3, r = lane & 7;
    const uint32_t sb = smem_addr(sm);
    const int nch = K >> 5;

    const int a_op  = tid / (MT*4);
    const int a_rem = tid % (MT*4);
    const int a_row = a_rem >> 2, a_seg = a_rem & 3;
    const int grow = rowBase + a_row;
    const bool a_ok = (grow < M);
    const float* a_src = ((a_op == 0) ? A1 : A2) + (size_t)grow*K + (a_seg << 3);
    const uint32_t a_off = (uint32_t)a_op*2u*APL + (uint32_t)a_row*80u + (uint32_t)a_seg*16u;

    auto issue_B = [&](uint32_t st, int c){
        #pragma unroll
        for (int i = 0; i < NB; ++i){
            int idx = tid + (i << 9);
            int op = idx >> 11;
            int rem = idx & 2047;
            int plane = rem >> 10;
            int rem2 = rem & 1023;
            int row = rem2 >> 2, seg = rem2 & 3;
            const __nv_bfloat16* Bp = (op == 0) ? (plane ? B1l : B1h)
                                                : (plane ? B2l : B2h);
            const __nv_bfloat16* src = Bp + (size_t)row*K + (c << 5) + (seg << 3);
            uint32_t dst = st + A_BYTES + (uint32_t)op*(2u*BPL) + (uint32_t)plane*BPL
                         + (uint32_t)row*80u + (uint32_t)seg*16u;
            CPA16(dst, src);
        }
        CP_COMMIT();
    };

    {
        float4 v0 = make_float4(0.f,0.f,0.f,0.f), v1 = v0;
        if (a_ok){ v0 = *(const float4*)a_src; v1 = *(const float4*)(a_src + 4); }
        issue_B(sb, 0);
        uint4 hi, lo; cvt_split8(v0, v1, hi, lo);
        *(uint4*)(sm + a_off)       = hi;
        *(uint4*)(sm + a_off + APL) = lo;
        CP_WAIT0();
    }
    __syncthreads();

    for (int c = 0; c < nch; ++c){
        const uint32_t st = sb + (c & 1)*STAGE_;
        const int nc = c + 1;
        float4 v0, v1;
        if (nc < nch){
            v0 = make_float4(0.f,0.f,0.f,0.f); v1 = v0;
            if (a_ok){
                const float* p = a_src + (nc << 5);
                v0 = *(const float4*)p; v1 = *(const float4*)(p + 4);
            }
            issue_B(sb + (nc & 1)*STAGE_, nc);
        }

        #pragma unroll
        for (int op = 0; op < NA; ++op){
            const uint32_t aBase = st + (uint32_t)op*2u*APL;
            const uint32_t bBase = st + A_BYTES + (uint32_t)op*(2u*BPL);
            #pragma unroll
            for (int ki = 0; ki < 2; ++ki){
                uint32_t ah[2][4], al[2][4];
                {
                    int arow = wm*32 + (g & 1)*8 + r;
                    uint32_t off = (uint32_t)(arow*PADK + ki*16 + (g >> 1)*8) * 2;
                    ldsm4(aBase + off,                   ah[0][0], ah[0][1], ah[0][2], ah[0][3]);
                    ldsm4(aBase + off + 16*PADK*2,       ah[1][0], ah[1][1], ah[1][2], ah[1][3]);
                    ldsm4(aBase + APL + off,             al[0][0], al[0][1], al[0][2], al[0][3]);
                    ldsm4(aBase + APL + off + 16*PADK*2, al[1][0], al[1][1], al[1][2], al[1][3]);
                }
                #pragma unroll
                for (int ng = 0; ng < NFR/4; ++ng){
                    uint32_t bhf[4][2], blf[4][2];
                    int nrow = wn*NSPAN + ng*32 + (g >> 1)*8 + r;
                    uint32_t off = (uint32_t)(nrow*PADK + ki*16 + (g & 1)*8) * 2;
                    ldsm4(bBase + off,                 bhf[0][0], bhf[0][1], bhf[1][0], bhf[1][1]);
                    ldsm4(bBase + off + 16*PADK*2,     bhf[2][0], bhf[2][1], bhf[3][0], bhf[3][1]);
                    ldsm4(bBase + BPL + off,             blf[0][0], blf[0][1], blf[1][0], blf[1][1]);
                    ldsm4(bBase + BPL + off + 16*PADK*2, blf[2][0], blf[2][1], blf[3][0], blf[3][1]);
                    #pragma unroll
                    for (int mi = 0; mi < 2; ++mi)
                        #pragma unroll
                        for (int j = 0; j < 4; ++j){
                            float* a = acc + (((op*2 + mi)*NFR) + ng*4 + j)*4;
                            mma16816(a, ah[mi], bhf[j]);
                            mma16816(a, ah[mi], blf[j]);
                            mma16816(a, al[mi], bhf[j]);
                        }
                }
            }
        }

        if (nc < nch){
            char* nsm = sm + (nc & 1)*STAGE_;
            uint4 hi, lo; cvt_split8(v0, v1, hi, lo);
            *(uint4*)(nsm + a_off)       = hi;
            *(uint4*)(nsm + a_off + APL) = lo;
            CP_WAIT0();
        }
        __syncthreads();
    }
}

#define SMEM_M0  (2*(2*128*80 + 2*20480))   // 122880
#define SMEM_HU  (2*(128*80 + 20480))       // 61440
#define SMEM_I3  (4*20480 + 2*40960)        // 163840

// step_fused smem layout
#define SF_CH 10256u                        // chunk stride (pad kills STS conflicts)
#define SF_OP 5120u                         // op plane within chunk
#define SF_B  (8u*SF_CH)                    // 82048: B region base
#define SF_BSTG 40960u                      // B stage: 2 ops x 20480
#define SF_NB (SF_B + 3u*SF_BSTG)           // 204928: neighbor idx table
#define SMEM_SF (204928 + 1536)             // 206464

// ================= single-pass bf16 GEMM for hU (gate path) ==============
__global__ __launch_bounds__(512, 1)
void hU_gemm(const float* __restrict__ A, const __nv_bfloat16* __restrict__ Bh,
             __half* __restrict__ Cout)
{
    constexpr int K = HD;
    constexpr uint32_t APL = 10240u, STAGE_ = 30720u;
    extern __shared__ char sm[];
    const int tid = threadIdx.x;
    const int rowBase = (int)blockIdx.x << 7;
    const int lane = tid & 31, wid = tid >> 5;
    const int wm = wid >> 2, wn = wid & 3;
    const int g = lane >> 3, r = lane & 7;
    const int tq = lane >> 2, tr = lane & 3;
    const uint32_t sb = smem_addr(sm);
    const int nch = K >> 5;

    const int a_row = tid >> 2, a_seg = tid & 3;
    const float* a_src = A + (size_t)(rowBase + a_row)*K + (a_seg << 3);
    const uint32_t a_off = (uint32_t)a_row*80u + (uint32_t)a_seg*16u;

    auto issue_B = [&](uint32_t st, int c){
        #pragma unroll
        for (int i = 0; i < 2; ++i){
            int idx = tid + (i << 9);
            int row = idx >> 2, seg = idx & 3;
            CPA16(st + APL + (uint32_t)row*80u + (uint32_t)seg*16u,
                  Bh + (size_t)row*K + (c << 5) + (seg << 3));
        }
        CP_COMMIT();
    };

    float acc[64];
    #pragma unroll
    for (int i = 0; i < 64; ++i) acc[i] = 0.f;

    {
        float4 v0 = *(const float4*)a_src;
        float4 v1 = *(const float4*)(a_src + 4);
        issue_B(sb, 0);
        *(uint4*)(sm + a_off) = cvt_hi8(v0, v1);
        CP_WAIT0();
    }
    __syncthreads();

    for (int c = 0; c < nch; ++c){
        const uint32_t st = sb + (c & 1)*STAGE_;
        const int nc = c + 1;
        float4 v0, v1;
        if (nc < nch){
            const float* p = a_src + (nc << 5);
            v0 = *(const float4*)p; v1 = *(const float4*)(p + 4);
            issue_B(sb + (nc & 1)*STAGE_, nc);
        }

        #pragma unroll
        for (int ki = 0; ki < 2; ++ki){
            uint32_t ah[2][4];
            {
                int arow = wm*32 + (g & 1)*8 + r;
                uint32_t off = (uint32_t)(arow*PADK + ki*16 + (g >> 1)*8) * 2;
                ldsm4(st + off,             ah[0][0], ah[0][1], ah[0][2], ah[0][3]);
                ldsm4(st + off + 16*PADK*2, ah[1][0], ah[1][1], ah[1][2], ah[1][3]);
            }
            #pragma unroll
            for (int ng = 0; ng < 2; ++ng){
                uint32_t bhf[4][2];
                int nrow = wn*64 + ng*32 + (g >> 1)*8 + r;
                uint32_t off = (uint32_t)(nrow*PADK + ki*16 + (g & 1)*8) * 2;
                ldsm4(st + APL + off,             bhf[0][0], bhf[0][1], bhf[1][0], bhf[1][1]);
                ldsm4(st + APL + off + 16*PADK*2, bhf[2][0], bhf[2][1], bhf[3][0], bhf[3][1]);
                #pragma unroll
                for (int mi = 0; mi < 2; ++mi)
                    #pragma unroll
                    for (int j = 0; j < 4; ++j)
                        mma16816(acc + ((mi*8) + ng*4 + j)*4, ah[mi], bhf[j]);
            }
        }

        if (nc < nch){
            *(uint4*)(sm + (nc & 1)*STAGE_ + a_off) = cvt_hi8(v0, v1);
            CP_WAIT0();
        }
        __syncthreads();
    }

    #pragma unroll
    for (int mi = 0; mi < 2; ++mi)
        #pragma unroll
        for (int ni = 0; ni < 8; ++ni){
            const float* a = acc + (mi*8 + ni)*4;
            int gcol = wn*64 + ni*8 + tr*2;
            int r0 = rowBase + wm*32 + mi*16 + tq;
            *(__half2*)&Cout[(size_t)r0*HD + gcol]     = __floats2half2_rn(a[0], a[1]);
            *(__half2*)&Cout[(size_t)(r0+8)*HD + gcol] = __floats2half2_rn(a[2], a[3]);
        }
}

// ================= fused invariants: fz16, fh16(+h1), rx16 ===============
__global__ __launch_bounds__(512, 1)
void inv3_gemm(const float* __restrict__ A,
               const __nv_bfloat16* __restrict__ Wzh, const __nv_bfloat16* __restrict__ Wzl,
               const __nv_bfloat16* __restrict__ Whh, const __nv_bfloat16* __restrict__ Whl,
               const __nv_bfloat16* __restrict__ Wrh, const __nv_bfloat16* __restrict__ Wrl,
               const float* __restrict__ b_z, const float* __restrict__ b_h,
               const float* __restrict__ b_ur,
               __half* __restrict__ fz, __half* __restrict__ fh,
               float* __restrict__ h1, __half* __restrict__ rx)
{
    constexpr int K = IND;
    constexpr uint32_t B_OFF = 81920u;
    constexpr uint32_t BPL = 20480u, BSTG = 40960u;
    extern __shared__ char sm[];
    const int tid = threadIdx.x;
    const int rowBase = (int)blockIdx.x << 7;
    const int lane = tid & 31, wid = tid >> 5;
    const int wm = wid >> 2, wn = wid & 3;
    const int g = lane >> 3, r = lane & 7;
    const int tq = lane >> 2, tr = lane & 3;
    const uint32_t sb = smem_addr(sm);

    #pragma unroll
    for (int u = 0; u < 4; ++u){
        int idx = tid + (u << 9);
        int row = idx >> 4, gi = idx & 15;
        int t = gi >> 2, seg = gi & 3;
        const float* p = A + (size_t)(rowBase + row)*K + (gi << 3);
        float4 v0 = *(const float4*)p, v1 = *(const float4*)(p + 4);
        uint4 hi, lo; cvt_split8(v0, v1, hi, lo);
        uint32_t off = (uint32_t)t*20480u + (uint32_t)row*80u + (uint32_t)seg*16u;
        *(uint4*)(sm + off)          = hi;
        *(uint4*)(sm + off + 10240u) = lo;
    }
    __syncthreads();

    const __nv_bfloat16* Bhs[3] = {Wzh, Whh, Wrh};
    const __nv_bfloat16* Bls[3] = {Wzl, Whl, Wrl};
    const float* biases[3] = {b_z, b_h, b_ur};

    #pragma unroll
    for (int op = 0; op < 3; ++op){
        const __nv_bfloat16* Bh = Bhs[op];
        const __nv_bfloat16* Bl = Bls[op];

        auto issue_B = [&](uint32_t st, int c){
            #pragma unroll
            for (int i = 0; i < 4; ++i){
                int idx = tid + (i << 9);
                int plane = idx >> 10;
                int rem = idx & 1023;
                int row = rem >> 2, seg = rem & 3;
                const __nv_bfloat16* src = (plane ? Bl : Bh)
                    + (size_t)row*K + (c << 5) + (seg << 3);
                CPA16(st + (uint32_t)plane*BPL + (uint32_t)row*80u + (uint32_t)seg*16u, src);
            }
            CP_COMMIT();
        };

        float acc[64];
        #pragma unroll
        for (int i = 0; i < 64; ++i) acc[i] = 0.f;

        issue_B(sb + B_OFF, 0);
        CP_WAIT0();
        __syncthreads();

        for (int c = 0; c < 4; ++c){
            const uint32_t aBase = sb + (uint32_t)c*20480u;
            const uint32_t bBase = sb + B_OFF + (uint32_t)(c & 1)*BSTG;
            if (c + 1 < 4) issue_B(sb + B_OFF + (uint32_t)((c+1) & 1)*BSTG, c+1);

            #pragma unroll
            for (int ki = 0; ki < 2; ++ki){
                uint32_t ah[2][4], al[2][4];
                {
                    int arow = wm*32 + (g & 1)*8 + r;
                    uint32_t off = (uint32_t)(arow*PADK + ki*16 + (g >> 1)*8) * 2;
                    ldsm4(aBase + off,                  ah[0][0], ah[0][1], ah[0][2], ah[0][3]);
                    ldsm4(aBase + off + 16*PADK*2,      ah[1][0], ah[1][1], ah[1][2], ah[1][3]);
                    ldsm4(aBase + 10240u + off,             al[0][0], al[0][1], al[0][2], al[0][3]);
                    ldsm4(aBase + 10240u + off + 16*PADK*2, al[1][0], al[1][1], al[1][2], al[1][3]);
                }
                #pragma unroll
                for (int ng = 0; ng < 2; ++ng){
                    uint32_t bhf[4][2], blf[4][2];
                    int nrow = wn*64 + ng*32 + (g >> 1)*8 + r;
                    uint32_t off = (uint32_t)(nrow*PADK + ki*16 + (g & 1)*8) * 2;
                    ldsm4(bBase + off,                 bhf[0][0], bhf[0][1], bhf[1][0], bhf[1][1]);
                    ldsm4(bBase + off + 16*PADK*2,     bhf[2][0], bhf[2][1], bhf[3][0], bhf[3][1]);
                    ldsm4(bBase + BPL + off,             blf[0][0], blf[0][1], blf[1][0], blf[1][1]);
                    ldsm4(bBase + BPL + off + 16*PADK*2, blf[2][0], blf[2][1], blf[3][0], blf[3][1]);
                    #pragma unroll
                    for (int mi = 0; mi < 2; ++mi)
                        #pragma unroll
                        for (int j = 0; j < 4; ++j){
                            float* a = acc + ((mi*8) + ng*4 + j)*4;
                            mma16816(a, ah[mi], bhf[j]);
                            mma16816(a, ah[mi], blf[j]);
                            mma16816(a, al[mi], bhf[j]);
                        }
                }
            }
            if (c + 1 < 4) CP_WAIT0();
            __syncthreads();
        }

        #pragma unroll
        for (int mi = 0; mi < 2; ++mi)
            #pragma unroll
            for (int ni = 0; ni < 8; ++ni){
                const float* a = acc + (mi*8 + ni)*4;
                int gcol = wn*64 + ni*8 + tr*2;
                int r0 = rowBase + wm*32 + mi*16 + tq;
                float2 b = *(const float2*)&biases[op][gcol];
                size_t o0 = (size_t)r0*HD + gcol;
                size_t o1 = (size_t)(r0+8)*HD + gcol;
                float2 u0 = make_float2(a[0]+b.x, a[1]+b.y);
                float2 u1 = make_float2(a[2]+b.x, a[3]+b.y);
                if (op == 0) {
                    *(__half2*)&fz[o0] = __floats2half2_rn(u0.x, u0.y);
                    *(__half2*)&fz[o1] = __floats2half2_rn(u1.x, u1.y);
                } else if (op == 1) {
                    *(__half2*)&fh[o0] = __floats2half2_rn(u0.x, u0.y);
                    *(__half2*)&fh[o1] = __floats2half2_rn(u1.x, u1.y);
                    float2 z0 = __half22float2(*(const __half2*)&fz[o0]);
                    float2 z1 = __half22float2(*(const __half2*)&fz[o1]);
                    float2 w0 = make_float2(sigm(z0.x)*tanhf(u0.x), sigm(z0.y)*tanhf(u0.y));
                    float2 w1 = make_float2(sigm(z1.x)*tanhf(u1.x), sigm(z1.y)*tanhf(u1.y));
                    if (r0 == 0) w0 = make_float2(0.f, 0.f);   // null message row
                    *(float2*)&h1[o0] = w0;
                    *(float2*)&h1[o1] = w1;
                } else {
                    *(__half2*)&rx[o0] = __floats2half2_rn(u0.x, u0.y);
                    *(__half2*)&rx[o1] = __floats2half2_rn(u1.x, u1.y);
                }
            }
    }
}

// ============ fused gather + fp16 dual GEMM + GRU epilogue ================
// Per CTA: 64 message rows. Gather sumh/sumg (fp16) into resident smem A,
// then D1 = sumh@Wz^T, D2 = sumg@Wh^T, h_new = (1-z)*sumh + z*tanh(fh+D2).
__global__ __launch_bounds__(512, 1)
void step_fused(const float* __restrict__ h, const __half* __restrict__ hU,
                const __half* __restrict__ rx, const int* __restrict__ bg,
                const __half* __restrict__ Bz, const __half* __restrict__ Bhh,
                const __half* __restrict__ fz, const __half* __restrict__ fh,
                float* __restrict__ C)
{
    constexpr int K = HD;                       // 8 chunks of 32
    extern __shared__ char sm[];
    const int tid = threadIdx.x;
    const int rowBase = (int)blockIdx.x << 6;   // 64 rows
    const int lane = tid & 31, wid = tid >> 5;
    const int wm = wid >> 3, wn = wid & 7;      // 2 x 8 warps
    const int g = lane >> 3, r = lane & 7;
    const int tq = lane >> 2, tr = lane & 3;
    const uint32_t sb = smem_addr(sm);
    int* s_nb = (int*)(sm + SF_NB);

    // B issue (fp16 weights, 2 ops x 256 rows x 4 segs = 4/thread)
    auto issue = [&](uint32_t st, int c){
        #pragma unroll
        for (int i = 0; i < 4; ++i){
            int idx = tid + (i << 9);
            int op = idx >> 10;
            int rem = idx & 1023;
            int row = rem >> 2, seg = rem & 3;
            const __half* src = ((op == 0) ? Bz : Bhh)
                + (size_t)row*K + (c << 5) + (seg << 3);
            CPA16(st + (uint32_t)op*20480u + (uint32_t)row*80u + (uint32_t)seg*16u, src);
        }
        CP_COMMIT();
    };

    // neighbor indices
    if (tid < 64*NBR) s_nb[tid] = bg[(size_t)rowBase*NBR + tid];
    __syncthreads();

    // kick off first two B stages so weight loads overlap the gather
    issue(sb + SF_B, 0);
    issue(sb + SF_B + SF_BSTG, 1);

    // ---- gather: thread (lrow = tid>>3, sub = tid&7) does chunk `sub` ----
    {
        const int lrow = tid >> 3;
        const int sub = tid & 7;
        const int grow = rowBase + lrow;
        int nb[NBR];
        #pragma unroll
        for (int j = 0; j < NBR; ++j) nb[j] = s_nb[lrow*NBR + j];
        const int c0 = sub << 5;
        #pragma unroll
        for (int g8 = 0; g8 < 4; ++g8){
            int col = c0 + (g8 << 3);
            size_t base = (size_t)grow*HD + col;
            uint4 rxq = *(const uint4*)(rx + base);
            float2 ra = __half22float2(*(__half2*)&rxq.x);
            float2 rb = __half22float2(*(__half2*)&rxq.y);
            float2 rc = __half22float2(*(__half2*)&rxq.z);
            float2 rd = __half22float2(*(__half2*)&rxq.w);
            float rr[8] = {ra.x,ra.y,rb.x,rb.y,rc.x,rc.y,rd.x,rd.y};
            float sh[8], sg[8];
            #pragma unroll
            for (int k = 0; k < 8; ++k){ sh[k] = 0.f; sg[k] = 0.f; }
            #pragma unroll
            for (int j = 0; j < NBR; ++j){
                size_t nbo = (size_t)nb[j]*HD + col;
                float4 h0 = *(const float4*)&h[nbo];
                float4 h1v = *(const float4*)&h[nbo + 4];
                uint4 uq = *(const uint4*)(hU + nbo);
                float2 ua = __half22float2(*(__half2*)&uq.x);
                float2 ub = __half22float2(*(__half2*)&uq.y);
                float2 uc = __half22float2(*(__half2*)&uq.z);
                float2 ud = __half22float2(*(__half2*)&uq.w);
                float hv[8] = {h0.x,h0.y,h0.z,h0.w,h1v.x,h1v.y,h1v.z,h1v.w};
                float uu[8] = {ua.x,ua.y,ub.x,ub.y,uc.x,uc.y,ud.x,ud.y};
                #pragma unroll
                for (int k = 0; k < 8; ++k){
                    sh[k] += hv[k];
                    sg[k] += sigm(rr[k] + uu[k]) * hv[k];
                }
            }
            uint4 shq = make_uint4(h2u(__floats2half2_rn(sh[0],sh[1])),
                                   h2u(__floats2half2_rn(sh[2],sh[3])),
                                   h2u(__floats2half2_rn(sh[4],sh[5])),
                                   h2u(__floats2half2_rn(sh[6],sh[7])));
            uint4 sgq = make_uint4(h2u(__floats2half2_rn(sg[0],sg[1])),
                                   h2u(__floats2half2_rn(sg[2],sg[3])),
                                   h2u(__floats2half2_rn(sg[4],sg[5])),
                                   h2u(__floats2half2_rn(sg[6],sg[7])));
            uint32_t off = (uint32_t)sub*SF_CH + (uint32_t)lrow*80u + (uint32_t)(g8 << 4);
            *(uint4*)(sm + off)         = shq;
            *(uint4*)(sm + off + SF_OP) = sgq;
        }
    }
    __syncthreads();

    // ---- fp16 dual GEMM: A resident in smem, B 3-stage pipeline ----
    float acc[64];
    #pragma unroll
    for (int i = 0; i < 64; ++i) acc[i] = 0.f;

    for (int c = 0; c < 8; ++c){
        if (c + 1 < 8) { CP_WAIT1(); } else { CP_WAIT0(); }
        __syncthreads();
        if (c + 2 < 8) issue(sb + SF_B + ((c+2)%3)*SF_BSTG, c+2);
        const uint32_t bst = sb + SF_B + (c%3)*SF_BSTG;
        const uint32_t ast = sb + (uint32_t)c*SF_CH;

        #pragma unroll
        for (int op = 0; op < 2; ++op){
            const uint32_t aBase = ast + (uint32_t)op*SF_OP;
            const uint32_t bBase = bst + (uint32_t)op*20480u;
            #pragma unroll
            for (int ki = 0; ki < 2; ++ki){
                uint32_t ah[2][4];
                {
                    int arow = wm*32 + (g & 1)*8 + r;
                    uint32_t off = (uint32_t)(arow*PADK + ki*16 + (g >> 1)*8) * 2;
                    ldsm4(aBase + off,             ah[0][0], ah[0][1], ah[0][2], ah[0][3]);
                    ldsm4(aBase + off + 16*PADK*2, ah[1][0], ah[1][1], ah[1][2], ah[1][3]);
                }
                uint32_t bf[4][2];
                {
                    int nrow = wn*32 + (g >> 1)*8 + r;
                    uint32_t off = (uint32_t)(nrow*PADK + ki*16 + (g & 1)*8) * 2;
                    ldsm4(bBase + off,             bf[0][0], bf[0][1], bf[1][0], bf[1][1]);
                    ldsm4(bBase + off + 16*PADK*2, bf[2][0], bf[2][1], bf[3][0], bf[3][1]);
                }
                #pragma unroll
                for (int mi = 0; mi < 2; ++mi)
                    #pragma unroll
                    for (int j = 0; j < 4; ++j)
                        mma16816h(acc + ((op*2 + mi)*4 + j)*4, ah[mi], bf[j]);
            }
        }
    }

    // ---- epilogue: sumh from smem, fz/fh from global, write h fp32 ----
    #pragma unroll
    for (int mi = 0; mi < 2; ++mi)
        #pragma unroll
        for (int ni = 0; ni < 4; ++ni){
            const float* a1 = acc + ((0*2 + mi)*4 + ni)*4;
            const float* a2 = acc + ((1*2 + mi)*4 + ni)*4;
            int lrow0 = wm*32 + mi*16 + tq;
            int gcol = wn*32 + ni*8 + tr*2;
            int r0 = rowBase + lrow0;
            size_t o0 = (size_t)r0*HD + gcol;
            size_t o1 = (size_t)(r0+8)*HD + gcol;
            // sumh from smem: chunk = wn, within = ni*8 + tr*2
            uint32_t sa0 = (uint32_t)wn*SF_CH + (uint32_t)lrow0*80u
                         + (uint32_t)((ni*8 + tr*2) << 1);
            float2 sa = __half22float2(*(__half2*)(sm + sa0));
            float2 sb2 = __half22float2(*(__half2*)(sm + sa0 + 8*80u));
            float2 za = __half22float2(*(const __half2*)&fz[o0]);
            float2 zb = __half22float2(*(const __half2*)&fz[o1]);
            float2 ha = __half22float2(*(const __half2*)&fh[o0]);
            float2 hb = __half22float2(*(const __half2*)&fh[o1]);
            float z0 = sigm(za.x + a1[0]);
            float z1 = sigm(za.y + a1[1]);
            float z2 = sigm(zb.x + a1[2]);
            float z3 = sigm(zb.y + a1[3]);
            float p0 = tanhf(ha.x + a2[0]);
            float p1 = tanhf(ha.y + a2[1]);
            float p2 = tanhf(hb.x + a2[2]);
            float p3 = tanhf(hb.y + a2[3]);
            float2 u0 = make_float2((1.f - z0)*sa.x + z0*p0, (1.f - z1)*sa.y + z1*p1);
            float2 u1 = make_float2((1.f - z2)*sb2.x + z2*p2, (1.f - z3)*sb2.y + z3*p3);
            if (r0 == 0) u0 = make_float2(0.f, 0.f);
            *(float2*)&C[o0] = u0;
            *(float2*)&C[o1] = u1;
        }
}

// ================= MODE2 (output layer, bf16 3-pass) ======================
__global__ __launch_bounds__(512, 1)
void mode2_gemm(const float* __restrict__ A1, int K1,
                const __nv_bfloat16* __restrict__ B1h, const __nv_bfloat16* __restrict__ B1l,
                const float* __restrict__ A2, int K2,
                const __nv_bfloat16* __restrict__ B2h, const __nv_bfloat16* __restrict__ B2l,
                int M, const float* __restrict__ bias, const float* __restrict__ maskv,
                float* __restrict__ C)
{
    extern __shared__ char sm[];
    const int tid = threadIdx.x;
    const int rowBase = (int)blockIdx.x << 7;
    const int lane = tid & 31, wid = tid >> 5;
    const int wm = wid >> 2, wn = wid & 3;
    const int tq = lane >> 2, tr = lane & 3;

    float acc[64];
    #pragma unroll
    for (int i = 0; i < 64; ++i) acc[i] = 0.f;

    run_phase<128,1>(A1, nullptr, K1, B1h, B1l, nullptr, nullptr, acc, sm, tid, rowBase, M);
    run_phase<128,1>(A2, nullptr, K2, B2h, B2l, nullptr, nullptr, acc, sm, tid, rowBase, M);

    #pragma unroll
    for (int mi = 0; mi < 2; ++mi)
        #pragma unroll
        for (int ni = 0; ni < 8; ++ni) {
            const float* a = acc + (mi*8 + ni)*4;
            int gcol = wn*64 + ni*8 + tr*2;
            int r0 = rowBase + wm*32 + mi*16 + tq;
            float2 b = *(const float2*)&bias[gcol];
            if (r0 < M) {
                float m = maskv[r0];
                *(float2*)&C[(size_t)r0*HD + gcol] =
                    make_float2(fmaxf(a[0]+b.x, 0.f)*m, fmaxf(a[1]+b.y, 0.f)*m);
            }
            if (r0 + 8 < M) {
                float m = maskv[r0+8];
                *(float2*)&C[(size_t)(r0+8)*HD + gcol] =
                    make_float2(fmaxf(a[2]+b.x, 0.f)*m, fmaxf(a[3]+b.y, 0.f)*m);
            }
        }
}

// transpose + bf16 hi/lo split of W[K,256] -> [256,K]
__global__ void prep_w(const float* __restrict__ W, __nv_bfloat16* __restrict__ oh,
                       __nv_bfloat16* __restrict__ ol, int K, int kshift)
{
    int i = blockIdx.x * blockDim.x + threadIdx.x;
    int k = i & (K - 1);
    int n = i >> kshift;
    float x = W[(size_t)k * HD + n];
    __nv_bfloat16 h = __float2bfloat16_rn(x);
    __nv_bfloat16 lo = __float2bfloat16_rn(x - __bfloat162float(h));
    oh[i] = h; ol[i] = lo;
}

// transpose to fp16 [256,K]
__global__ void prep_w16(const float* __restrict__ W, __half* __restrict__ o,
                         int K, int kshift)
{
    int i = blockIdx.x * blockDim.x + threadIdx.x;
    int k = i & (K - 1);
    int n = i >> kshift;
    o[i] = __float2half_rn(W[(size_t)k * HD + n]);
}

__global__ void gather_nodes(const float* __restrict__ h, const int* __restrict__ ag,
                             float* __restrict__ nei)
{
    __shared__ int s_nb[4][NBR];
    int v = blockIdx.x * 4 + threadIdx.y;
    if (threadIdx.x < NBR) s_nb[threadIdx.y][threadIdx.x] = ag[v*NBR + threadIdx.x];
    __syncthreads();
    int c = threadIdx.x << 2;
    float4 s = make_float4(0.f,0.f,0.f,0.f);
    #pragma unroll
    for (int j = 0; j < NBR; ++j) {
        size_t nb = (size_t)s_nb[threadIdx.y][j]*HD + c;
        float4 hv = *(const float4*)&h[nb];
        s.x += hv.x; s.y += hv.y; s.z += hv.z; s.w += hv.w;
    }
    *(float4*)&nei[(size_t)v*HD + c] = s;
}

extern "C" void kernel_launch(void* const* d_in, const int* in_sizes, int n_in,
                              void* d_out, int out_size)
{
    const float* fnode  = (const float*)d_in[0];
    const float* fmess  = (const float*)d_in[1];
    const int*   agraph = (const int*)  d_in[2];
    const int*   bgraph = (const int*)  d_in[3];
    const float* mask   = (const float*)d_in[4];
    const float* W_z    = (const float*)d_in[5];
    const float* b_z    = (const float*)d_in[6];
    const float* W_r    = (const float*)d_in[7];
    const float* U_r    = (const float*)d_in[8];
    const float* b_ur   = (const float*)d_in[9];
    const float* W_h    = (const float*)d_in[10];
    const float* b_h    = (const float*)d_in[11];
    const float* W_o    = (const float*)d_in[12];
    const float* b_o    = (const float*)d_in[13];

    float* out_node = (float*)d_out;
    float* out_h    = out_node + (size_t)NN*HD;

    float *hA, *nei;
    __half *fz16, *fh16, *hU16, *rx16, *wz16, *wh16;
    __nv_bfloat16 *bh, *bl;
    cudaGetSymbolAddress((void**)&hA,     g_hA);
    cudaGetSymbolAddress((void**)&nei,    g_nei);
    cudaGetSymbolAddress((void**)&fz16,   g_fz16);
    cudaGetSymbolAddress((void**)&fh16,   g_fh16);
    cudaGetSymbolAddress((void**)&hU16,   g_hU16);
    cudaGetSymbolAddress((void**)&rx16,   g_rx16);
    cudaGetSymbolAddress((void**)&wz16,   g_wz16);
    cudaGetSymbolAddress((void**)&wh16,   g_wh16);
    cudaGetSymbolAddress((void**)&bh,     g_bh);
    cudaGetSymbolAddress((void**)&bl,     g_bl);

    cudaFuncSetAttribute((const void*)inv3_gemm,
                         cudaFuncAttributeMaxDynamicSharedMemorySize, SMEM_I3);
    cudaFuncSetAttribute((const void*)hU_gemm,
                         cudaFuncAttributeMaxDynamicSharedMemorySize, SMEM_HU);
    cudaFuncSetAttribute((const void*)step_fused,
                         cudaFuncAttributeMaxDynamicSharedMemorySize, SMEM_SF);
    cudaFuncSetAttribute((const void*)mode2_gemm,
                         cudaFuncAttributeMaxDynamicSharedMemorySize, SMEM_M0);

    const int gE128 = NM / 128;               // 625
    const int gE64  = NM / 64;                // 1250
    const int gV    = NNP / 128;              // 274

    // weight preps
    prep_w<<<256, 256>>>(U_r, bh+OFF_UR,  bl+OFF_UR,  HD, 8);
    prep_w<<<128, 256>>>(W_z, bh+OFF_WZT, bl+OFF_WZT, IND, 7);
    prep_w<<<128, 256>>>(W_h, bh+OFF_WHT, bl+OFF_WHT, IND, 7);
    prep_w<<<128, 256>>>(W_r, bh+OFF_WR,  bl+OFF_WR,  IND, 7);

    // fused invariants (fz16, fh16, h1, rx16)
    inv3_gemm<<<gE128, 512, SMEM_I3>>>(fmess,
        bh+OFF_WZT, bl+OFF_WZT, bh+OFF_WHT, bl+OFF_WHT, bh+OFF_WR, bl+OFF_WR,
        b_z, b_h, b_ur, fz16, fh16, out_h, rx16);

    // fp16 weight preps for the GRU-step GEMMs (+ output-layer preps)
    prep_w16<<<256, 256>>>(W_z + (size_t)IND*HD, wz16, HD, 8);
    prep_w16<<<256, 256>>>(W_h + (size_t)IND*HD, wh16, HD, 8);
    prep_w<<<128, 256>>>(W_o,                  bh+OFF_WOT, bl+OFF_WOT, IND, 7);
    prep_w<<<256, 256>>>(W_o + (size_t)IND*HD, bh+OFF_WOB, bl+OFF_WOB, HD, 8);

    float* hc = out_h;
    float* hn = hA;
    for (int d = 1; d < DEPTH; ++d) {
        hU_gemm<<<gE128, 512, SMEM_HU>>>(hc, bh+OFF_UR, hU16);
        step_fused<<<gE64, 512, SMEM_SF>>>(hc, hU16, rx16, bgraph,
                                           wz16, wh16, fz16, fh16, hn);
        float* t = hc; hc = hn; hn = t;
    }

    gather_nodes<<<NN/4, dim3(64,4)>>>(hc, agraph, nei);
    mode2_gemm<<<gV, 512, SMEM_M0>>>(fnode, IND, bh+OFF_WOT, bl+OFF_WOT,
                                     nei, HD, bh+OFF_WOB, bl+OFF_WOB,
                                     NN, b_o, mask, out_node);
}

// round 13
// speedup vs baseline: 1.3465x; 1.3465x over previous
#include <cuda_runtime.h>
#include <cuda_bf16.h>
#include <cuda_fp16.h>
#include <math.h>
#include <cstdint>

#define NN 35000
#define NM 80000
#define NBR 6
#define IND 128
#define HD 256
#define DEPTH 5
#define NNP 35072

// ---------------- scratch (__device__ globals; no allocs) ----------------
__device__ float g_hA  [(size_t)NM*HD];
__device__ float g_nei [(size_t)NNP*HD];
__device__ __align__(16) __half g_h16  [(size_t)NM*HD];   // fp16 mirror of h
__device__ __align__(16) __half g_fz16 [(size_t)NM*HD];
__device__ __align__(16) __half g_fh16 [(size_t)NM*HD];
__device__ __align__(16) __half g_sumh16[(size_t)NM*HD];
__device__ __align__(16) __half g_sumg16[(size_t)NM*HD];
__device__ __align__(16) __half g_hU16[(size_t)NM*HD];
__device__ __align__(16) __half g_rx16[(size_t)NM*HD];
// fp16 transposed weights for the GRU-step GEMMs: [256,256]
__device__ __align__(16) __half g_wz16[65536];
__device__ __align__(16) __half g_wh16[65536];

// transposed+split bf16 weights (hi/lo planes): inv3 / hU / mode2
#define OFF_WZT 0
#define OFF_WHT 32768
#define OFF_WR  65536
#define OFF_WOT 98304
#define OFF_UR  131072
#define OFF_WOB 196608
__device__ __align__(16) __nv_bfloat16 g_bh[262144];
__device__ __align__(16) __nv_bfloat16 g_bl[262144];

__device__ __forceinline__ float sigm(float x){ return 1.0f/(1.0f+expf(-x)); }

// ---------------- mma / ldmatrix / cp.async helpers ----------------------
__device__ __forceinline__ uint32_t smem_addr(const void* p){
    return (uint32_t)__cvta_generic_to_shared(p);
}
__device__ __forceinline__ void ldsm4(uint32_t a, uint32_t& r0, uint32_t& r1,
                                      uint32_t& r2, uint32_t& r3){
    asm volatile("ldmatrix.sync.aligned.m8n8.x4.shared.b16 {%0,%1,%2,%3}, [%4];"
                 : "=r"(r0), "=r"(r1), "=r"(r2), "=r"(r3) : "r"(a));
}
__device__ __forceinline__ void mma16816(float* c, const uint32_t* a, const uint32_t* b){
    asm volatile(
        "mma.sync.aligned.m16n8k16.row.col.f32.bf16.bf16.f32 "
        "{%0,%1,%2,%3}, {%4,%5,%6,%7}, {%8,%9}, {%0,%1,%2,%3};"
        : "+f"(c[0]), "+f"(c[1]), "+f"(c[2]), "+f"(c[3])
        : "r"(a[0]), "r"(a[1]), "r"(a[2]), "r"(a[3]), "r"(b[0]), "r"(b[1]));
}
__device__ __forceinline__ void mma16816h(float* c, const uint32_t* a, const uint32_t* b){
    asm volatile(
        "mma.sync.aligned.m16n8k16.row.col.f32.f16.f16.f32 "
        "{%0,%1,%2,%3}, {%4,%5,%6,%7}, {%8,%9}, {%0,%1,%2,%3};"
        : "+f"(c[0]), "+f"(c[1]), "+f"(c[2]), "+f"(c[3])
        : "r"(a[0]), "r"(a[1]), "r"(a[2]), "r"(a[3]), "r"(b[0]), "r"(b[1]));
}
#define CPA16(dst, src) \
    asm volatile("cp.async.cg.shared.global [%0], [%1], 16;" :: "r"(dst), "l"(src))
#define CP_COMMIT() asm volatile("cp.async.commit_group;" ::: "memory")
#define CP_WAIT0()  asm volatile("cp.async.wait_group 0;" ::: "memory")
#define CP_WAIT1()  asm volatile("cp.async.wait_group 1;" ::: "memory")

__device__ __forceinline__ void cvt_split8(float4 v0, float4 v1, uint4& hi, uint4& lo){
    float f[8] = {v0.x,v0.y,v0.z,v0.w,v1.x,v1.y,v1.z,v1.w};
    uint32_t hh[8], ll[8];
    #pragma unroll
    for (int j = 0; j < 8; ++j) {
        __nv_bfloat16 h = __float2bfloat16_rn(f[j]);
        float hf = __bfloat162float(h);
        __nv_bfloat16 l = __float2bfloat16_rn(f[j] - hf);
        hh[j] = (uint32_t)__bfloat16_as_ushort(h);
        ll[j] = (uint32_t)__bfloat16_as_ushort(l);
    }
    hi = make_uint4(hh[0]|(hh[1]<<16), hh[2]|(hh[3]<<16), hh[4]|(hh[5]<<16), hh[6]|(hh[7]<<16));
    lo = make_uint4(ll[0]|(ll[1]<<16), ll[2]|(ll[3]<<16), ll[4]|(ll[5]<<16), ll[6]|(ll[7]<<16));
}
// 8 fp16 -> 8 bf16 (hi only)
__device__ __forceinline__ uint4 cvt_h8_bf8(uint4 v){
    const __half* hp = (const __half*)&v;
    uint32_t hh[8];
    #pragma unroll
    for (int j = 0; j < 8; ++j)
        hh[j] = (uint32_t)__bfloat16_as_ushort(__float2bfloat16_rn(__half2float(hp[j])));
    return make_uint4(hh[0]|(hh[1]<<16), hh[2]|(hh[3]<<16), hh[4]|(hh[5]<<16), hh[6]|(hh[7]<<16));
}
__device__ __forceinline__ uint32_t h2u(__half2 v){ return *(uint32_t*)&v; }

#define PADK 40

// ================= 3-pass bf16 phase (mode2 only) =========================
template<int MT, int NA>
__device__ __forceinline__ void run_phase(
    const float* __restrict__ A1, const float* __restrict__ A2, int K,
    const __nv_bfloat16* __restrict__ B1h, const __nv_bfloat16* __restrict__ B1l,
    const __nv_bfloat16* __restrict__ B2h, const __nv_bfloat16* __restrict__ B2l,
    float* acc, char* sm, int tid, int rowBase, int M)
{
    constexpr int WM = MT/32;
    constexpr int WN = 16/WM;
    constexpr int NSPAN = 256/WN;
    constexpr int NFR = NSPAN/8;
    constexpr uint32_t APL = MT*80u;
    constexpr uint32_t A_BYTES = NA*2u*APL;
    constexpr uint32_t BPL = 20480u;
    constexpr uint32_t STAGE_ = A_BYTES + NA*2u*BPL;
    constexpr int NB = NA*4;
    const int lane = tid & 31, wid = tid >> 5;
    const int wm = wid / WN, wn = wid % WN;
    const int g = lane >> 3, r = lane & 7;
    const uint32_t sb = smem_addr(sm);
    const int nch = K >> 5;

    const int a_op  = tid / (MT*4);
    const int a_rem = tid % (MT*4);
    const int a_row = a_rem >> 2, a_seg = a_rem & 3;
    const int grow = rowBase + a_row;
    const bool a_ok = (grow < M);
    const float* a_src = ((a_op == 0) ? A1 : A2) + (size_t)grow*K + (a_seg << 3);
    const uint32_t a_off = (uint32_t)a_op*2u*APL + (uint32_t)a_row*80u + (uint32_t)a_seg*16u;

    auto issue_B = [&](uint32_t st, int c){
        #pragma unroll
        for (int i = 0; i < NB; ++i){
            int idx = tid + (i << 9);
            int op = idx >> 11;
            int rem = idx & 2047;
            int plane = rem >> 10;
            int rem2 = rem & 1023;
            int row = rem2 >> 2, seg = rem2 & 3;
            const __nv_bfloat16* Bp = (op == 0) ? (plane ? B1l : B1h)
                                                : (plane ? B2l : B2h);
            const __nv_bfloat16* src = Bp + (size_t)row*K + (c << 5) + (seg << 3);
            uint32_t dst = st + A_BYTES + (uint32_t)op*(2u*BPL) + (uint32_t)plane*BPL
                         + (uint32_t)row*80u + (uint32_t)seg*16u;
            CPA16(dst, src);
        }
        CP_COMMIT();
    };

    {
        float4 v0 = make_float4(0.f,0.f,0.f,0.f), v1 = v0;
        if (a_ok){ v0 = *(const float4*)a_src; v1 = *(const float4*)(a_src + 4); }
        issue_B(sb, 0);
        uint4 hi, lo; cvt_split8(v0, v1, hi, lo);
        *(uint4*)(sm + a_off)       = hi;
        *(uint4*)(sm + a_off + APL) = lo;
        CP_WAIT0();
    }
    __syncthreads();

    for (int c = 0; c < nch; ++c){
        const uint32_t st = sb + (c & 1)*STAGE_;
        const int nc = c + 1;
        float4 v0, v1;
        if (nc < nch){
            v0 = make_float4(0.f,0.f,0.f,0.f); v1 = v0;
            if (a_ok){
                const float* p = a_src + (nc << 5);
                v0 = *(const float4*)p; v1 = *(const float4*)(p + 4);
            }
            issue_B(sb + (nc & 1)*STAGE_, nc);
        }

        #pragma unroll
        for (int op = 0; op < NA; ++op){
            const uint32_t aBase = st + (uint32_t)op*2u*APL;
            const uint32_t bBase = st + A_BYTES + (uint32_t)op*(2u*BPL);
            #pragma unroll
            for (int ki = 0; ki < 2; ++ki){
                uint32_t ah[2][4], al[2][4];
                {
                    int arow = wm*32 + (g & 1)*8 + r;
                    uint32_t off = (uint32_t)(arow*PADK + ki*16 + (g >> 1)*8) * 2;
                    ldsm4(aBase + off,                   ah[0][0], ah[0][1], ah[0][2], ah[0][3]);
                    ldsm4(aBase + off + 16*PADK*2,       ah[1][0], ah[1][1], ah[1][2], ah[1][3]);
                    ldsm4(aBase + APL + off,             al[0][0], al[0][1], al[0][2], al[0][3]);
                    ldsm4(aBase + APL + off + 16*PADK*2, al[1][0], al[1][1], al[1][2], al[1][3]);
                }
                #pragma unroll
                for (int ng = 0; ng < NFR/4; ++ng){
                    uint32_t bhf[4][2], blf[4][2];
                    int nrow = wn*NSPAN + ng*32 + (g >> 1)*8 + r;
                    uint32_t off = (uint32_t)(nrow*PADK + ki*16 + (g & 1)*8) * 2;
                    ldsm4(bBase + off,                 bhf[0][0], bhf[0][1], bhf[1][0], bhf[1][1]);
                    ldsm4(bBase + off + 16*PADK*2,     bhf[2][0], bhf[2][1], bhf[3][0], bhf[3][1]);
                    ldsm4(bBase + BPL + off,             blf[0][0], blf[0][1], blf[1][0], blf[1][1]);
                    ldsm4(bBase + BPL + off + 16*PADK*2, blf[2][0], blf[2][1], blf[3][0], blf[3][1]);
                    #pragma unroll
                    for (int mi = 0; mi < 2; ++mi)
                        #pragma unroll
                        for (int j = 0; j < 4; ++j){
                            float* a = acc + (((op*2 + mi)*NFR) + ng*4 + j)*4;
                            mma16816(a, ah[mi], bhf[j]);
                            mma16816(a, ah[mi], blf[j]);
                            mma16816(a, al[mi], bhf[j]);
                        }
                }
            }
        }

        if (nc < nch){
            char* nsm = sm + (nc & 1)*STAGE_;
            uint4 hi, lo; cvt_split8(v0, v1, hi, lo);
            *(uint4*)(nsm + a_off)       = hi;
            *(uint4*)(nsm + a_off + APL) = lo;
            CP_WAIT0();
        }
        __syncthreads();
    }
}

#define SMEM_M0  (2*(2*128*80 + 2*20480))   // 122880
#define SMEM_HU  (2*(128*80 + 20480))       // 61440
#define SMEM_I3  (4*20480 + 2*40960)        // 163840
#define SMEM_M1F (3*(2*64*80 + 2*20480))    // 153600

// ================= single-pass bf16 GEMM for hU (gate path) ==============
// A is the fp16 h mirror; converted to bf16 (hi) on the fly.
__global__ __launch_bounds__(512, 1)
void hU_gemm(const __half* __restrict__ A, const __nv_bfloat16* __restrict__ Bh,
             __half* __restrict__ Cout)
{
    constexpr int K = HD;
    constexpr uint32_t APL = 10240u, STAGE_ = 30720u;
    extern __shared__ char sm[];
    const int tid = threadIdx.x;
    const int rowBase = (int)blockIdx.x << 7;
    const int lane = tid & 31, wid = tid >> 5;
    const int wm = wid >> 2, wn = wid & 3;
    const int g = lane >> 3, r = lane & 7;
    const int tq = lane >> 2, tr = lane & 3;
    const uint32_t sb = smem_addr(sm);
    const int nch = K >> 5;

    const int a_row = tid >> 2, a_seg = tid & 3;
    const __half* a_src = A + (size_t)(rowBase + a_row)*K + (a_seg << 3);
    const uint32_t a_off = (uint32_t)a_row*80u + (uint32_t)a_seg*16u;

    auto issue_B = [&](uint32_t st, int c){
        #pragma unroll
        for (int i = 0; i < 2; ++i){
            int idx = tid + (i << 9);
            int row = idx >> 2, seg = idx & 3;
            CPA16(st + APL + (uint32_t)row*80u + (uint32_t)seg*16u,
                  Bh + (size_t)row*K + (c << 5) + (seg << 3));
        }
        CP_COMMIT();
    };

    float acc[64];
    #pragma unroll
    for (int i = 0; i < 64; ++i) acc[i] = 0.f;

    {
        uint4 v = *(const uint4*)a_src;
        issue_B(sb, 0);
        *(uint4*)(sm + a_off) = cvt_h8_bf8(v);
        CP_WAIT0();
    }
    __syncthreads();

    for (int c = 0; c < nch; ++c){
        const uint32_t st = sb + (c & 1)*STAGE_;
        const int nc = c + 1;
        uint4 v;
        if (nc < nch){
            v = *(const uint4*)(a_src + (nc << 5));
            issue_B(sb + (nc & 1)*STAGE_, nc);
        }

        #pragma unroll
        for (int ki = 0; ki < 2; ++ki){
            uint32_t ah[2][4];
            {
                int arow = wm*32 + (g & 1)*8 + r;
                uint32_t off = (uint32_t)(arow*PADK + ki*16 + (g >> 1)*8) * 2;
                ldsm4(st + off,             ah[0][0], ah[0][1], ah[0][2], ah[0][3]);
                ldsm4(st + off + 16*PADK*2, ah[1][0], ah[1][1], ah[1][2], ah[1][3]);
            }
            #pragma unroll
            for (int ng = 0; ng < 2; ++ng){
                uint32_t bhf[4][2];
                int nrow = wn*64 + ng*32 + (g >> 1)*8 + r;
                uint32_t off = (uint32_t)(nrow*PADK + ki*16 + (g & 1)*8) * 2;
                ldsm4(st + APL + off,             bhf[0][0], bhf[0][1], bhf[1][0], bhf[1][1]);
                ldsm4(st + APL + off + 16*PADK*2, bhf[2][0], bhf[2][1], bhf[3][0], bhf[3][1]);
                #pragma unroll
                for (int mi = 0; mi < 2; ++mi)
                    #pragma unroll
                    for (int j = 0; j < 4; ++j)
                        mma16816(acc + ((mi*8) + ng*4 + j)*4, ah[mi], bhf[j]);
            }
        }

        if (nc < nch){
            *(uint4*)(sm + (nc & 1)*STAGE_ + a_off) = cvt_h8_bf8(v);
            CP_WAIT0();
        }
        __syncthreads();
    }

    #pragma unroll
    for (int mi = 0; mi < 2; ++mi)
        #pragma unroll
        for (int ni = 0; ni < 8; ++ni){
            const float* a = acc + (mi*8 + ni)*4;
            int gcol = wn*64 + ni*8 + tr*2;
            int r0 = rowBase + wm*32 + mi*16 + tq;
            *(__half2*)&Cout[(size_t)r0*HD + gcol]     = __floats2half2_rn(a[0], a[1]);
            *(__half2*)&Cout[(size_t)(r0+8)*HD + gcol] = __floats2half2_rn(a[2], a[3]);
        }
}

// ================= fused invariants: fz16, fh16(+h1+h16), rx16 ===========
__global__ __launch_bounds__(512, 1)
void inv3_gemm(const float* __restrict__ A,
               const __nv_bfloat16* __restrict__ Wzh, const __nv_bfloat16* __restrict__ Wzl,
               const __nv_bfloat16* __restrict__ Whh, const __nv_bfloat16* __restrict__ Whl,
               const __nv_bfloat16* __restrict__ Wrh, const __nv_bfloat16* __restrict__ Wrl,
               const float* __restrict__ b_z, const float* __restrict__ b_h,
               const float* __restrict__ b_ur,
               __half* __restrict__ fz, __half* __restrict__ fh,
               float* __restrict__ h1, __half* __restrict__ h16,
               __half* __restrict__ rx)
{
    constexpr int K = IND;
    constexpr uint32_t B_OFF = 81920u;
    constexpr uint32_t BPL = 20480u, BSTG = 40960u;
    extern __shared__ char sm[];
    const int tid = threadIdx.x;
    const int rowBase = (int)blockIdx.x << 7;
    const int lane = tid & 31, wid = tid >> 5;
    const int wm = wid >> 2, wn = wid & 3;
    const int g = lane >> 3, r = lane & 7;
    const int tq = lane >> 2, tr = lane & 3;
    const uint32_t sb = smem_addr(sm);

    #pragma unroll
    for (int u = 0; u < 4; ++u){
        int idx = tid + (u << 9);
        int row = idx >> 4, gi = idx & 15;
        int t = gi >> 2, seg = gi & 3;
        const float* p = A + (size_t)(rowBase + row)*K + (gi << 3);
        float4 v0 = *(const float4*)p, v1 = *(const float4*)(p + 4);
        uint4 hi, lo; cvt_split8(v0, v1, hi, lo);
        uint32_t off = (uint32_t)t*20480u + (uint32_t)row*80u + (uint32_t)seg*16u;
        *(uint4*)(sm + off)          = hi;
        *(uint4*)(sm + off + 10240u) = lo;
    }
    __syncthreads();

    const __nv_bfloat16* Bhs[3] = {Wzh, Whh, Wrh};
    const __nv_bfloat16* Bls[3] = {Wzl, Whl, Wrl};
    const float* biases[3] = {b_z, b_h, b_ur};

    #pragma unroll
    for (int op = 0; op < 3; ++op){
        const __nv_bfloat16* Bh = Bhs[op];
        const __nv_bfloat16* Bl = Bls[op];

        auto issue_B = [&](uint32_t st, int c){
            #pragma unroll
            for (int i = 0; i < 4; ++i){
                int idx = tid + (i << 9);
                int plane = idx >> 10;
                int rem = idx & 1023;
                int row = rem >> 2, seg = rem & 3;
                const __nv_bfloat16* src = (plane ? Bl : Bh)
                    + (size_t)row*K + (c << 5) + (seg << 3);
                CPA16(st + (uint32_t)plane*BPL + (uint32_t)row*80u + (uint32_t)seg*16u, src);
            }
            CP_COMMIT();
        };

        float acc[64];
        #pragma unroll
        for (int i = 0; i < 64; ++i) acc[i] = 0.f;

        issue_B(sb + B_OFF, 0);
        CP_WAIT0();
        __syncthreads();

        for (int c = 0; c < 4; ++c){
            const uint32_t aBase = sb + (uint32_t)c*20480u;
            const uint32_t bBase = sb + B_OFF + (uint32_t)(c & 1)*BSTG;
            if (c + 1 < 4) issue_B(sb + B_OFF + (uint32_t)((c+1) & 1)*BSTG, c+1);

            #pragma unroll
            for (int ki = 0; ki < 2; ++ki){
                uint32_t ah[2][4], al[2][4];
                {
                    int arow = wm*32 + (g & 1)*8 + r;
                    uint32_t off = (uint32_t)(arow*PADK + ki*16 + (g >> 1)*8) * 2;
                    ldsm4(aBase + off,                  ah[0][0], ah[0][1], ah[0][2], ah[0][3]);
                    ldsm4(aBase + off + 16*PADK*2,      ah[1][0], ah[1][1], ah[1][2], ah[1][3]);
                    ldsm4(aBase + 10240u + off,             al[0][0], al[0][1], al[0][2], al[0][3]);
                    ldsm4(aBase + 10240u + off + 16*PADK*2, al[1][0], al[1][1], al[1][2], al[1][3]);
                }
                #pragma unroll
                for (int ng = 0; ng < 2; ++ng){
                    uint32_t bhf[4][2], blf[4][2];
                    int nrow = wn*64 + ng*32 + (g >> 1)*8 + r;
                    uint32_t off = (uint32_t)(nrow*PADK + ki*16 + (g & 1)*8) * 2;
                    ldsm4(bBase + off,                 bhf[0][0], bhf[0][1], bhf[1][0], bhf[1][1]);
                    ldsm4(bBase + off + 16*PADK*2,     bhf[2][0], bhf[2][1], bhf[3][0], bhf[3][1]);
                    ldsm4(bBase + BPL + off,             blf[0][0], blf[0][1], blf[1][0], blf[1][1]);
                    ldsm4(bBase + BPL + off + 16*PADK*2, blf[2][0], blf[2][1], blf[3][0], blf[3][1]);
                    #pragma unroll
                    for (int mi = 0; mi < 2; ++mi)
                        #pragma unroll
                        for (int j = 0; j < 4; ++j){
                            float* a = acc + ((mi*8) + ng*4 + j)*4;
                            mma16816(a, ah[mi], bhf[j]);
                            mma16816(a, ah[mi], blf[j]);
                            mma16816(a, al[mi], bhf[j]);
                        }
                }
            }
            if (c + 1 < 4) CP_WAIT0();
            __syncthreads();
        }

        #pragma unroll
        for (int mi = 0; mi < 2; ++mi)
            #pragma unroll
            for (int ni = 0; ni < 8; ++ni){
                const float* a = acc + (mi*8 + ni)*4;
                int gcol = wn*64 + ni*8 + tr*2;
                int r0 = rowBase + wm*32 + mi*16 + tq;
                float2 b = *(const float2*)&biases[op][gcol];
                size_t o0 = (size_t)r0*HD + gcol;
                size_t o1 = (size_t)(r0+8)*HD + gcol;
                float2 u0 = make_float2(a[0]+b.x, a[1]+b.y);
                float2 u1 = make_float2(a[2]+b.x, a[3]+b.y);
                if (op == 0) {
                    *(__half2*)&fz[o0] = __floats2half2_rn(u0.x, u0.y);
                    *(__half2*)&fz[o1] = __floats2half2_rn(u1.x, u1.y);
                } else if (op == 1) {
                    *(__half2*)&fh[o0] = __floats2half2_rn(u0.x, u0.y);
                    *(__half2*)&fh[o1] = __floats2half2_rn(u1.x, u1.y);
                    float2 z0 = __half22float2(*(const __half2*)&fz[o0]);
                    float2 z1 = __half22float2(*(const __half2*)&fz[o1]);
                    float2 w0 = make_float2(sigm(z0.x)*tanhf(u0.x), sigm(z0.y)*tanhf(u0.y));
                    float2 w1 = make_float2(sigm(z1.x)*tanhf(u1.x), sigm(z1.y)*tanhf(u1.y));
                    if (r0 == 0) w0 = make_float2(0.f, 0.f);   // null message row
                    *(float2*)&h1[o0] = w0;
                    *(float2*)&h1[o1] = w1;
                    *(__half2*)&h16[o0] = __floats2half2_rn(w0.x, w0.y);
                    *(__half2*)&h16[o1] = __floats2half2_rn(w1.x, w1.y);
                } else {
                    *(__half2*)&rx[o0] = __floats2half2_rn(u0.x, u0.y);
                    *(__half2*)&rx[o1] = __floats2half2_rn(u1.x, u1.y);
                }
            }
    }
}

// ================= fp16 single-pass GRU-step dual GEMM ====================
__global__ __launch_bounds__(512, 1)
void mode1f(const __half* __restrict__ A1, const __half* __restrict__ B1,
            const __half* __restrict__ A2, const __half* __restrict__ B2,
            const __half* __restrict__ fz, const __half* __restrict__ fh,
            float* __restrict__ C, __half* __restrict__ C16)
{
    constexpr int K = HD;                          // 256, 8 chunks
    constexpr uint32_t APL = 5120u, ABYTES = 10240u;
    constexpr uint32_t BPL = 20480u, STG = 51200u;
    extern __shared__ char sm[];
    const int tid = threadIdx.x;
    const int rowBase = (int)blockIdx.x << 6;      // MT=64
    const int lane = tid & 31, wid = tid >> 5;
    const int wm = wid >> 3, wn = wid & 7;         // 2 x 8 warps
    const int g = lane >> 3, r = lane & 7;
    const int tq = lane >> 2, tr = lane & 3;
    const uint32_t sb = smem_addr(sm);

    const int a_op = tid >> 8, a_rem = tid & 255;
    const int a_row = a_rem >> 2, a_seg = a_rem & 3;
    const __half* a_src = ((a_op == 0) ? A1 : A2)
        + (size_t)(rowBase + a_row)*K + (a_seg << 3);
    const uint32_t a_dst = (uint32_t)a_op*APL + (uint32_t)a_row*80u + (uint32_t)a_seg*16u;

    auto issue = [&](uint32_t st, int c){
        CPA16(st + a_dst, a_src + (c << 5));
        #pragma unroll
        for (int i = 0; i < 4; ++i){
            int idx = tid + (i << 9);
            int op = idx >> 10;
            int rem = idx & 1023;
            int row = rem >> 2, seg = rem & 3;
            const __half* src = ((op == 0) ? B1 : B2)
                + (size_t)row*K + (c << 5) + (seg << 3);
            CPA16(st + ABYTES + (uint32_t)op*BPL + (uint32_t)row*80u + (uint32_t)seg*16u, src);
        }
        CP_COMMIT();
    };

    float acc[64];
    #pragma unroll
    for (int i = 0; i < 64; ++i) acc[i] = 0.f;

    issue(sb, 0);
    issue(sb + STG, 1);

    for (int c = 0; c < 8; ++c){
        if (c + 1 < 8) { CP_WAIT1(); } else { CP_WAIT0(); }
        __syncthreads();
        if (c + 2 < 8) issue(sb + ((c+2)%3)*STG, c+2);
        const uint32_t st = sb + (c%3)*STG;

        #pragma unroll
        for (int op = 0; op < 2; ++op){
            const uint32_t aBase = st + (uint32_t)op*APL;
            const uint32_t bBase = st + ABYTES + (uint32_t)op*BPL;
            #pragma unroll
            for (int ki = 0; ki < 2; ++ki){
                uint32_t ah[2][4];
                {
                    int arow = wm*32 + (g & 1)*8 + r;
                    uint32_t off = (uint32_t)(arow*PADK + ki*16 + (g >> 1)*8) * 2;
                    ldsm4(aBase + off,             ah[0][0], ah[0][1], ah[0][2], ah[0][3]);
                    ldsm4(aBase + off + 16*PADK*2, ah[1][0], ah[1][1], ah[1][2], ah[1][3]);
                }
                uint32_t bf[4][2];
                {
                    int nrow = wn*32 + (g >> 1)*8 + r;
                    uint32_t off = (uint32_t)(nrow*PADK + ki*16 + (g & 1)*8) * 2;
                    ldsm4(bBase + off,             bf[0][0], bf[0][1], bf[1][0], bf[1][1]);
                    ldsm4(bBase + off + 16*PADK*2, bf[2][0], bf[2][1], bf[3][0], bf[3][1]);
                }
                #pragma unroll
                for (int mi = 0; mi < 2; ++mi)
                    #pragma unroll
                    for (int j = 0; j < 4; ++j)
                        mma16816h(acc + ((op*2 + mi)*4 + j)*4, ah[mi], bf[j]);
            }
        }
    }

    #pragma unroll
    for (int mi = 0; mi < 2; ++mi)
        #pragma unroll
        for (int ni = 0; ni < 4; ++ni){
            const float* a1 = acc + ((0*2 + mi)*4 + ni)*4;
            const float* a2 = acc + ((1*2 + mi)*4 + ni)*4;
            int gcol = wn*32 + ni*8 + tr*2;
            int r0 = rowBase + wm*32 + mi*16 + tq;
            size_t o0 = (size_t)r0*HD + gcol;
            size_t o1 = (size_t)(r0+8)*HD + gcol;
            float2 za = __half22float2(*(const __half2*)&fz[o0]);
            float2 zb = __half22float2(*(const __half2*)&fz[o1]);
            float2 ha = __half22float2(*(const __half2*)&fh[o0]);
            float2 hb = __half22float2(*(const __half2*)&fh[o1]);
            float2 sa = __half22float2(*(const __half2*)&A1[o0]);
            float2 sb2 = __half22float2(*(const __half2*)&A1[o1]);
            float z0 = sigm(za.x + a1[0]);
            float z1 = sigm(za.y + a1[1]);
            float z2 = sigm(zb.x + a1[2]);
            float z3 = sigm(zb.y + a1[3]);
            float p0 = tanhf(ha.x + a2[0]);
            float p1 = tanhf(ha.y + a2[1]);
            float p2 = tanhf(hb.x + a2[2]);
            float p3 = tanhf(hb.y + a2[3]);
            float2 u0 = make_float2((1.f - z0)*sa.x + z0*p0, (1.f - z1)*sa.y + z1*p1);
            float2 u1 = make_float2((1.f - z2)*sb2.x + z2*p2, (1.f - z3)*sb2.y + z3*p3);
            if (r0 == 0) u0 = make_float2(0.f, 0.f);
            *(float2*)&C[o0] = u0;
            *(float2*)&C[o1] = u1;
            *(__half2*)&C16[o0] = __floats2half2_rn(u0.x, u0.y);
            *(__half2*)&C16[o1] = __floats2half2_rn(u1.x, u1.y);
        }
}

// ================= MODE2 (output layer, bf16 3-pass) ======================
__global__ __launch_bounds__(512, 1)
void mode2_gemm(const float* __restrict__ A1, int K1,
                const __nv_bfloat16* __restrict__ B1h, const __nv_bfloat16* __restrict__ B1l,
                const float* __restrict__ A2, int K2,
                const __nv_bfloat16* __restrict__ B2h, const __nv_bfloat16* __restrict__ B2l,
                int M, const float* __restrict__ bias, const float* __restrict__ maskv,
                float* __restrict__ C)
{
    extern __shared__ char sm[];
    const int tid = threadIdx.x;
    const int rowBase = (int)blockIdx.x << 7;
    const int lane = tid & 31, wid = tid >> 5;
    const int wm = wid >> 2, wn = wid & 3;
    const int tq = lane >> 2, tr = lane & 3;

    float acc[64];
    #pragma unroll
    for (int i = 0; i < 64; ++i) acc[i] = 0.f;

    run_phase<128,1>(A1, nullptr, K1, B1h, B1l, nullptr, nullptr, acc, sm, tid, rowBase, M);
    run_phase<128,1>(A2, nullptr, K2, B2h, B2l, nullptr, nullptr, acc, sm, tid, rowBase, M);

    #pragma unroll
    for (int mi = 0; mi < 2; ++mi)
        #pragma unroll
        for (int ni = 0; ni < 8; ++ni) {
            const float* a = acc + (mi*8 + ni)*4;
            int gcol = wn*64 + ni*8 + tr*2;
            int r0 = rowBase + wm*32 + mi*16 + tq;
            float2 b = *(const float2*)&bias[gcol];
            if (r0 < M) {
                float m = maskv[r0];
                *(float2*)&C[(size_t)r0*HD + gcol] =
                    make_float2(fmaxf(a[0]+b.x, 0.f)*m, fmaxf(a[1]+b.y, 0.f)*m);
            }
            if (r0 + 8 < M) {
                float m = maskv[r0+8];
                *(float2*)&C[(size_t)(r0+8)*HD + gcol] =
                    make_float2(fmaxf(a[2]+b.x, 0.f)*m, fmaxf(a[3]+b.y, 0.f)*m);
            }
        }
}

// transpose + bf16 hi/lo split of W[K,256] -> [256,K]
__global__ void prep_w(const float* __restrict__ W, __nv_bfloat16* __restrict__ oh,
                       __nv_bfloat16* __restrict__ ol, int K, int kshift)
{
    int i = blockIdx.x * blockDim.x + threadIdx.x;
    int k = i & (K - 1);
    int n = i >> kshift;
    float x = W[(size_t)k * HD + n];
    __nv_bfloat16 h = __float2bfloat16_rn(x);
    __nv_bfloat16 lo = __float2bfloat16_rn(x - __bfloat162float(h));
    oh[i] = h; ol[i] = lo;
}

// transpose to fp16 [256,K]
__global__ void prep_w16(const float* __restrict__ W, __half* __restrict__ o,
                         int K, int kshift)
{
    int i = blockIdx.x * blockDim.x + threadIdx.x;
    int k = i & (K - 1);
    int n = i >> kshift;
    o[i] = __float2half_rn(W[(size_t)k * HD + n]);
}

__global__ void gather_msgs(const __half* __restrict__ h16, const __half* __restrict__ hU,
                            const __half* __restrict__ rx, const int* __restrict__ bg,
                            __half* __restrict__ sumh, __half* __restrict__ sumg)
{
    __shared__ int s_nb[4][NBR];
    int e = blockIdx.x * 4 + threadIdx.y;
    if (threadIdx.x < NBR) s_nb[threadIdx.y][threadIdx.x] = bg[e*NBR + threadIdx.x];
    __syncthreads();
    int c = threadIdx.x << 2;
    size_t base = (size_t)e*HD + c;
    uint2 rx4 = *(const uint2*)(rx + base);
    float2 r01 = __half22float2(*reinterpret_cast<__half2*>(&rx4.x));
    float2 r23 = __half22float2(*reinterpret_cast<__half2*>(&rx4.y));
    float4 sh = make_float4(0.f,0.f,0.f,0.f);
    float4 sg = make_float4(0.f,0.f,0.f,0.f);
    #pragma unroll
    for (int j = 0; j < NBR; ++j) {
        size_t nb = (size_t)s_nb[threadIdx.y][j]*HD + c;
        uint2 hq = *(const uint2*)(h16 + nb);
        float2 h01 = __half22float2(*reinterpret_cast<__half2*>(&hq.x));
        float2 h23 = __half22float2(*reinterpret_cast<__half2*>(&hq.y));
        uint2 hu4 = *(const uint2*)(hU + nb);
        float2 u01 = __half22float2(*reinterpret_cast<__half2*>(&hu4.x));
        float2 u23 = __half22float2(*reinterpret_cast<__half2*>(&hu4.y));
        sh.x += h01.x; sh.y += h01.y; sh.z += h23.x; sh.w += h23.y;
        sg.x += sigm(r01.x + u01.x) * h01.x;
        sg.y += sigm(r01.y + u01.y) * h01.y;
        sg.z += sigm(r23.x + u23.x) * h23.x;
        sg.w += sigm(r23.y + u23.y) * h23.y;
    }
    __half2 sh01 = __floats2half2_rn(sh.x, sh.y), sh23 = __floats2half2_rn(sh.z, sh.w);
    __half2 sg01 = __floats2half2_rn(sg.x, sg.y), sg23 = __floats2half2_rn(sg.z, sg.w);
    *(uint2*)(sumh + base) = make_uint2(h2u(sh01), h2u(sh23));
    *(uint2*)(sumg + base) = make_uint2(h2u(sg01), h2u(sg23));
}

__global__ void gather_nodes(const float* __restrict__ h, const int* __restrict__ ag,
                             float* __restrict__ nei)
{
    __shared__ int s_nb[4][NBR];
    int v = blockIdx.x * 4 + threadIdx.y;
    if (threadIdx.x < NBR) s_nb[threadIdx.y][threadIdx.x] = ag[v*NBR + threadIdx.x];
    __syncthreads();
    int c = threadIdx.x << 2;
    float4 s = make_float4(0.f,0.f,0.f,0.f);
    #pragma unroll
    for (int j = 0; j < NBR; ++j) {
        size_t nb = (size_t)s_nb[threadIdx.y][j]*HD + c;
        float4 hv = *(const float4*)&h[nb];
        s.x += hv.x; s.y += hv.y; s.z += hv.z; s.w += hv.w;
    }
    *(float4*)&nei[(size_t)v*HD + c] = s;
}

extern "C" void kernel_launch(void* const* d_in, const int* in_sizes, int n_in,
                              void* d_out, int out_size)
{
    const float* fnode  = (const float*)d_in[0];
    const float* fmess  = (const float*)d_in[1];
    const int*   agraph = (const int*)  d_in[2];
    const int*   bgraph = (const int*)  d_in[3];
    const float* mask   = (const float*)d_in[4];
    const float* W_z    = (const float*)d_in[5];
    const float* b_z    = (const float*)d_in[6];
    const float* W_r    = (const float*)d_in[7];
    const float* U_r    = (const float*)d_in[8];
    const float* b_ur   = (const float*)d_in[9];
    const float* W_h    = (const float*)d_in[10];
    const float* b_h    = (const float*)d_in[11];
    const float* W_o    = (const float*)d_in[12];
    const float* b_o    = (const float*)d_in[13];

    float* out_node = (float*)d_out;
    float* out_h    = out_node + (size_t)NN*HD;

    float *hA, *nei;
    __half *h16, *fz16, *fh16, *sumh16, *sumg16, *hU16, *rx16, *wz16, *wh16;
    __nv_bfloat16 *bh, *bl;
    cudaGetSymbolAddress((void**)&hA,     g_hA);
    cudaGetSymbolAddress((void**)&nei,    g_nei);
    cudaGetSymbolAddress((void**)&h16,    g_h16);
    cudaGetSymbolAddress((void**)&fz16,   g_fz16);
    cudaGetSymbolAddress((void**)&fh16,   g_fh16);
    cudaGetSymbolAddress((void**)&sumh16, g_sumh16);
    cudaGetSymbolAddress((void**)&sumg16, g_sumg16);
    cudaGetSymbolAddress((void**)&hU16,   g_hU16);
    cudaGetSymbolAddress((void**)&rx16,   g_rx16);
    cudaGetSymbolAddress((void**)&wz16,   g_wz16);
    cudaGetSymbolAddress((void**)&wh16,   g_wh16);
    cudaGetSymbolAddress((void**)&bh,     g_bh);
    cudaGetSymbolAddress((void**)&bl,     g_bl);

    cudaFuncSetAttribute((const void*)inv3_gemm,
                         cudaFuncAttributeMaxDynamicSharedMemorySize, SMEM_I3);
    cudaFuncSetAttribute((const void*)hU_gemm,
                         cudaFuncAttributeMaxDynamicSharedMemorySize, SMEM_HU);
    cudaFuncSetAttribute((const void*)mode1f,
                         cudaFuncAttributeMaxDynamicSharedMemorySize, SMEM_M1F);
    cudaFuncSetAttribute((const void*)mode2_gemm,
                         cudaFuncAttributeMaxDynamicSharedMemorySize, SMEM_M0);

    const int gE128 = NM / 128;               // 625
    const int gE64  = NM / 64;                // 1250
    const int gV    = NNP / 128;              // 274

    // weight preps
    prep_w<<<256, 256>>>(U_r, bh+OFF_UR,  bl+OFF_UR,  HD, 8);
    prep_w<<<128, 256>>>(W_z, bh+OFF_WZT, bl+OFF_WZT, IND, 7);
    prep_w<<<128, 256>>>(W_h, bh+OFF_WHT, bl+OFF_WHT, IND, 7);
    prep_w<<<128, 256>>>(W_r, bh+OFF_WR,  bl+OFF_WR,  IND, 7);

    // fused invariants (fz16, fh16, h1 + h16 mirror, rx16)
    inv3_gemm<<<gE128, 512, SMEM_I3>>>(fmess,
        bh+OFF_WZT, bl+OFF_WZT, bh+OFF_WHT, bl+OFF_WHT, bh+OFF_WR, bl+OFF_WR,
        b_z, b_h, b_ur, fz16, fh16, out_h, h16, rx16);

    // fp16 weight preps for the GRU-step GEMMs (+ output-layer preps)
    prep_w16<<<256, 256>>>(W_z + (size_t)IND*HD, wz16, HD, 8);
    prep_w16<<<256, 256>>>(W_h + (size_t)IND*HD, wh16, HD, 8);
    prep_w<<<128, 256>>>(W_o,                  bh+OFF_WOT, bl+OFF_WOT, IND, 7);
    prep_w<<<256, 256>>>(W_o + (size_t)IND*HD, bh+OFF_WOB, bl+OFF_WOB, HD, 8);

    float* hc = out_h;
    float* hn = hA;
    for (int d = 1; d < DEPTH; ++d) {
        hU_gemm<<<gE128, 512, SMEM_HU>>>(h16, bh+OFF_UR, hU16);
        gather_msgs<<<NM/4, dim3(64,4)>>>(h16, hU16, rx16, bgraph, sumh16, sumg16);
        mode1f<<<gE64, 512, SMEM_M1F>>>(sumh16, wz16, sumg16, wh16,
                                        fz16, fh16, hn, h16);
        float* t = hc; hc = hn; hn = t;
    }

    gather_nodes<<<NN/4, dim3(64,4)>>>(hc, agraph, nei);
    mode2_gemm<<<gV, 512, SMEM_M0>>>(fnode, IND, bh+OFF_WOT, bl+OFF_WOT,
                                     nei, HD, bh+OFF_WOB, bl+OFF_WOB,
                                     NN, b_o, mask, out_node);
}

// round 14
// speedup vs baseline: 1.4074x; 1.0452x over previous
#include <cuda_runtime.h>
#include <cuda_bf16.h>
#include <cuda_fp16.h>
#include <math.h>
#include <cstdint>

#define NN 35000
#define NM 80000
#define NBR 6
#define IND 128
#define HD 256
#define DEPTH 5
#define NNP 35072

// ---------------- scratch (__device__ globals; no allocs) ----------------
__device__ float g_nei [(size_t)NNP*HD];
__device__ __align__(16) __half g_h16  [(size_t)NM*HD];   // fp16 h (steps 1..4)
__device__ __align__(16) __half g_fz16 [(size_t)NM*HD];
__device__ __align__(16) __half g_fh16 [(size_t)NM*HD];
__device__ __align__(16) __half g_sumh16[(size_t)NM*HD];
__device__ __align__(16) __half g_sumg16[(size_t)NM*HD];
__device__ __align__(16) __half g_hU16[(size_t)NM*HD];
__device__ __align__(16) __half g_rx16[(size_t)NM*HD];
__device__ __align__(16) __half g_wz16[65536];
__device__ __align__(16) __half g_wh16[65536];

#define OFF_WZT 0
#define OFF_WHT 32768
#define OFF_WR  65536
#define OFF_WOT 98304
#define OFF_UR  131072
#define OFF_WOB 196608
__device__ __align__(16) __nv_bfloat16 g_bh[262144];
__device__ __align__(16) __nv_bfloat16 g_bl[262144];

__device__ __forceinline__ float sigm(float x){ return 1.0f/(1.0f+expf(-x)); }

// ---------------- mma / ldmatrix / cp.async helpers ----------------------
__device__ __forceinline__ uint32_t smem_addr(const void* p){
    return (uint32_t)__cvta_generic_to_shared(p);
}
__device__ __forceinline__ void ldsm4(uint32_t a, uint32_t& r0, uint32_t& r1,
                                      uint32_t& r2, uint32_t& r3){
    asm volatile("ldmatrix.sync.aligned.m8n8.x4.shared.b16 {%0,%1,%2,%3}, [%4];"
                 : "=r"(r0), "=r"(r1), "=r"(r2), "=r"(r3) : "r"(a));
}
__device__ __forceinline__ void mma16816(float* c, const uint32_t* a, const uint32_t* b){
    asm volatile(
        "mma.sync.aligned.m16n8k16.row.col.f32.bf16.bf16.f32 "
        "{%0,%1,%2,%3}, {%4,%5,%6,%7}, {%8,%9}, {%0,%1,%2,%3};"
        : "+f"(c[0]), "+f"(c[1]), "+f"(c[2]), "+f"(c[3])
        : "r"(a[0]), "r"(a[1]), "r"(a[2]), "r"(a[3]), "r"(b[0]), "r"(b[1]));
}
__device__ __forceinline__ void mma16816h(float* c, const uint32_t* a, const uint32_t* b){
    asm volatile(
        "mma.sync.aligned.m16n8k16.row.col.f32.f16.f16.f32 "
        "{%0,%1,%2,%3}, {%4,%5,%6,%7}, {%8,%9}, {%0,%1,%2,%3};"
        : "+f"(c[0]), "+f"(c[1]), "+f"(c[2]), "+f"(c[3])
        : "r"(a[0]), "r"(a[1]), "r"(a[2]), "r"(a[3]), "r"(b[0]), "r"(b[1]));
}
#define CPA16(dst, src) \
    asm volatile("cp.async.cg.shared.global [%0], [%1], 16;" :: "r"(dst), "l"(src))
#define CP_COMMIT() asm volatile("cp.async.commit_group;" ::: "memory")
#define CP_WAIT0()  asm volatile("cp.async.wait_group 0;" ::: "memory")
#define CP_WAIT1()  asm volatile("cp.async.wait_group 1;" ::: "memory")

__device__ __forceinline__ void cvt_split8(float4 v0, float4 v1, uint4& hi, uint4& lo){
    float f[8] = {v0.x,v0.y,v0.z,v0.w,v1.x,v1.y,v1.z,v1.w};
    uint32_t hh[8], ll[8];
    #pragma unroll
    for (int j = 0; j < 8; ++j) {
        __nv_bfloat16 h = __float2bfloat16_rn(f[j]);
        float hf = __bfloat162float(h);
        __nv_bfloat16 l = __float2bfloat16_rn(f[j] - hf);
        hh[j] = (uint32_t)__bfloat16_as_ushort(h);
        ll[j] = (uint32_t)__bfloat16_as_ushort(l);
    }
    hi = make_uint4(hh[0]|(hh[1]<<16), hh[2]|(hh[3]<<16), hh[4]|(hh[5]<<16), hh[6]|(hh[7]<<16));
    lo = make_uint4(ll[0]|(ll[1]<<16), ll[2]|(ll[3]<<16), ll[4]|(ll[5]<<16), ll[6]|(ll[7]<<16));
}
// 8 fp16 -> 8 bf16 (hi only)
__device__ __forceinline__ uint4 cvt_h8_bf8(uint4 v){
    const __half* hp = (const __half*)&v;
    uint32_t hh[8];
    #pragma unroll
    for (int j = 0; j < 8; ++j)
        hh[j] = (uint32_t)__bfloat16_as_ushort(__float2bfloat16_rn(__half2float(hp[j])));
    return make_uint4(hh[0]|(hh[1]<<16), hh[2]|(hh[3]<<16), hh[4]|(hh[5]<<16), hh[6]|(hh[7]<<16));
}
__device__ __forceinline__ uint32_t h2u(__half2 v){ return *(uint32_t*)&v; }

#define PADK 40

// ================= 3-pass bf16 phase (mode2 only) =========================
template<int MT, int NA>
__device__ __forceinline__ void run_phase(
    const float* __restrict__ A1, const float* __restrict__ A2, int K,
    const __nv_bfloat16* __restrict__ B1h, const __nv_bfloat16* __restrict__ B1l,
    const __nv_bfloat16* __restrict__ B2h, const __nv_bfloat16* __restrict__ B2l,
    float* acc, char* sm, int tid, int rowBase, int M)
{
    constexpr int WM = MT/32;
    constexpr int WN = 16/WM;
    constexpr int NSPAN = 256/WN;
    constexpr int NFR = NSPAN/8;
    constexpr uint32_t APL = MT*80u;
    constexpr uint32_t A_BYTES = NA*2u*APL;
    constexpr uint32_t BPL = 20480u;
    constexpr uint32_t STAGE_ = A_BYTES + NA*2u*BPL;
    constexpr int NB = NA*4;
    const int lane = tid & 31, wid = tid >> 5;
    const int wm = wid / WN, wn = wid % WN;
    const int g = lane >> 3, r = lane & 7;
    const uint32_t sb = smem_addr(sm);
    const int nch = K >> 5;

    const int a_op  = tid / (MT*4);
    const int a_rem = tid % (MT*4);
    const int a_row = a_rem >> 2, a_seg = a_rem & 3;
    const int grow = rowBase + a_row;
    const bool a_ok = (grow < M);
    const float* a_src = ((a_op == 0) ? A1 : A2) + (size_t)grow*K + (a_seg << 3);
    const uint32_t a_off = (uint32_t)a_op*2u*APL + (uint32_t)a_row*80u + (uint32_t)a_seg*16u;

    auto issue_B = [&](uint32_t st, int c){
        #pragma unroll
        for (int i = 0; i < NB; ++i){
            int idx = tid + (i << 9);
            int op = idx >> 11;
            int rem = idx & 2047;
            int plane = rem >> 10;
            int rem2 = rem & 1023;
            int row = rem2 >> 2, seg = rem2 & 3;
            const __nv_bfloat16* Bp = (op == 0) ? (plane ? B1l : B1h)
                                                : (plane ? B2l : B2h);
            const __nv_bfloat16* src = Bp + (size_t)row*K + (c << 5) + (seg << 3);
            uint32_t dst = st + A_BYTES + (uint32_t)op*(2u*BPL) + (uint32_t)plane*BPL
                         + (uint32_t)row*80u + (uint32_t)seg*16u;
            CPA16(dst, src);
        }
        CP_COMMIT();
    };

    {
        float4 v0 = make_float4(0.f,0.f,0.f,0.f), v1 = v0;
        if (a_ok){ v0 = *(const float4*)a_src; v1 = *(const float4*)(a_src + 4); }
        issue_B(sb, 0);
        uint4 hi, lo; cvt_split8(v0, v1, hi, lo);
        *(uint4*)(sm + a_off)       = hi;
        *(uint4*)(sm + a_off + APL) = lo;
        CP_WAIT0();
    }
    __syncthreads();

    for (int c = 0; c < nch; ++c){
        const uint32_t st = sb + (c & 1)*STAGE_;
        const int nc = c + 1;
        float4 v0, v1;
        if (nc < nch){
            v0 = make_float4(0.f,0.f,0.f,0.f); v1 = v0;
            if (a_ok){
                const float* p = a_src + (nc << 5);
                v0 = *(const float4*)p; v1 = *(const float4*)(p + 4);
            }
            issue_B(sb + (nc & 1)*STAGE_, nc);
        }

        #pragma unroll
        for (int op = 0; op < NA; ++op){
            const uint32_t aBase = st + (uint32_t)op*2u*APL;
            const uint32_t bBase = st + A_BYTES + (uint32_t)op*(2u*BPL);
            #pragma unroll
            for (int ki = 0; ki < 2; ++ki){
                uint32_t ah[2][4], al[2][4];
                {
                    int arow = wm*32 + (g & 1)*8 + r;
                    uint32_t off = (uint32_t)(arow*PADK + ki*16 + (g >> 1)*8) * 2;
                    ldsm4(aBase + off,                   ah[0][0], ah[0][1], ah[0][2], ah[0][3]);
                    ldsm4(aBase + off + 16*PADK*2,       ah[1][0], ah[1][1], ah[1][2], ah[1][3]);
                    ldsm4(aBase + APL + off,             al[0][0], al[0][1], al[0][2], al[0][3]);
                    ldsm4(aBase + APL + off + 16*PADK*2, al[1][0], al[1][1], al[1][2], al[1][3]);
                }
                #pragma unroll
                for (int ng = 0; ng < NFR/4; ++ng){
                    uint32_t bhf[4][2], blf[4][2];
                    int nrow = wn*NSPAN + ng*32 + (g >> 1)*8 + r;
                    uint32_t off = (uint32_t)(nrow*PADK + ki*16 + (g & 1)*8) * 2;
                    ldsm4(bBase + off,                 bhf[0][0], bhf[0][1], bhf[1][0], bhf[1][1]);
                    ldsm4(bBase + off + 16*PADK*2,     bhf[2][0], bhf[2][1], bhf[3][0], bhf[3][1]);
                    ldsm4(bBase + BPL + off,             blf[0][0], blf[0][1], blf[1][0], blf[1][1]);
                    ldsm4(bBase + BPL + off + 16*PADK*2, blf[2][0], blf[2][1], blf[3][0], blf[3][1]);
                    #pragma unroll
                    for (int mi = 0; mi < 2; ++mi)
                        #pragma unroll
                        for (int j = 0; j < 4; ++j){
                            float* a = acc + (((op*2 + mi)*NFR) + ng*4 + j)*4;
                            mma16816(a, ah[mi], bhf[j]);
                            mma16816(a, ah[mi], blf[j]);
                            mma16816(a, al[mi], bhf[j]);
                        }
                }
            }
        }

        if (nc < nch){
            char* nsm = sm + (nc & 1)*STAGE_;
            uint4 hi, lo; cvt_split8(v0, v1, hi, lo);
            *(uint4*)(nsm + a_off)       = hi;
            *(uint4*)(nsm + a_off + APL) = lo;
            CP_WAIT0();
        }
        __syncthreads();
    }
}

#define SMEM_M0  (2*(2*128*80 + 2*20480))   // 122880
#define SMEM_HU  (2*(128*80 + 20480))       // 61440
#define SMEM_I3  (4*20480 + 2*40960)        // 163840
#define SMEM_M1F (3*(2*64*80 + 2*20480))    // 153600

// ================= single-pass bf16 GEMM for hU (gate path) ==============
__global__ __launch_bounds__(512, 1)
void hU_gemm(const __half* __restrict__ A, const __nv_bfloat16* __restrict__ Bh,
             __half* __restrict__ Cout)
{
    constexpr int K = HD;
    constexpr uint32_t APL = 10240u, STAGE_ = 30720u;
    extern __shared__ char sm[];
    const int tid = threadIdx.x;
    const int rowBase = (int)blockIdx.x << 7;
    const int lane = tid & 31, wid = tid >> 5;
    const int wm = wid >> 2, wn = wid & 3;
    const int g = lane >> 3, r = lane & 7;
    const int tq = lane >> 2, tr = lane & 3;
    const uint32_t sb = smem_addr(sm);
    const int nch = K >> 5;

    const int a_row = tid >> 2, a_seg = tid & 3;
    const __half* a_src = A + (size_t)(rowBase + a_row)*K + (a_seg << 3);
    const uint32_t a_off = (uint32_t)a_row*80u + (uint32_t)a_seg*16u;

    auto issue_B = [&](uint32_t st, int c){
        #pragma unroll
        for (int i = 0; i < 2; ++i){
            int idx = tid + (i << 9);
            int row = idx >> 2, seg = idx & 3;
            CPA16(st + APL + (uint32_t)row*80u + (uint32_t)seg*16u,
                  Bh + (size_t)row*K + (c << 5) + (seg << 3));
        }
        CP_COMMIT();
    };

    float acc[64];
    #pragma unroll
    for (int i = 0; i < 64; ++i) acc[i] = 0.f;

    {
        uint4 v = *(const uint4*)a_src;
        issue_B(sb, 0);
        *(uint4*)(sm + a_off) = cvt_h8_bf8(v);
        CP_WAIT0();
    }
    __syncthreads();

    for (int c = 0; c < nch; ++c){
        const uint32_t st = sb + (c & 1)*STAGE_;
        const int nc = c + 1;
        uint4 v;
        if (nc < nch){
            v = *(const uint4*)(a_src + (nc << 5));
            issue_B(sb + (nc & 1)*STAGE_, nc);
        }

        #pragma unroll
        for (int ki = 0; ki < 2; ++ki){
            uint32_t ah[2][4];
            {
                int arow = wm*32 + (g & 1)*8 + r;
                uint32_t off = (uint32_t)(arow*PADK + ki*16 + (g >> 1)*8) * 2;
                ldsm4(st + off,             ah[0][0], ah[0][1], ah[0][2], ah[0][3]);
                ldsm4(st + off + 16*PADK*2, ah[1][0], ah[1][1], ah[1][2], ah[1][3]);
            }
            #pragma unroll
            for (int ng = 0; ng < 2; ++ng){
                uint32_t bhf[4][2];
                int nrow = wn*64 + ng*32 + (g >> 1)*8 + r;
                uint32_t off = (uint32_t)(nrow*PADK + ki*16 + (g & 1)*8) * 2;
                ldsm4(st + APL + off,             bhf[0][0], bhf[0][1], bhf[1][0], bhf[1][1]);
                ldsm4(st + APL + off + 16*PADK*2, bhf[2][0], bhf[2][1], bhf[3][0], bhf[3][1]);
                #pragma unroll
                for (int mi = 0; mi < 2; ++mi)
                    #pragma unroll
                    for (int j = 0; j < 4; ++j)
                        mma16816(acc + ((mi*8) + ng*4 + j)*4, ah[mi], bhf[j]);
            }
        }

        if (nc < nch){
            *(uint4*)(sm + (nc & 1)*STAGE_ + a_off) = cvt_h8_bf8(v);
            CP_WAIT0();
        }
        __syncthreads();
    }

    #pragma unroll
    for (int mi = 0; mi < 2; ++mi)
        #pragma unroll
        for (int ni = 0; ni < 8; ++ni){
            const float* a = acc + (mi*8 + ni)*4;
            int gcol = wn*64 + ni*8 + tr*2;
            int r0 = rowBase + wm*32 + mi*16 + tq;
            *(__half2*)&Cout[(size_t)r0*HD + gcol]     = __floats2half2_rn(a[0], a[1]);
            *(__half2*)&Cout[(size_t)(r0+8)*HD + gcol] = __floats2half2_rn(a[2], a[3]);
        }
}

// ================= fused invariants: fz16, fh16(+h16), rx16 ==============
__global__ __launch_bounds__(512, 1)
void inv3_gemm(const float* __restrict__ A,
               const __nv_bfloat16* __restrict__ Wzh, const __nv_bfloat16* __restrict__ Wzl,
               const __nv_bfloat16* __restrict__ Whh, const __nv_bfloat16* __restrict__ Whl,
               const __nv_bfloat16* __restrict__ Wrh, const __nv_bfloat16* __restrict__ Wrl,
               const float* __restrict__ b_z, const float* __restrict__ b_h,
               const float* __restrict__ b_ur,
               __half* __restrict__ fz, __half* __restrict__ fh,
               __half* __restrict__ h16, __half* __restrict__ rx)
{
    constexpr int K = IND;
    constexpr uint32_t B_OFF = 81920u;
    constexpr uint32_t BPL = 20480u, BSTG = 40960u;
    extern __shared__ char sm[];
    const int tid = threadIdx.x;
    const int rowBase = (int)blockIdx.x << 7;
    const int lane = tid & 31, wid = tid >> 5;
    const int wm = wid >> 2, wn = wid & 3;
    const int g = lane >> 3, r = lane & 7;
    const int tq = lane >> 2, tr = lane & 3;
    const uint32_t sb = smem_addr(sm);

    #pragma unroll
    for (int u = 0; u < 4; ++u){
        int idx = tid + (u << 9);
        int row = idx >> 4, gi = idx & 15;
        int t = gi >> 2, seg = gi & 3;
        const float* p = A + (size_t)(rowBase + row)*K + (gi << 3);
        float4 v0 = *(const float4*)p, v1 = *(const float4*)(p + 4);
        uint4 hi, lo; cvt_split8(v0, v1, hi, lo);
        uint32_t off = (uint32_t)t*20480u + (uint32_t)row*80u + (uint32_t)seg*16u;
        *(uint4*)(sm + off)          = hi;
        *(uint4*)(sm + off + 10240u) = lo;
    }
    __syncthreads();

    const __nv_bfloat16* Bhs[3] = {Wzh, Whh, Wrh};
    const __nv_bfloat16* Bls[3] = {Wzl, Whl, Wrl};
    const float* biases[3] = {b_z, b_h, b_ur};

    #pragma unroll
    for (int op = 0; op < 3; ++op){
        const __nv_bfloat16* Bh = Bhs[op];
        const __nv_bfloat16* Bl = Bls[op];

        auto issue_B = [&](uint32_t st, int c){
            #pragma unroll
            for (int i = 0; i < 4; ++i){
                int idx = tid + (i << 9);
                int plane = idx >> 10;
                int rem = idx & 1023;
                int row = rem >> 2, seg = rem & 3;
                const __nv_bfloat16* src = (plane ? Bl : Bh)
                    + (size_t)row*K + (c << 5) + (seg << 3);
                CPA16(st + (uint32_t)plane*BPL + (uint32_t)row*80u + (uint32_t)seg*16u, src);
            }
            CP_COMMIT();
        };

        float acc[64];
        #pragma unroll
        for (int i = 0; i < 64; ++i) acc[i] = 0.f;

        issue_B(sb + B_OFF, 0);
        CP_WAIT0();
        __syncthreads();

        for (int c = 0; c < 4; ++c){
            const uint32_t aBase = sb + (uint32_t)c*20480u;
            const uint32_t bBase = sb + B_OFF + (uint32_t)(c & 1)*BSTG;
            if (c + 1 < 4) issue_B(sb + B_OFF + (uint32_t)((c+1) & 1)*BSTG, c+1);

            #pragma unroll
            for (int ki = 0; ki < 2; ++ki){
                uint32_t ah[2][4], al[2][4];
                {
                    int arow = wm*32 + (g & 1)*8 + r;
                    uint32_t off = (uint32_t)(arow*PADK + ki*16 + (g >> 1)*8) * 2;
                    ldsm4(aBase + off,                  ah[0][0], ah[0][1], ah[0][2], ah[0][3]);
                    ldsm4(aBase + off + 16*PADK*2,      ah[1][0], ah[1][1], ah[1][2], ah[1][3]);
                    ldsm4(aBase + 10240u + off,             al[0][0], al[0][1], al[0][2], al[0][3]);
                    ldsm4(aBase + 10240u + off + 16*PADK*2, al[1][0], al[1][1], al[1][2], al[1][3]);
                }
                #pragma unroll
                for (int ng = 0; ng < 2; ++ng){
                    uint32_t bhf[4][2], blf[4][2];
                    int nrow = wn*64 + ng*32 + (g >> 1)*8 + r;
                    uint32_t off = (uint32_t)(nrow*PADK + ki*16 + (g & 1)*8) * 2;
                    ldsm4(bBase + off,                 bhf[0][0], bhf[0][1], bhf[1][0], bhf[1][1]);
                    ldsm4(bBase + off + 16*PADK*2,     bhf[2][0], bhf[2][1], bhf[3][0], bhf[3][1]);
                    ldsm4(bBase + BPL + off,             blf[0][0], blf[0][1], blf[1][0], blf[1][1]);
                    ldsm4(bBase + BPL + off + 16*PADK*2, blf[2][0], blf[2][1], blf[3][0], blf[3][1]);
                    #pragma unroll
                    for (int mi = 0; mi < 2; ++mi)
                        #pragma unroll
                        for (int j = 0; j < 4; ++j){
                            float* a = acc + ((mi*8) + ng*4 + j)*4;
                            mma16816(a, ah[mi], bhf[j]);
                            mma16816(a, ah[mi], blf[j]);
                            mma16816(a, al[mi], bhf[j]);
                        }
                }
            }
            if (c + 1 < 4) CP_WAIT0();
            __syncthreads();
        }

        #pragma unroll
        for (int mi = 0; mi < 2; ++mi)
            #pragma unroll
            for (int ni = 0; ni < 8; ++ni){
                const float* a = acc + (mi*8 + ni)*4;
                int gcol = wn*64 + ni*8 + tr*2;
                int r0 = rowBase + wm*32 + mi*16 + tq;
                float2 b = *(const float2*)&biases[op][gcol];
                size_t o0 = (size_t)r0*HD + gcol;
                size_t o1 = (size_t)(r0+8)*HD + gcol;
                float2 u0 = make_float2(a[0]+b.x, a[1]+b.y);
                float2 u1 = make_float2(a[2]+b.x, a[3]+b.y);
                if (op == 0) {
                    *(__half2*)&fz[o0] = __floats2half2_rn(u0.x, u0.y);
                    *(__half2*)&fz[o1] = __floats2half2_rn(u1.x, u1.y);
                } else if (op == 1) {
                    *(__half2*)&fh[o0] = __floats2half2_rn(u0.x, u0.y);
                    *(__half2*)&fh[o1] = __floats2half2_rn(u1.x, u1.y);
                    float2 z0 = __half22float2(*(const __half2*)&fz[o0]);
                    float2 z1 = __half22float2(*(const __half2*)&fz[o1]);
                    float2 w0 = make_float2(sigm(z0.x)*tanhf(u0.x), sigm(z0.y)*tanhf(u0.y));
                    float2 w1 = make_float2(sigm(z1.x)*tanhf(u1.x), sigm(z1.y)*tanhf(u1.y));
                    if (r0 == 0) w0 = make_float2(0.f, 0.f);   // null message row
                    *(__half2*)&h16[o0] = __floats2half2_rn(w0.x, w0.y);
                    *(__half2*)&h16[o1] = __floats2half2_rn(w1.x, w1.y);
                } else {
                    *(__half2*)&rx[o0] = __floats2half2_rn(u0.x, u0.y);
                    *(__half2*)&rx[o1] = __floats2half2_rn(u1.x, u1.y);
                }
            }
    }
}

// ================= fp16 single-pass GRU-step dual GEMM ====================
// wr32 != 0: write fp32 C only (final step). wr32 == 0: write fp16 C16 only.
__global__ __launch_bounds__(512, 1)
void mode1f(const __half* __restrict__ A1, const __half* __restrict__ B1,
            const __half* __restrict__ A2, const __half* __restrict__ B2,
            const __half* __restrict__ fz, const __half* __restrict__ fh,
            float* __restrict__ C, __half* __restrict__ C16, int wr32)
{
    constexpr int K = HD;                          // 256, 8 chunks
    constexpr uint32_t APL = 5120u, ABYTES = 10240u;
    constexpr uint32_t BPL = 20480u, STG = 51200u;
    extern __shared__ char sm[];
    const int tid = threadIdx.x;
    const int rowBase = (int)blockIdx.x << 6;      // MT=64
    const int lane = tid & 31, wid = tid >> 5;
    const int wm = wid >> 3, wn = wid & 7;         // 2 x 8 warps
    const int g = lane >> 3, r = lane & 7;
    const int tq = lane >> 2, tr = lane & 3;
    const uint32_t sb = smem_addr(sm);

    const int a_op = tid >> 8, a_rem = tid & 255;
    const int a_row = a_rem >> 2, a_seg = a_rem & 3;
    const __half* a_src = ((a_op == 0) ? A1 : A2)
        + (size_t)(rowBase + a_row)*K + (a_seg << 3);
    const uint32_t a_dst = (uint32_t)a_op*APL + (uint32_t)a_row*80u + (uint32_t)a_seg*16u;

    auto issue = [&](uint32_t st, int c){
        CPA16(st + a_dst, a_src + (c << 5));
        #pragma unroll
        for (int i = 0; i < 4; ++i){
            int idx = tid + (i << 9);
            int op = idx >> 10;
            int rem = idx & 1023;
            int row = rem >> 2, seg = rem & 3;
            const __half* src = ((op == 0) ? B1 : B2)
                + (size_t)row*K + (c << 5) + (seg << 3);
            CPA16(st + ABYTES + (uint32_t)op*BPL + (uint32_t)row*80u + (uint32_t)seg*16u, src);
        }
        CP_COMMIT();
    };

    float acc[64];
    #pragma unroll
    for (int i = 0; i < 64; ++i) acc[i] = 0.f;

    issue(sb, 0);
    issue(sb + STG, 1);

    for (int c = 0; c < 8; ++c){
        if (c + 1 < 8) { CP_WAIT1(); } else { CP_WAIT0(); }
        __syncthreads();
        if (c + 2 < 8) issue(sb + ((c+2)%3)*STG, c+2);
        const uint32_t st = sb + (c%3)*STG;

        #pragma unroll
        for (int op = 0; op < 2; ++op){
            const uint32_t aBase = st + (uint32_t)op*APL;
            const uint32_t bBase = st + ABYTES + (uint32_t)op*BPL;
            #pragma unroll
            for (int ki = 0; ki < 2; ++ki){
                uint32_t ah[2][4];
                {
                    int arow = wm*32 + (g & 1)*8 + r;
                    uint32_t off = (uint32_t)(arow*PADK + ki*16 + (g >> 1)*8) * 2;
                    ldsm4(aBase + off,             ah[0][0], ah[0][1], ah[0][2], ah[0][3]);
                    ldsm4(aBase + off + 16*PADK*2, ah[1][0], ah[1][1], ah[1][2], ah[1][3]);
                }
                uint32_t bf[4][2];
                {
                    int nrow = wn*32 + (g >> 1)*8 + r;
                    uint32_t off = (uint32_t)(nrow*PADK + ki*16 + (g & 1)*8) * 2;
                    ldsm4(bBase + off,             bf[0][0], bf[0][1], bf[1][0], bf[1][1]);
                    ldsm4(bBase + off + 16*PADK*2, bf[2][0], bf[2][1], bf[3][0], bf[3][1]);
                }
                #pragma unroll
                for (int mi = 0; mi < 2; ++mi)
                    #pragma unroll
                    for (int j = 0; j < 4; ++j)
                        mma16816h(acc + ((op*2 + mi)*4 + j)*4, ah[mi], bf[j]);
            }
        }
    }

    #pragma unroll
    for (int mi = 0; mi < 2; ++mi)
        #pragma unroll
        for (int ni = 0; ni < 4; ++ni){
            const float* a1 = acc + ((0*2 + mi)*4 + ni)*4;
            const float* a2 = acc + ((1*2 + mi)*4 + ni)*4;
            int gcol = wn*32 + ni*8 + tr*2;
            int r0 = rowBase + wm*32 + mi*16 + tq;
            size_t o0 = (size_t)r0*HD + gcol;
            size_t o1 = (size_t)(r0+8)*HD + gcol;
            float2 za = __half22float2(*(const __half2*)&fz[o0]);
            float2 zb = __half22float2(*(const __half2*)&fz[o1]);
            float2 ha = __half22float2(*(const __half2*)&fh[o0]);
            float2 hb = __half22float2(*(const __half2*)&fh[o1]);
            float2 sa = __half22float2(*(const __half2*)&A1[o0]);
            float2 sb2 = __half22float2(*(const __half2*)&A1[o1]);
            float z0 = sigm(za.x + a1[0]);
            float z1 = sigm(za.y + a1[1]);
            float z2 = sigm(zb.x + a1[2]);
            float z3 = sigm(zb.y + a1[3]);
            float p0 = tanhf(ha.x + a2[0]);
            float p1 = tanhf(ha.y + a2[1]);
            float p2 = tanhf(hb.x + a2[2]);
            float p3 = tanhf(hb.y + a2[3]);
            float2 u0 = make_float2((1.f - z0)*sa.x + z0*p0, (1.f - z1)*sa.y + z1*p1);
            float2 u1 = make_float2((1.f - z2)*sb2.x + z2*p2, (1.f - z3)*sb2.y + z3*p3);
            if (r0 == 0) u0 = make_float2(0.f, 0.f);
            if (wr32) {
                *(float2*)&C[o0] = u0;
                *(float2*)&C[o1] = u1;
            } else {
                *(__half2*)&C16[o0] = __floats2half2_rn(u0.x, u0.y);
                *(__half2*)&C16[o1] = __floats2half2_rn(u1.x, u1.y);
            }
        }
}

// ================= MODE2 (output layer, bf16 3-pass) ======================
__global__ __launch_bounds__(512, 1)
void mode2_gemm(const float* __restrict__ A1, int K1,
                const __nv_bfloat16* __restrict__ B1h, const __nv_bfloat16* __restrict__ B1l,
                const float* __restrict__ A2, int K2,
                const __nv_bfloat16* __restrict__ B2h, const __nv_bfloat16* __restrict__ B2l,
                int M, const float* __restrict__ bias, const float* __restrict__ maskv,
                float* __restrict__ C)
{
    extern __shared__ char sm[];
    const int tid = threadIdx.x;
    const int rowBase = (int)blockIdx.x << 7;
    const int lane = tid & 31, wid = tid >> 5;
    const int wm = wid >> 2, wn = wid & 3;
    const int tq = lane >> 2, tr = lane & 3;

    float acc[64];
    #pragma unroll
    for (int i = 0; i < 64; ++i) acc[i] = 0.f;

    run_phase<128,1>(A1, nullptr, K1, B1h, B1l, nullptr, nullptr, acc, sm, tid, rowBase, M);
    run_phase<128,1>(A2, nullptr, K2, B2h, B2l, nullptr, nullptr, acc, sm, tid, rowBase, M);

    #pragma unroll
    for (int mi = 0; mi < 2; ++mi)
        #pragma unroll
        for (int ni = 0; ni < 8; ++ni) {
            const float* a = acc + (mi*8 + ni)*4;
            int gcol = wn*64 + ni*8 + tr*2;
            int r0 = rowBase + wm*32 + mi*16 + tq;
            float2 b = *(const float2*)&bias[gcol];
            if (r0 < M) {
                float m = maskv[r0];
                *(float2*)&C[(size_t)r0*HD + gcol] =
                    make_float2(fmaxf(a[0]+b.x, 0.f)*m, fmaxf(a[1]+b.y, 0.f)*m);
            }
            if (r0 + 8 < M) {
                float m = maskv[r0+8];
                *(float2*)&C[(size_t)(r0+8)*HD + gcol] =
                    make_float2(fmaxf(a[2]+b.x, 0.f)*m, fmaxf(a[3]+b.y, 0.f)*m);
            }
        }
}

// ===== one-shot weight prep: all bf16 splits + fp16 transposes ============
__global__ void prep_all(const float* __restrict__ W_z, const float* __restrict__ W_h,
                         const float* __restrict__ W_r, const float* __restrict__ U_r,
                         const float* __restrict__ W_o,
                         __nv_bfloat16* __restrict__ bh, __nv_bfloat16* __restrict__ bl,
                         __half* __restrict__ wz16, __half* __restrict__ wh16)
{
    int b = blockIdx.x, t = threadIdx.x;
    if (b < 512) {
        // bf16 split, K=128: WZT, WHT, WR, WOT
        int job = b >> 7;
        int i = ((b & 127) << 8) + t;
        const float* W = (job == 0) ? W_z : (job == 1) ? W_h : (job == 2) ? W_r : W_o;
        int off = (job == 0) ? OFF_WZT : (job == 1) ? OFF_WHT : (job == 2) ? OFF_WR : OFF_WOT;
        int k = i & 127, n = i >> 7;
        float x = W[(size_t)k*HD + n];
        __nv_bfloat16 h = __float2bfloat16_rn(x);
        bh[off + i] = h;
        bl[off + i] = __float2bfloat16_rn(x - __bfloat162float(h));
    } else if (b < 1024) {
        // bf16 split, K=256: UR, WOB
        int job = (b - 512) >> 8;
        int i = (((b - 512) & 255) << 8) + t;
        const float* W = (job == 0) ? U_r : (W_o + (size_t)IND*HD);
        int off = (job == 0) ? OFF_UR : OFF_WOB;
        int k = i & 255, n = i >> 8;
        float x = W[(size_t)k*HD + n];
        __nv_bfloat16 h = __float2bfloat16_rn(x);
        bh[off + i] = h;
        bl[off + i] = __float2bfloat16_rn(x - __bfloat162float(h));
    } else {
        // fp16 transpose, K=256: wz16, wh16 (bottom halves of W_z, W_h)
        int job = (b - 1024) >> 8;
        int i = (((b - 1024) & 255) << 8) + t;
        const float* W = ((job == 0) ? W_z : W_h) + (size_t)IND*HD;
        __half* o = (job == 0) ? wz16 : wh16;
        int k = i & 255, n = i >> 8;
        o[i] = __float2half_rn(W[(size_t)k*HD + n]);
    }
}

__global__ void gather_msgs(const __half* __restrict__ h16, const __half* __restrict__ hU,
                            const __half* __restrict__ rx, const int* __restrict__ bg,
                            __half* __restrict__ sumh, __half* __restrict__ sumg)
{
    __shared__ int s_nb[4][NBR];
    int e = blockIdx.x * 4 + threadIdx.y;
    if (threadIdx.x < NBR) s_nb[threadIdx.y][threadIdx.x] = bg[e*NBR + threadIdx.x];
    __syncthreads();
    int c = threadIdx.x << 2;
    size_t base = (size_t)e*HD + c;
    uint2 rx4 = *(const uint2*)(rx + base);
    float2 r01 = __half22float2(*reinterpret_cast<__half2*>(&rx4.x));
    float2 r23 = __half22float2(*reinterpret_cast<__half2*>(&rx4.y));
    float4 sh = make_float4(0.f,0.f,0.f,0.f);
    float4 sg = make_float4(0.f,0.f,0.f,0.f);
    #pragma unroll
    for (int j = 0; j < NBR; ++j) {
        size_t nb = (size_t)s_nb[threadIdx.y][j]*HD + c;
        uint2 hq = *(const uint2*)(h16 + nb);
        float2 h01 = __half22float2(*reinterpret_cast<__half2*>(&hq.x));
        float2 h23 = __half22float2(*reinterpret_cast<__half2*>(&hq.y));
        uint2 hu4 = *(const uint2*)(hU + nb);
        float2 u01 = __half22float2(*reinterpret_cast<__half2*>(&hu4.x));
        float2 u23 = __half22float2(*reinterpret_cast<__half2*>(&hu4.y));
        sh.x += h01.x; sh.y += h01.y; sh.z += h23.x; sh.w += h23.y;
        sg.x += sigm(r01.x + u01.x) * h01.x;
        sg.y += sigm(r01.y + u01.y) * h01.y;
        sg.z += sigm(r23.x + u23.x) * h23.x;
        sg.w += sigm(r23.y + u23.y) * h23.y;
    }
    __half2 sh01 = __floats2half2_rn(sh.x, sh.y), sh23 = __floats2half2_rn(sh.z, sh.w);
    __half2 sg01 = __floats2half2_rn(sg.x, sg.y), sg23 = __floats2half2_rn(sg.z, sg.w);
    *(uint2*)(sumh + base) = make_uint2(h2u(sh01), h2u(sh23));
    *(uint2*)(sumg + base) = make_uint2(h2u(sg01), h2u(sg23));
}

__global__ void gather_nodes(const float* __restrict__ h, const int* __restrict__ ag,
                             float* __restrict__ nei)
{
    __shared__ int s_nb[4][NBR];
    int v = blockIdx.x * 4 + threadIdx.y;
    if (threadIdx.x < NBR) s_nb[threadIdx.y][threadIdx.x] = ag[v*NBR + threadIdx.x];
    __syncthreads();
    int c = threadIdx.x << 2;
    float4 s = make_float4(0.f,0.f,0.f,0.f);
    #pragma unroll
    for (int j = 0; j < NBR; ++j) {
        size_t nb = (size_t)s_nb[threadIdx.y][j]*HD + c;
        float4 hv = *(const float4*)&h[nb];
        s.x += hv.x; s.y += hv.y; s.z += hv.z; s.w += hv.w;
    }
    *(float4*)&nei[(size_t)v*HD + c] = s;
}

extern "C" void kernel_launch(void* const* d_in, const int* in_sizes, int n_in,
                              void* d_out, int out_size)
{
    const float* fnode  = (const float*)d_in[0];
    const float* fmess  = (const float*)d_in[1];
    const int*   agraph = (const int*)  d_in[2];
    const int*   bgraph = (const int*)  d_in[3];
    const float* mask   = (const float*)d_in[4];
    const float* W_z    = (const float*)d_in[5];
    const float* b_z    = (const float*)d_in[6];
    const float* W_r    = (const float*)d_in[7];
    const float* U_r    = (const float*)d_in[8];
    const float* b_ur   = (const float*)d_in[9];
    const float* W_h    = (const float*)d_in[10];
    const float* b_h    = (const float*)d_in[11];
    const float* W_o    = (const float*)d_in[12];
    const float* b_o    = (const float*)d_in[13];

    float* out_node = (float*)d_out;
    float* out_h    = out_node + (size_t)NN*HD;

    float *nei;
    __half *h16, *fz16, *fh16, *sumh16, *sumg16, *hU16, *rx16, *wz16, *wh16;
    __nv_bfloat16 *bh, *bl;
    cudaGetSymbolAddress((void**)&nei,    g_nei);
    cudaGetSymbolAddress((void**)&h16,    g_h16);
    cudaGetSymbolAddress((void**)&fz16,   g_fz16);
    cudaGetSymbolAddress((void**)&fh16,   g_fh16);
    cudaGetSymbolAddress((void**)&sumh16, g_sumh16);
    cudaGetSymbolAddress((void**)&sumg16, g_sumg16);
    cudaGetSymbolAddress((void**)&hU16,   g_hU16);
    cudaGetSymbolAddress((void**)&rx16,   g_rx16);
    cudaGetSymbolAddress((void**)&wz16,   g_wz16);
    cudaGetSymbolAddress((void**)&wh16,   g_wh16);
    cudaGetSymbolAddress((void**)&bh,     g_bh);
    cudaGetSymbolAddress((void**)&bl,     g_bl);

    cudaFuncSetAttribute((const void*)inv3_gemm,
                         cudaFuncAttributeMaxDynamicSharedMemorySize, SMEM_I3);
    cudaFuncSetAttribute((const void*)hU_gemm,
                         cudaFuncAttributeMaxDynamicSharedMemorySize, SMEM_HU);
    cudaFuncSetAttribute((const void*)mode1f,
                         cudaFuncAttributeMaxDynamicSharedMemorySize, SMEM_M1F);
    cudaFuncSetAttribute((const void*)mode2_gemm,
                         cudaFuncAttributeMaxDynamicSharedMemorySize, SMEM_M0);

    const int gE128 = NM / 128;               // 625
    const int gE64  = NM / 64;                // 1250
    const int gV    = NNP / 128;              // 274

    // launch 1: all weight preps in one kernel
    prep_all<<<1536, 256>>>(W_z, W_h, W_r, U_r, W_o, bh, bl, wz16, wh16);

    // launch 2: fused invariants (fz16, fh16, h16 step-1, rx16)
    inv3_gemm<<<gE128, 512, SMEM_I3>>>(fmess,
        bh+OFF_WZT, bl+OFF_WZT, bh+OFF_WHT, bl+OFF_WHT, bh+OFF_WR, bl+OFF_WR,
        b_z, b_h, b_ur, fz16, fh16, h16, rx16);

    // launches 3..14: 4 GRU steps (launch 6 = step-2 hU_gemm is profiled)
    for (int d = 1; d < DEPTH; ++d) {
        hU_gemm<<<gE128, 512, SMEM_HU>>>(h16, bh+OFF_UR, hU16);
        gather_msgs<<<NM/4, dim3(64,4)>>>(h16, hU16, rx16, bgraph, sumh16, sumg16);
        mode1f<<<gE64, 512, SMEM_M1F>>>(sumh16, wz16, sumg16, wh16,
                                        fz16, fh16, out_h, h16, (d == DEPTH-1) ? 1 : 0);
    }

    gather_nodes<<<NN/4, dim3(64,4)>>>(out_h, agraph, nei);
    mode2_gemm<<<gV, 512, SMEM_M0>>>(fnode, IND, bh+OFF_WOT, bl+OFF_WOT,
                                     nei, HD, bh+OFF_WOB, bl+OFF_WOB,
                                     NN, b_o, mask, out_node);
}

// round 15
// speedup vs baseline: 1.7077x; 1.2134x over previous
#include <cuda_runtime.h>
#include <cuda_bf16.h>
#include <cuda_fp16.h>
#include <math.h>
#include <cstdint>

#define NN 35000
#define NM 80000
#define NBR 6
#define IND 128
#define HD 256
#define DEPTH 5
#define NNP 35072

// ---------------- scratch (__device__ globals; no allocs) ----------------
__device__ float g_nei [(size_t)NNP*HD];
__device__ __align__(16) __half g_h16  [(size_t)NM*HD];   // fp16 h (steps 1..4)
__device__ __align__(16) __half g_fz16 [(size_t)NM*HD];
__device__ __align__(16) __half g_fh16 [(size_t)NM*HD];
__device__ __align__(16) __half g_sumh16[(size_t)NM*HD];
__device__ __align__(16) __half g_sumg16[(size_t)NM*HD];
__device__ __align__(16) __half g_hU16[(size_t)NM*HD];
__device__ __align__(16) __half g_rx16[(size_t)NM*HD];
__device__ __align__(16) __half g_wz16[65536];
__device__ __align__(16) __half g_wh16[65536];

#define OFF_WZT 0
#define OFF_WHT 32768
#define OFF_WR  65536
#define OFF_WOT 98304
#define OFF_UR  131072
#define OFF_WOB 196608
__device__ __align__(16) __nv_bfloat16 g_bh[262144];
__device__ __align__(16) __nv_bfloat16 g_bl[262144];

// fast sigmoid: 2 MUFU + ~3 ALU (vs ~35 issue slots for precise expf+div).
// rel error ~1e-6, negligible against fp16 storage rounding in the gate path.
__device__ __forceinline__ float sigm(float x){
    return __fdividef(1.0f, 1.0f + __expf(-x));
}

// ---------------- mma / ldmatrix / cp.async helpers ----------------------
__device__ __forceinline__ uint32_t smem_addr(const void* p){
    return (uint32_t)__cvta_generic_to_shared(p);
}
__device__ __forceinline__ void ldsm4(uint32_t a, uint32_t& r0, uint32_t& r1,
                                      uint32_t& r2, uint32_t& r3){
    asm volatile("ldmatrix.sync.aligned.m8n8.x4.shared.b16 {%0,%1,%2,%3}, [%4];"
                 : "=r"(r0), "=r"(r1), "=r"(r2), "=r"(r3) : "r"(a));
}
__device__ __forceinline__ void mma16816(float* c, const uint32_t* a, const uint32_t* b){
    asm volatile(
        "mma.sync.aligned.m16n8k16.row.col.f32.bf16.bf16.f32 "
        "{%0,%1,%2,%3}, {%4,%5,%6,%7}, {%8,%9}, {%0,%1,%2,%3};"
        : "+f"(c[0]), "+f"(c[1]), "+f"(c[2]), "+f"(c[3])
        : "r"(a[0]), "r"(a[1]), "r"(a[2]), "r"(a[3]), "r"(b[0]), "r"(b[1]));
}
__device__ __forceinline__ void mma16816h(float* c, const uint32_t* a, const uint32_t* b){
    asm volatile(
        "mma.sync.aligned.m16n8k16.row.col.f32.f16.f16.f32 "
        "{%0,%1,%2,%3}, {%4,%5,%6,%7}, {%8,%9}, {%0,%1,%2,%3};"
        : "+f"(c[0]), "+f"(c[1]), "+f"(c[2]), "+f"(c[3])
        : "r"(a[0]), "r"(a[1]), "r"(a[2]), "r"(a[3]), "r"(b[0]), "r"(b[1]));
}
#define CPA16(dst, src) \
    asm volatile("cp.async.cg.shared.global [%0], [%1], 16;" :: "r"(dst), "l"(src))
#define CP_COMMIT() asm volatile("cp.async.commit_group;" ::: "memory")
#define CP_WAIT0()  asm volatile("cp.async.wait_group 0;" ::: "memory")
#define CP_WAIT1()  asm volatile("cp.async.wait_group 1;" ::: "memory")

__device__ __forceinline__ void cvt_split8(float4 v0, float4 v1, uint4& hi, uint4& lo){
    float f[8] = {v0.x,v0.y,v0.z,v0.w,v1.x,v1.y,v1.z,v1.w};
    uint32_t hh[8], ll[8];
    #pragma unroll
    for (int j = 0; j < 8; ++j) {
        __nv_bfloat16 h = __float2bfloat16_rn(f[j]);
        float hf = __bfloat162float(h);
        __nv_bfloat16 l = __float2bfloat16_rn(f[j] - hf);
        hh[j] = (uint32_t)__bfloat16_as_ushort(h);
        ll[j] = (uint32_t)__bfloat16_as_ushort(l);
    }
    hi = make_uint4(hh[0]|(hh[1]<<16), hh[2]|(hh[3]<<16), hh[4]|(hh[5]<<16), hh[6]|(hh[7]<<16));
    lo = make_uint4(ll[0]|(ll[1]<<16), ll[2]|(ll[3]<<16), ll[4]|(ll[5]<<16), ll[6]|(ll[7]<<16));
}
// 8 fp16 -> 8 bf16 (hi only)
__device__ __forceinline__ uint4 cvt_h8_bf8(uint4 v){
    const __half* hp = (const __half*)&v;
    uint32_t hh[8];
    #pragma unroll
    for (int j = 0; j < 8; ++j)
        hh[j] = (uint32_t)__bfloat16_as_ushort(__float2bfloat16_rn(__half2float(hp[j])));
    return make_uint4(hh[0]|(hh[1]<<16), hh[2]|(hh[3]<<16), hh[4]|(hh[5]<<16), hh[6]|(hh[7]<<16));
}
__device__ __forceinline__ uint32_t h2u(__half2 v){ return *(uint32_t*)&v; }

#define PADK 40

// ================= 3-pass bf16 phase (mode2 only) =========================
template<int MT, int NA>
__device__ __forceinline__ void run_phase(
    const float* __restrict__ A1, const float* __restrict__ A2, int K,
    const __nv_bfloat16* __restrict__ B1h, const __nv_bfloat16* __restrict__ B1l,
    const __nv_bfloat16* __restrict__ B2h, const __nv_bfloat16* __restrict__ B2l,
    float* acc, char* sm, int tid, int rowBase, int M)
{
    constexpr int WM = MT/32;
    constexpr int WN = 16/WM;
    constexpr int NSPAN = 256/WN;
    constexpr int NFR = NSPAN/8;
    constexpr uint32_t APL = MT*80u;
    constexpr uint32_t A_BYTES = NA*2u*APL;
    constexpr uint32_t BPL = 20480u;
    constexpr uint32_t STAGE_ = A_BYTES + NA*2u*BPL;
    constexpr int NB = NA*4;
    const int lane = tid & 31, wid = tid >> 5;
    const int wm = wid / WN, wn = wid % WN;
    const int g = lane >> 3, r = lane & 7;
    const uint32_t sb = smem_addr(sm);
    const int nch = K >> 5;

    const int a_op  = tid / (MT*4);
    const int a_rem = tid % (MT*4);
    const int a_row = a_rem >> 2, a_seg = a_rem & 3;
    const int grow = rowBase + a_row;
    const bool a_ok = (grow < M);
    const float* a_src = ((a_op == 0) ? A1 : A2) + (size_t)grow*K + (a_seg << 3);
    const uint32_t a_off = (uint32_t)a_op*2u*APL + (uint32_t)a_row*80u + (uint32_t)a_seg*16u;

    auto issue_B = [&](uint32_t st, int c){
        #pragma unroll
        for (int i = 0; i < NB; ++i){
            int idx = tid + (i << 9);
            int op = idx >> 11;
            int rem = idx & 2047;
            int plane = rem >> 10;
            int rem2 = rem & 1023;
            int row = rem2 >> 2, seg = rem2 & 3;
            const __nv_bfloat16* Bp = (op == 0) ? (plane ? B1l : B1h)
                                                : (plane ? B2l : B2h);
            const __nv_bfloat16* src = Bp + (size_t)row*K + (c << 5) + (seg << 3);
            uint32_t dst = st + A_BYTES + (uint32_t)op*(2u*BPL) + (uint32_t)plane*BPL
                         + (uint32_t)row*80u + (uint32_t)seg*16u;
            CPA16(dst, src);
        }
        CP_COMMIT();
    };

    {
        float4 v0 = make_float4(0.f,0.f,0.f,0.f), v1 = v0;
        if (a_ok){ v0 = *(const float4*)a_src; v1 = *(const float4*)(a_src + 4); }
        issue_B(sb, 0);
        uint4 hi, lo; cvt_split8(v0, v1, hi, lo);
        *(uint4*)(sm + a_off)       = hi;
        *(uint4*)(sm + a_off + APL) = lo;
        CP_WAIT0();
    }
    __syncthreads();

    for (int c = 0; c < nch; ++c){
        const uint32_t st = sb + (c & 1)*STAGE_;
        const int nc = c + 1;
        float4 v0, v1;
        if (nc < nch){
            v0 = make_float4(0.f,0.f,0.f,0.f); v1 = v0;
            if (a_ok){
                const float* p = a_src + (nc << 5);
                v0 = *(const float4*)p; v1 = *(const float4*)(p + 4);
            }
            issue_B(sb + (nc & 1)*STAGE_, nc);
        }

        #pragma unroll
        for (int op = 0; op < NA; ++op){
            const uint32_t aBase = st + (uint32_t)op*2u*APL;
            const uint32_t bBase = st + A_BYTES + (uint32_t)op*(2u*BPL);
            #pragma unroll
            for (int ki = 0; ki < 2; ++ki){
                uint32_t ah[2][4], al[2][4];
                {
                    int arow = wm*32 + (g & 1)*8 + r;
                    uint32_t off = (uint32_t)(arow*PADK + ki*16 + (g >> 1)*8) * 2;
                    ldsm4(aBase + off,                   ah[0][0], ah[0][1], ah[0][2], ah[0][3]);
                    ldsm4(aBase + off + 16*PADK*2,       ah[1][0], ah[1][1], ah[1][2], ah[1][3]);
                    ldsm4(aBase + APL + off,             al[0][0], al[0][1], al[0][2], al[0][3]);
                    ldsm4(aBase + APL + off + 16*PADK*2, al[1][0], al[1][1], al[1][2], al[1][3]);
                }
                #pragma unroll
                for (int ng = 0; ng < NFR/4; ++ng){
                    uint32_t bhf[4][2], blf[4][2];
                    int nrow = wn*NSPAN + ng*32 + (g >> 1)*8 + r;
                    uint32_t off = (uint32_t)(nrow*PADK + ki*16 + (g & 1)*8) * 2;
                    ldsm4(bBase + off,                 bhf[0][0], bhf[0][1], bhf[1][0], bhf[1][1]);
                    ldsm4(bBase + off + 16*PADK*2,     bhf[2][0], bhf[2][1], bhf[3][0], bhf[3][1]);
                    ldsm4(bBase + BPL + off,             blf[0][0], blf[0][1], blf[1][0], blf[1][1]);
                    ldsm4(bBase + BPL + off + 16*PADK*2, blf[2][0], blf[2][1], blf[3][0], blf[3][1]);
                    #pragma unroll
                    for (int mi = 0; mi < 2; ++mi)
                        #pragma unroll
                        for (int j = 0; j < 4; ++j){
                            float* a = acc + (((op*2 + mi)*NFR) + ng*4 + j)*4;
                            mma16816(a, ah[mi], bhf[j]);
                            mma16816(a, ah[mi], blf[j]);
                            mma16816(a, al[mi], bhf[j]);
                        }
                }
            }
        }

        if (nc < nch){
            char* nsm = sm + (nc & 1)*STAGE_;
            uint4 hi, lo; cvt_split8(v0, v1, hi, lo);
            *(uint4*)(nsm + a_off)       = hi;
            *(uint4*)(nsm + a_off + APL) = lo;
            CP_WAIT0();
        }
        __syncthreads();
    }
}

#define SMEM_M0  (2*(2*128*80 + 2*20480))   // 122880
#define SMEM_HU  (2*(128*80 + 20480))       // 61440
#define SMEM_I3  (4*20480 + 2*40960)        // 163840
#define SMEM_M1F (3*(2*64*80 + 2*20480))    // 153600

// ================= single-pass bf16 GEMM for hU (gate path) ==============
__global__ __launch_bounds__(512, 1)
void hU_gemm(const __half* __restrict__ A, const __nv_bfloat16* __restrict__ Bh,
             __half* __restrict__ Cout)
{
    constexpr int K = HD;
    constexpr uint32_t APL = 10240u, STAGE_ = 30720u;
    extern __shared__ char sm[];
    const int tid = threadIdx.x;
    const int rowBase = (int)blockIdx.x << 7;
    const int lane = tid & 31, wid = tid >> 5;
    const int wm = wid >> 2, wn = wid & 3;
    const int g = lane >> 3, r = lane & 7;
    const int tq = lane >> 2, tr = lane & 3;
    const uint32_t sb = smem_addr(sm);
    const int nch = K >> 5;

    const int a_row = tid >> 2, a_seg = tid & 3;
    const __half* a_src = A + (size_t)(rowBase + a_row)*K + (a_seg << 3);
    const uint32_t a_off = (uint32_t)a_row*80u + (uint32_t)a_seg*16u;

    auto issue_B = [&](uint32_t st, int c){
        #pragma unroll
        for (int i = 0; i < 2; ++i){
            int idx = tid + (i << 9);
            int row = idx >> 2, seg = idx & 3;
            CPA16(st + APL + (uint32_t)row*80u + (uint32_t)seg*16u,
                  Bh + (size_t)row*K + (c << 5) + (seg << 3));
        }
        CP_COMMIT();
    };

    float acc[64];
    #pragma unroll
    for (int i = 0; i < 64; ++i) acc[i] = 0.f;

    {
        uint4 v = *(const uint4*)a_src;
        issue_B(sb, 0);
        *(uint4*)(sm + a_off) = cvt_h8_bf8(v);
        CP_WAIT0();
    }
    __syncthreads();

    for (int c = 0; c < nch; ++c){
        const uint32_t st = sb + (c & 1)*STAGE_;
        const int nc = c + 1;
        uint4 v;
        if (nc < nch){
            v = *(const uint4*)(a_src + (nc << 5));
            issue_B(sb + (nc & 1)*STAGE_, nc);
        }

        #pragma unroll
        for (int ki = 0; ki < 2; ++ki){
            uint32_t ah[2][4];
            {
                int arow = wm*32 + (g & 1)*8 + r;
                uint32_t off = (uint32_t)(arow*PADK + ki*16 + (g >> 1)*8) * 2;
                ldsm4(st + off,             ah[0][0], ah[0][1], ah[0][2], ah[0][3]);
                ldsm4(st + off + 16*PADK*2, ah[1][0], ah[1][1], ah[1][2], ah[1][3]);
            }
            #pragma unroll
            for (int ng = 0; ng < 2; ++ng){
                uint32_t bhf[4][2];
                int nrow = wn*64 + ng*32 + (g >> 1)*8 + r;
                uint32_t off = (uint32_t)(nrow*PADK + ki*16 + (g & 1)*8) * 2;
                ldsm4(st + APL + off,             bhf[0][0], bhf[0][1], bhf[1][0], bhf[1][1]);
                ldsm4(st + APL + off + 16*PADK*2, bhf[2][0], bhf[2][1], bhf[3][0], bhf[3][1]);
                #pragma unroll
                for (int mi = 0; mi < 2; ++mi)
                    #pragma unroll
                    for (int j = 0; j < 4; ++j)
                        mma16816(acc + ((mi*8) + ng*4 + j)*4, ah[mi], bhf[j]);
            }
        }

        if (nc < nch){
            *(uint4*)(sm + (nc & 1)*STAGE_ + a_off) = cvt_h8_bf8(v);
            CP_WAIT0();
        }
        __syncthreads();
    }

    #pragma unroll
    for (int mi = 0; mi < 2; ++mi)
        #pragma unroll
        for (int ni = 0; ni < 8; ++ni){
            const float* a = acc + (mi*8 + ni)*4;
            int gcol = wn*64 + ni*8 + tr*2;
            int r0 = rowBase + wm*32 + mi*16 + tq;
            *(__half2*)&Cout[(size_t)r0*HD + gcol]     = __floats2half2_rn(a[0], a[1]);
            *(__half2*)&Cout[(size_t)(r0+8)*HD + gcol] = __floats2half2_rn(a[2], a[3]);
        }
}

// ================= fused invariants: fz16, fh16(+h16), rx16 ==============
__global__ __launch_bounds__(512, 1)
void inv3_gemm(const float* __restrict__ A,
               const __nv_bfloat16* __restrict__ Wzh, const __nv_bfloat16* __restrict__ Wzl,
               const __nv_bfloat16* __restrict__ Whh, const __nv_bfloat16* __restrict__ Whl,
               const __nv_bfloat16* __restrict__ Wrh, const __nv_bfloat16* __restrict__ Wrl,
               const float* __restrict__ b_z, const float* __restrict__ b_h,
               const float* __restrict__ b_ur,
               __half* __restrict__ fz, __half* __restrict__ fh,
               __half* __restrict__ h16, __half* __restrict__ rx)
{
    constexpr int K = IND;
    constexpr uint32_t B_OFF = 81920u;
    constexpr uint32_t BPL = 20480u, BSTG = 40960u;
    extern __shared__ char sm[];
    const int tid = threadIdx.x;
    const int rowBase = (int)blockIdx.x << 7;
    const int lane = tid & 31, wid = tid >> 5;
    const int wm = wid >> 2, wn = wid & 3;
    const int g = lane >> 3, r = lane & 7;
    const int tq = lane >> 2, tr = lane & 3;
    const uint32_t sb = smem_addr(sm);

    #pragma unroll
    for (int u = 0; u < 4; ++u){
        int idx = tid + (u << 9);
        int row = idx >> 4, gi = idx & 15;
        int t = gi >> 2, seg = gi & 3;
        const float* p = A + (size_t)(rowBase + row)*K + (gi << 3);
        float4 v0 = *(const float4*)p, v1 = *(const float4*)(p + 4);
        uint4 hi, lo; cvt_split8(v0, v1, hi, lo);
        uint32_t off = (uint32_t)t*20480u + (uint32_t)row*80u + (uint32_t)seg*16u;
        *(uint4*)(sm + off)          = hi;
        *(uint4*)(sm + off + 10240u) = lo;
    }
    __syncthreads();

    const __nv_bfloat16* Bhs[3] = {Wzh, Whh, Wrh};
    const __nv_bfloat16* Bls[3] = {Wzl, Whl, Wrl};
    const float* biases[3] = {b_z, b_h, b_ur};

    #pragma unroll
    for (int op = 0; op < 3; ++op){
        const __nv_bfloat16* Bh = Bhs[op];
        const __nv_bfloat16* Bl = Bls[op];

        auto issue_B = [&](uint32_t st, int c){
            #pragma unroll
            for (int i = 0; i < 4; ++i){
                int idx = tid + (i << 9);
                int plane = idx >> 10;
                int rem = idx & 1023;
                int row = rem >> 2, seg = rem & 3;
                const __nv_bfloat16* src = (plane ? Bl : Bh)
                    + (size_t)row*K + (c << 5) + (seg << 3);
                CPA16(st + (uint32_t)plane*BPL + (uint32_t)row*80u + (uint32_t)seg*16u, src);
            }
            CP_COMMIT();
        };

        float acc[64];
        #pragma unroll
        for (int i = 0; i < 64; ++i) acc[i] = 0.f;

        issue_B(sb + B_OFF, 0);
        CP_WAIT0();
        __syncthreads();

        for (int c = 0; c < 4; ++c){
            const uint32_t aBase = sb + (uint32_t)c*20480u;
            const uint32_t bBase = sb + B_OFF + (uint32_t)(c & 1)*BSTG;
            if (c + 1 < 4) issue_B(sb + B_OFF + (uint32_t)((c+1) & 1)*BSTG, c+1);

            #pragma unroll
            for (int ki = 0; ki < 2; ++ki){
                uint32_t ah[2][4], al[2][4];
                {
                    int arow = wm*32 + (g & 1)*8 + r;
                    uint32_t off = (uint32_t)(arow*PADK + ki*16 + (g >> 1)*8) * 2;
                    ldsm4(aBase + off,                  ah[0][0], ah[0][1], ah[0][2], ah[0][3]);
                    ldsm4(aBase + off + 16*PADK*2,      ah[1][0], ah[1][1], ah[1][2], ah[1][3]);
                    ldsm4(aBase + 10240u + off,             al[0][0], al[0][1], al[0][2], al[0][3]);
                    ldsm4(aBase + 10240u + off + 16*PADK*2, al[1][0], al[1][1], al[1][2], al[1][3]);
                }
                #pragma unroll
                for (int ng = 0; ng < 2; ++ng){
                    uint32_t bhf[4][2], blf[4][2];
                    int nrow = wn*64 + ng*32 + (g >> 1)*8 + r;
                    uint32_t off = (uint32_t)(nrow*PADK + ki*16 + (g & 1)*8) * 2;
                    ldsm4(bBase + off,                 bhf[0][0], bhf[0][1], bhf[1][0], bhf[1][1]);
                    ldsm4(bBase + off + 16*PADK*2,     bhf[2][0], bhf[2][1], bhf[3][0], bhf[3][1]);
                    ldsm4(bBase + BPL + off,             blf[0][0], blf[0][1], blf[1][0], blf[1][1]);
                    ldsm4(bBase + BPL + off + 16*PADK*2, blf[2][0], blf[2][1], blf[3][0], blf[3][1]);
                    #pragma unroll
                    for (int mi = 0; mi < 2; ++mi)
                        #pragma unroll
                        for (int j = 0; j < 4; ++j){
                            float* a = acc + ((mi*8) + ng*4 + j)*4;
                            mma16816(a, ah[mi], bhf[j]);
                            mma16816(a, ah[mi], blf[j]);
                            mma16816(a, al[mi], bhf[j]);
                        }
                }
            }
            if (c + 1 < 4) CP_WAIT0();
            __syncthreads();
        }

        #pragma unroll
        for (int mi = 0; mi < 2; ++mi)
            #pragma unroll
            for (int ni = 0; ni < 8; ++ni){
                const float* a = acc + (mi*8 + ni)*4;
                int gcol = wn*64 + ni*8 + tr*2;
                int r0 = rowBase + wm*32 + mi*16 + tq;
                float2 b = *(const float2*)&biases[op][gcol];
                size_t o0 = (size_t)r0*HD + gcol;
                size_t o1 = (size_t)(r0+8)*HD + gcol;
                float2 u0 = make_float2(a[0]+b.x, a[1]+b.y);
                float2 u1 = make_float2(a[2]+b.x, a[3]+b.y);
                if (op == 0) {
                    *(__half2*)&fz[o0] = __floats2half2_rn(u0.x, u0.y);
                    *(__half2*)&fz[o1] = __floats2half2_rn(u1.x, u1.y);
                } else if (op == 1) {
                    *(__half2*)&fh[o0] = __floats2half2_rn(u0.x, u0.y);
                    *(__half2*)&fh[o1] = __floats2half2_rn(u1.x, u1.y);
                    float2 z0 = __half22float2(*(const __half2*)&fz[o0]);
                    float2 z1 = __half22float2(*(const __half2*)&fz[o1]);
                    float2 w0 = make_float2(sigm(z0.x)*tanhf(u0.x), sigm(z0.y)*tanhf(u0.y));
                    float2 w1 = make_float2(sigm(z1.x)*tanhf(u1.x), sigm(z1.y)*tanhf(u1.y));
                    if (r0 == 0) w0 = make_float2(0.f, 0.f);   // null message row
                    *(__half2*)&h16[o0] = __floats2half2_rn(w0.x, w0.y);
                    *(__half2*)&h16[o1] = __floats2half2_rn(w1.x, w1.y);
                } else {
                    *(__half2*)&rx[o0] = __floats2half2_rn(u0.x, u0.y);
                    *(__half2*)&rx[o1] = __floats2half2_rn(u1.x, u1.y);
                }
            }
    }
}

// ================= fp16 single-pass GRU-step dual GEMM ====================
// wr32 != 0: write fp32 C only (final step). wr32 == 0: write fp16 C16 only.
__global__ __launch_bounds__(512, 1)
void mode1f(const __half* __restrict__ A1, const __half* __restrict__ B1,
            const __half* __restrict__ A2, const __half* __restrict__ B2,
            const __half* __restrict__ fz, const __half* __restrict__ fh,
            float* __restrict__ C, __half* __restrict__ C16, int wr32)
{
    constexpr int K = HD;                          // 256, 8 chunks
    constexpr uint32_t APL = 5120u, ABYTES = 10240u;
    constexpr uint32_t BPL = 20480u, STG = 51200u;
    extern __shared__ char sm[];
    const int tid = threadIdx.x;
    const int rowBase = (int)blockIdx.x << 6;      // MT=64
    const int lane = tid & 31, wid = tid >> 5;
    const int wm = wid >> 3, wn = wid & 7;         // 2 x 8 warps
    const int g = lane >> 3, r = lane & 7;
    const int tq = lane >> 2, tr = lane & 3;
    const uint32_t sb = smem_addr(sm);

    const int a_op = tid >> 8, a_rem = tid & 255;
    const int a_row = a_rem >> 2, a_seg = a_rem & 3;
    const __half* a_src = ((a_op == 0) ? A1 : A2)
        + (size_t)(rowBase + a_row)*K + (a_seg << 3);
    const uint32_t a_dst = (uint32_t)a_op*APL + (uint32_t)a_row*80u + (uint32_t)a_seg*16u;

    auto issue = [&](uint32_t st, int c){
        CPA16(st + a_dst, a_src + (c << 5));
        #pragma unroll
        for (int i = 0; i < 4; ++i){
            int idx = tid + (i << 9);
            int op = idx >> 10;
            int rem = idx & 1023;
            int row = rem >> 2, seg = rem & 3;
            const __half* src = ((op == 0) ? B1 : B2)
                + (size_t)row*K + (c << 5) + (seg << 3);
            CPA16(st + ABYTES + (uint32_t)op*BPL + (uint32_t)row*80u + (uint32_t)seg*16u, src);
        }
        CP_COMMIT();
    };

    float acc[64];
    #pragma unroll
    for (int i = 0; i < 64; ++i) acc[i] = 0.f;

    issue(sb, 0);
    issue(sb + STG, 1);

    for (int c = 0; c < 8; ++c){
        if (c + 1 < 8) { CP_WAIT1(); } else { CP_WAIT0(); }
        __syncthreads();
        if (c + 2 < 8) issue(sb + ((c+2)%3)*STG, c+2);
        const uint32_t st = sb + (c%3)*STG;

        #pragma unroll
        for (int op = 0; op < 2; ++op){
            const uint32_t aBase = st + (uint32_t)op*APL;
            const uint32_t bBase = st + ABYTES + (uint32_t)op*BPL;
            #pragma unroll
            for (int ki = 0; ki < 2; ++ki){
                uint32_t ah[2][4];
                {
                    int arow = wm*32 + (g & 1)*8 + r;
                    uint32_t off = (uint32_t)(arow*PADK + ki*16 + (g >> 1)*8) * 2;
                    ldsm4(aBase + off,             ah[0][0], ah[0][1], ah[0][2], ah[0][3]);
                    ldsm4(aBase + off + 16*PADK*2, ah[1][0], ah[1][1], ah[1][2], ah[1][3]);
                }
                uint32_t bf[4][2];
                {
                    int nrow = wn*32 + (g >> 1)*8 + r;
                    uint32_t off = (uint32_t)(nrow*PADK + ki*16 + (g & 1)*8) * 2;
                    ldsm4(bBase + off,             bf[0][0], bf[0][1], bf[1][0], bf[1][1]);
                    ldsm4(bBase + off + 16*PADK*2, bf[2][0], bf[2][1], bf[3][0], bf[3][1]);
                }
                #pragma unroll
                for (int mi = 0; mi < 2; ++mi)
                    #pragma unroll
                    for (int j = 0; j < 4; ++j)
                        mma16816h(acc + ((op*2 + mi)*4 + j)*4, ah[mi], bf[j]);
            }
        }
    }

    #pragma unroll
    for (int mi = 0; mi < 2; ++mi)
        #pragma unroll
        for (int ni = 0; ni < 4; ++ni){
            const float* a1 = acc + ((0*2 + mi)*4 + ni)*4;
            const float* a2 = acc + ((1*2 + mi)*4 + ni)*4;
            int gcol = wn*32 + ni*8 + tr*2;
            int r0 = rowBase + wm*32 + mi*16 + tq;
            size_t o0 = (size_t)r0*HD + gcol;
            size_t o1 = (size_t)(r0+8)*HD + gcol;
            float2 za = __half22float2(*(const __half2*)&fz[o0]);
            float2 zb = __half22float2(*(const __half2*)&fz[o1]);
            float2 ha = __half22float2(*(const __half2*)&fh[o0]);
            float2 hb = __half22float2(*(const __half2*)&fh[o1]);
            float2 sa = __half22float2(*(const __half2*)&A1[o0]);
            float2 sb2 = __half22float2(*(const __half2*)&A1[o1]);
            float z0 = sigm(za.x + a1[0]);
            float z1 = sigm(za.y + a1[1]);
            float z2 = sigm(zb.x + a1[2]);
            float z3 = sigm(zb.y + a1[3]);
            float p0 = tanhf(ha.x + a2[0]);
            float p1 = tanhf(ha.y + a2[1]);
            float p2 = tanhf(hb.x + a2[2]);
            float p3 = tanhf(hb.y + a2[3]);
            float2 u0 = make_float2((1.f - z0)*sa.x + z0*p0, (1.f - z1)*sa.y + z1*p1);
            float2 u1 = make_float2((1.f - z2)*sb2.x + z2*p2, (1.f - z3)*sb2.y + z3*p3);
            if (r0 == 0) u0 = make_float2(0.f, 0.f);
            if (wr32) {
                *(float2*)&C[o0] = u0;
                *(float2*)&C[o1] = u1;
            } else {
                *(__half2*)&C16[o0] = __floats2half2_rn(u0.x, u0.y);
                *(__half2*)&C16[o1] = __floats2half2_rn(u1.x, u1.y);
            }
        }
}

// ================= MODE2 (output layer, bf16 3-pass) ======================
__global__ __launch_bounds__(512, 1)
void mode2_gemm(const float* __restrict__ A1, int K1,
                const __nv_bfloat16* __restrict__ B1h, const __nv_bfloat16* __restrict__ B1l,
                const float* __restrict__ A2, int K2,
                const __nv_bfloat16* __restrict__ B2h, const __nv_bfloat16* __restrict__ B2l,
                int M, const float* __restrict__ bias, const float* __restrict__ maskv,
                float* __restrict__ C)
{
    extern __shared__ char sm[];
    const int tid = threadIdx.x;
    const int rowBase = (int)blockIdx.x << 7;
    const int lane = tid & 31, wid = tid >> 5;
    const int wm = wid >> 2, wn = wid & 3;
    const int tq = lane >> 2, tr = lane & 3;

    float acc[64];
    #pragma unroll
    for (int i = 0; i < 64; ++i) acc[i] = 0.f;

    run_phase<128,1>(A1, nullptr, K1, B1h, B1l, nullptr, nullptr, acc, sm, tid, rowBase, M);
    run_phase<128,1>(A2, nullptr, K2, B2h, B2l, nullptr, nullptr, acc, sm, tid, rowBase, M);

    #pragma unroll
    for (int mi = 0; mi < 2; ++mi)
        #pragma unroll
        for (int ni = 0; ni < 8; ++ni) {
            const float* a = acc + (mi*8 + ni)*4;
            int gcol = wn*64 + ni*8 + tr*2;
            int r0 = rowBase + wm*32 + mi*16 + tq;
            float2 b = *(const float2*)&bias[gcol];
            if (r0 < M) {
                float m = maskv[r0];
                *(float2*)&C[(size_t)r0*HD + gcol] =
                    make_float2(fmaxf(a[0]+b.x, 0.f)*m, fmaxf(a[1]+b.y, 0.f)*m);
            }
            if (r0 + 8 < M) {
                float m = maskv[r0+8];
                *(float2*)&C[(size_t)(r0+8)*HD + gcol] =
                    make_float2(fmaxf(a[2]+b.x, 0.f)*m, fmaxf(a[3]+b.y, 0.f)*m);
            }
        }
}

// ===== one-shot weight prep: all bf16 splits + fp16 transposes ============
__global__ void prep_all(const float* __restrict__ W_z, const float* __restrict__ W_h,
                         const float* __restrict__ W_r, const float* __restrict__ U_r,
                         const float* __restrict__ W_o,
                         __nv_bfloat16* __restrict__ bh, __nv_bfloat16* __restrict__ bl,
                         __half* __restrict__ wz16, __half* __restrict__ wh16)
{
    int b = blockIdx.x, t = threadIdx.x;
    if (b < 512) {
        int job = b >> 7;
        int i = ((b & 127) << 8) + t;
        const float* W = (job == 0) ? W_z : (job == 1) ? W_h : (job == 2) ? W_r : W_o;
        int off = (job == 0) ? OFF_WZT : (job == 1) ? OFF_WHT : (job == 2) ? OFF_WR : OFF_WOT;
        int k = i & 127, n = i >> 7;
        float x = W[(size_t)k*HD + n];
        __nv_bfloat16 h = __float2bfloat16_rn(x);
        bh[off + i] = h;
        bl[off + i] = __float2bfloat16_rn(x - __bfloat162float(h));
    } else if (b < 1024) {
        int job = (b - 512) >> 8;
        int i = (((b - 512) & 255) << 8) + t;
        const float* W = (job == 0) ? U_r : (W_o + (size_t)IND*HD);
        int off = (job == 0) ? OFF_UR : OFF_WOB;
        int k = i & 255, n = i >> 8;
        float x = W[(size_t)k*HD + n];
        __nv_bfloat16 h = __float2bfloat16_rn(x);
        bh[off + i] = h;
        bl[off + i] = __float2bfloat16_rn(x - __bfloat162float(h));
    } else {
        int job = (b - 1024) >> 8;
        int i = (((b - 1024) & 255) << 8) + t;
        const float* W = ((job == 0) ? W_z : W_h) + (size_t)IND*HD;
        __half* o = (job == 0) ? wz16 : wh16;
        int k = i & 255, n = i >> 8;
        o[i] = __float2half_rn(W[(size_t)k*HD + n]);
    }
}

__global__ void gather_msgs(const __half* __restrict__ h16, const __half* __restrict__ hU,
                            const __half* __restrict__ rx, const int* __restrict__ bg,
                            __half* __restrict__ sumh, __half* __restrict__ sumg)
{
    __shared__ int s_nb[4][NBR];
    int e = blockIdx.x * 4 + threadIdx.y;
    if (threadIdx.x < NBR) s_nb[threadIdx.y][threadIdx.x] = bg[e*NBR + threadIdx.x];
    __syncthreads();
    int c = threadIdx.x << 2;
    size_t base = (size_t)e*HD + c;
    uint2 rx4 = *(const uint2*)(rx + base);
    float2 r01 = __half22float2(*reinterpret_cast<__half2*>(&rx4.x));
    float2 r23 = __half22float2(*reinterpret_cast<__half2*>(&rx4.y));
    float4 sh = make_float4(0.f,0.f,0.f,0.f);
    float4 sg = make_float4(0.f,0.f,0.f,0.f);
    #pragma unroll
    for (int j = 0; j < NBR; ++j) {
        size_t nb = (size_t)s_nb[threadIdx.y][j]*HD + c;
        uint2 hq = *(const uint2*)(h16 + nb);
        float2 h01 = __half22float2(*reinterpret_cast<__half2*>(&hq.x));
        float2 h23 = __half22float2(*reinterpret_cast<__half2*>(&hq.y));
        uint2 hu4 = *(const uint2*)(hU + nb);
        float2 u01 = __half22float2(*reinterpret_cast<__half2*>(&hu4.x));
        float2 u23 = __half22float2(*reinterpret_cast<__half2*>(&hu4.y));
        sh.x += h01.x; sh.y += h01.y; sh.z += h23.x; sh.w += h23.y;
        sg.x += sigm(r01.x + u01.x) * h01.x;
        sg.y += sigm(r01.y + u01.y) * h01.y;
        sg.z += sigm(r23.x + u23.x) * h23.x;
        sg.w += sigm(r23.y + u23.y) * h23.y;
    }
    __half2 sh01 = __floats2half2_rn(sh.x, sh.y), sh23 = __floats2half2_rn(sh.z, sh.w);
    __half2 sg01 = __floats2half2_rn(sg.x, sg.y), sg23 = __floats2half2_rn(sg.z, sg.w);
    *(uint2*)(sumh + base) = make_uint2(h2u(sh01), h2u(sh23));
    *(uint2*)(sumg + base) = make_uint2(h2u(sg01), h2u(sg23));
}

__global__ void gather_nodes(const float* __restrict__ h, const int* __restrict__ ag,
                             float* __restrict__ nei)
{
    __shared__ int s_nb[4][NBR];
    int v = blockIdx.x * 4 + threadIdx.y;
    if (threadIdx.x < NBR) s_nb[threadIdx.y][threadIdx.x] = ag[v*NBR + threadIdx.x];
    __syncthreads();
    int c = threadIdx.x << 2;
    float4 s = make_float4(0.f,0.f,0.f,0.f);
    #pragma unroll
    for (int j = 0; j < NBR; ++j) {
        size_t nb = (size_t)s_nb[threadIdx.y][j]*HD + c;
        float4 hv = *(const float4*)&h[nb];
        s.x += hv.x; s.y += hv.y; s.z += hv.z; s.w += hv.w;
    }
    *(float4*)&nei[(size_t)v*HD + c] = s;
}

extern "C" void kernel_launch(void* const* d_in, const int* in_sizes, int n_in,
                              void* d_out, int out_size)
{
    const float* fnode  = (const float*)d_in[0];
    const float* fmess  = (const float*)d_in[1];
    const int*   agraph = (const int*)  d_in[2];
    const int*   bgraph = (const int*)  d_in[3];
    const float* mask   = (const float*)d_in[4];
    const float* W_z    = (const float*)d_in[5];
    const float* b_z    = (const float*)d_in[6];
    const float* W_r    = (const float*)d_in[7];
    const float* U_r    = (const float*)d_in[8];
    const float* b_ur   = (const float*)d_in[9];
    const float* W_h    = (const float*)d_in[10];
    const float* b_h    = (const float*)d_in[11];
    const float* W_o    = (const float*)d_in[12];
    const float* b_o    = (const float*)d_in[13];

    float* out_node = (float*)d_out;
    float* out_h    = out_node + (size_t)NN*HD;

    float *nei;
    __half *h16, *fz16, *fh16, *sumh16, *sumg16, *hU16, *rx16, *wz16, *wh16;
    __nv_bfloat16 *bh, *bl;
    cudaGetSymbolAddress((void**)&nei,    g_nei);
    cudaGetSymbolAddress((void**)&h16,    g_h16);
    cudaGetSymbolAddress((void**)&fz16,   g_fz16);
    cudaGetSymbolAddress((void**)&fh16,   g_fh16);
    cudaGetSymbolAddress((void**)&sumh16, g_sumh16);
    cudaGetSymbolAddress((void**)&sumg16, g_sumg16);
    cudaGetSymbolAddress((void**)&hU16,   g_hU16);
    cudaGetSymbolAddress((void**)&rx16,   g_rx16);
    cudaGetSymbolAddress((void**)&wz16,   g_wz16);
    cudaGetSymbolAddress((void**)&wh16,   g_wh16);
    cudaGetSymbolAddress((void**)&bh,     g_bh);
    cudaGetSymbolAddress((void**)&bl,     g_bl);

    cudaFuncSetAttribute((const void*)inv3_gemm,
                         cudaFuncAttributeMaxDynamicSharedMemorySize, SMEM_I3);
    cudaFuncSetAttribute((const void*)hU_gemm,
                         cudaFuncAttributeMaxDynamicSharedMemorySize, SMEM_HU);
    cudaFuncSetAttribute((const void*)mode1f,
                         cudaFuncAttributeMaxDynamicSharedMemorySize, SMEM_M1F);
    cudaFuncSetAttribute((const void*)mode2_gemm,
                         cudaFuncAttributeMaxDynamicSharedMemorySize, SMEM_M0);

    const int gE128 = NM / 128;               // 625
    const int gE64  = NM / 64;                // 1250
    const int gV    = NNP / 128;              // 274

    // launch 1: all weight preps in one kernel
    prep_all<<<1536, 256>>>(W_z, W_h, W_r, U_r, W_o, bh, bl, wz16, wh16);

    // launch 2: fused invariants (fz16, fh16, h16 step-1, rx16)
    inv3_gemm<<<gE128, 512, SMEM_I3>>>(fmess,
        bh+OFF_WZT, bl+OFF_WZT, bh+OFF_WHT, bl+OFF_WHT, bh+OFF_WR, bl+OFF_WR,
        b_z, b_h, b_ur, fz16, fh16, h16, rx16);

    // launches 3..14: 4 GRU steps
    for (int d = 1; d < DEPTH; ++d) {
        hU_gemm<<<gE128, 512, SMEM_HU>>>(h16, bh+OFF_UR, hU16);
        gather_msgs<<<NM/4, dim3(64,4)>>>(h16, hU16, rx16, bgraph, sumh16, sumg16);
        mode1f<<<gE64, 512, SMEM_M1F>>>(sumh16, wz16, sumg16, wh16,
                                        fz16, fh16, out_h, h16, (d == DEPTH-1) ? 1 : 0);
    }

    gather_nodes<<<NN/4, dim3(64,4)>>>(out_h, agraph, nei);
    mode2_gemm<<<gV, 512, SMEM_M0>>>(fnode, IND, bh+OFF_WOT, bl+OFF_WOT,
                                     nei, HD, bh+OFF_WOB, bl+OFF_WOB,
                                     NN, b_o, mask, out_node);
}

// round 16
// speedup vs baseline: 1.7817x; 1.0433x over previous
#include <cuda_runtime.h>
#include <cuda_bf16.h>
#include <cuda_fp16.h>
#include <math.h>
#include <cstdint>

#define NN 35000
#define NM 80000
#define NBR 6
#define IND 128
#define HD 256
#define DEPTH 5
#define NNP 35072

// ---------------- scratch (__device__ globals; no allocs) ----------------
__device__ float g_nei [(size_t)NNP*HD];
__device__ __align__(16) __half g_h16  [(size_t)NM*HD];   // fp16 h (steps 1..4)
__device__ __align__(16) __half g_fz16 [(size_t)NM*HD];
__device__ __align__(16) __half g_fh16 [(size_t)NM*HD];
__device__ __align__(16) __half g_sumh16[(size_t)NM*HD];
__device__ __align__(16) __half g_sumg16[(size_t)NM*HD];
__device__ __align__(16) __half g_hU16[(size_t)NM*HD];
__device__ __align__(16) __half g_rx16[(size_t)NM*HD];
__device__ __align__(16) __half g_wz16[65536];
__device__ __align__(16) __half g_wh16[65536];

#define OFF_WZT 0
#define OFF_WHT 32768
#define OFF_WR  65536
#define OFF_WOT 98304
#define OFF_UR  131072
#define OFF_WOB 196608
__device__ __align__(16) __nv_bfloat16 g_bh[262144];
__device__ __align__(16) __nv_bfloat16 g_bl[262144];

// fast fp32 sigmoid (epilogues): 2 MUFU + ~3 ALU
__device__ __forceinline__ float sigm(float x){
    return __fdividef(1.0f, 1.0f + __expf(-x));
}
// packed fp16 sigmoid via MUFU.TANH.F16x2: sig(x) = 0.5*tanh(x/2) + 0.5
__device__ __forceinline__ __half2 sigm2(__half2 x){
    const __half2 h05 = __half2half2(__float2half_rn(0.5f));
    __half2 t = __hmul2(x, h05);
    uint32_t r;
    asm("tanh.approx.f16x2 %0, %1;" : "=r"(r) : "r"(*(uint32_t*)&t));
    return __hfma2(*(__half2*)&r, h05, h05);
}

// ---------------- mma / ldmatrix / cp.async helpers ----------------------
__device__ __forceinline__ uint32_t smem_addr(const void* p){
    return (uint32_t)__cvta_generic_to_shared(p);
}
__device__ __forceinline__ void ldsm4(uint32_t a, uint32_t& r0, uint32_t& r1,
                                      uint32_t& r2, uint32_t& r3){
    asm volatile("ldmatrix.sync.aligned.m8n8.x4.shared.b16 {%0,%1,%2,%3}, [%4];"
                 : "=r"(r0), "=r"(r1), "=r"(r2), "=r"(r3) : "r"(a));
}
__device__ __forceinline__ void mma16816(float* c, const uint32_t* a, const uint32_t* b){
    asm volatile(
        "mma.sync.aligned.m16n8k16.row.col.f32.bf16.bf16.f32 "
        "{%0,%1,%2,%3}, {%4,%5,%6,%7}, {%8,%9}, {%0,%1,%2,%3};"
        : "+f"(c[0]), "+f"(c[1]), "+f"(c[2]), "+f"(c[3])
        : "r"(a[0]), "r"(a[1]), "r"(a[2]), "r"(a[3]), "r"(b[0]), "r"(b[1]));
}
__device__ __forceinline__ void mma16816h(float* c, const uint32_t* a, const uint32_t* b){
    asm volatile(
        "mma.sync.aligned.m16n8k16.row.col.f32.f16.f16.f32 "
        "{%0,%1,%2,%3}, {%4,%5,%6,%7}, {%8,%9}, {%0,%1,%2,%3};"
        : "+f"(c[0]), "+f"(c[1]), "+f"(c[2]), "+f"(c[3])
        : "r"(a[0]), "r"(a[1]), "r"(a[2]), "r"(a[3]), "r"(b[0]), "r"(b[1]));
}
#define CPA16(dst, src) \
    asm volatile("cp.async.cg.shared.global [%0], [%1], 16;" :: "r"(dst), "l"(src))
#define CP_COMMIT() asm volatile("cp.async.commit_group;" ::: "memory")
#define CP_WAIT0()  asm volatile("cp.async.wait_group 0;" ::: "memory")
#define CP_WAIT1()  asm volatile("cp.async.wait_group 1;" ::: "memory")

__device__ __forceinline__ void cvt_split8(float4 v0, float4 v1, uint4& hi, uint4& lo){
    float f[8] = {v0.x,v0.y,v0.z,v0.w,v1.x,v1.y,v1.z,v1.w};
    uint32_t hh[8], ll[8];
    #pragma unroll
    for (int j = 0; j < 8; ++j) {
        __nv_bfloat16 h = __float2bfloat16_rn(f[j]);
        float hf = __bfloat162float(h);
        __nv_bfloat16 l = __float2bfloat16_rn(f[j] - hf);
        hh[j] = (uint32_t)__bfloat16_as_ushort(h);
        ll[j] = (uint32_t)__bfloat16_as_ushort(l);
    }
    hi = make_uint4(hh[0]|(hh[1]<<16), hh[2]|(hh[3]<<16), hh[4]|(hh[5]<<16), hh[6]|(hh[7]<<16));
    lo = make_uint4(ll[0]|(ll[1]<<16), ll[2]|(ll[3]<<16), ll[4]|(ll[5]<<16), ll[6]|(ll[7]<<16));
}
// 8 fp16 -> 8 bf16 (hi only)
__device__ __forceinline__ uint4 cvt_h8_bf8(uint4 v){
    const __half* hp = (const __half*)&v;
    uint32_t hh[8];
    #pragma unroll
    for (int j = 0; j < 8; ++j)
        hh[j] = (uint32_t)__bfloat16_as_ushort(__float2bfloat16_rn(__half2float(hp[j])));
    return make_uint4(hh[0]|(hh[1]<<16), hh[2]|(hh[3]<<16), hh[4]|(hh[5]<<16), hh[6]|(hh[7]<<16));
}
__device__ __forceinline__ uint32_t h2u(__half2 v){ return *(uint32_t*)&v; }

#define PADK 40

// ================= 3-pass bf16 phase (mode2 only) =========================
template<int MT, int NA>
__device__ __forceinline__ void run_phase(
    const float* __restrict__ A1, const float* __restrict__ A2, int K,
    const __nv_bfloat16* __restrict__ B1h, const __nv_bfloat16* __restrict__ B1l,
    const __nv_bfloat16* __restrict__ B2h, const __nv_bfloat16* __restrict__ B2l,
    float* acc, char* sm, int tid, int rowBase, int M)
{
    constexpr int WM = MT/32;
    constexpr int WN = 16/WM;
    constexpr int NSPAN = 256/WN;
    constexpr int NFR = NSPAN/8;
    constexpr uint32_t APL = MT*80u;
    constexpr uint32_t A_BYTES = NA*2u*APL;
    constexpr uint32_t BPL = 20480u;
    constexpr uint32_t STAGE_ = A_BYTES + NA*2u*BPL;
    constexpr int NB = NA*4;
    const int lane = tid & 31, wid = tid >> 5;
    const int wm = wid / WN, wn = wid % WN;
    const int g = lane >> 3, r = lane & 7;
    const uint32_t sb = smem_addr(sm);
    const int nch = K >> 5;

    const int a_op  = tid / (MT*4);
    const int a_rem = tid % (MT*4);
    const int a_row = a_rem >> 2, a_seg = a_rem & 3;
    const int grow = rowBase + a_row;
    const bool a_ok = (grow < M);
    const float* a_src = ((a_op == 0) ? A1 : A2) + (size_t)grow*K + (a_seg << 3);
    const uint32_t a_off = (uint32_t)a_op*2u*APL + (uint32_t)a_row*80u + (uint32_t)a_seg*16u;

    auto issue_B = [&](uint32_t st, int c){
        #pragma unroll
        for (int i = 0; i < NB; ++i){
            int idx = tid + (i << 9);
            int op = idx >> 11;
            int rem = idx & 2047;
            int plane = rem >> 10;
            int rem2 = rem & 1023;
            int row = rem2 >> 2, seg = rem2 & 3;
            const __nv_bfloat16* Bp = (op == 0) ? (plane ? B1l : B1h)
                                                : (plane ? B2l : B2h);
            const __nv_bfloat16* src = Bp + (size_t)row*K + (c << 5) + (seg << 3);
            uint32_t dst = st + A_BYTES + (uint32_t)op*(2u*BPL) + (uint32_t)plane*BPL
                         + (uint32_t)row*80u + (uint32_t)seg*16u;
            CPA16(dst, src);
        }
        CP_COMMIT();
    };

    {
        float4 v0 = make_float4(0.f,0.f,0.f,0.f), v1 = v0;
        if (a_ok){ v0 = *(const float4*)a_src; v1 = *(const float4*)(a_src + 4); }
        issue_B(sb, 0);
        uint4 hi, lo; cvt_split8(v0, v1, hi, lo);
        *(uint4*)(sm + a_off)       = hi;
        *(uint4*)(sm + a_off + APL) = lo;
        CP_WAIT0();
    }
    __syncthreads();

    for (int c = 0; c < nch; ++c){
        const uint32_t st = sb + (c & 1)*STAGE_;
        const int nc = c + 1;
        float4 v0, v1;
        if (nc < nch){
            v0 = make_float4(0.f,0.f,0.f,0.f); v1 = v0;
            if (a_ok){
                const float* p = a_src + (nc << 5);
                v0 = *(const float4*)p; v1 = *(const float4*)(p + 4);
            }
            issue_B(sb + (nc & 1)*STAGE_, nc);
        }

        #pragma unroll
        for (int op = 0; op < NA; ++op){
            const uint32_t aBase = st + (uint32_t)op*2u*APL;
            const uint32_t bBase = st + A_BYTES + (uint32_t)op*(2u*BPL);
            #pragma unroll
            for (int ki = 0; ki < 2; ++ki){
                uint32_t ah[2][4], al[2][4];
                {
                    int arow = wm*32 + (g & 1)*8 + r;
                    uint32_t off = (uint32_t)(arow*PADK + ki*16 + (g >> 1)*8) * 2;
                    ldsm4(aBase + off,                   ah[0][0], ah[0][1], ah[0][2], ah[0][3]);
                    ldsm4(aBase + off + 16*PADK*2,       ah[1][0], ah[1][1], ah[1][2], ah[1][3]);
                    ldsm4(aBase + APL + off,             al[0][0], al[0][1], al[0][2], al[0][3]);
                    ldsm4(aBase + APL + off + 16*PADK*2, al[1][0], al[1][1], al[1][2], al[1][3]);
                }
                #pragma unroll
                for (int ng = 0; ng < NFR/4; ++ng){
                    uint32_t bhf[4][2], blf[4][2];
                    int nrow = wn*NSPAN + ng*32 + (g >> 1)*8 + r;
                    uint32_t off = (uint32_t)(nrow*PADK + ki*16 + (g & 1)*8) * 2;
                    ldsm4(bBase + off,                 bhf[0][0], bhf[0][1], bhf[1][0], bhf[1][1]);
                    ldsm4(bBase + off + 16*PADK*2,     bhf[2][0], bhf[2][1], bhf[3][0], bhf[3][1]);
                    ldsm4(bBase + BPL + off,             blf[0][0], blf[0][1], blf[1][0], blf[1][1]);
                    ldsm4(bBase + BPL + off + 16*PADK*2, blf[2][0], blf[2][1], blf[3][0], blf[3][1]);
                    #pragma unroll
                    for (int mi = 0; mi < 2; ++mi)
                        #pragma unroll
                        for (int j = 0; j < 4; ++j){
                            float* a = acc + (((op*2 + mi)*NFR) + ng*4 + j)*4;
                            mma16816(a, ah[mi], bhf[j]);
                            mma16816(a, ah[mi], blf[j]);
                            mma16816(a, al[mi], bhf[j]);
                        }
                }
            }
        }

        if (nc < nch){
            char* nsm = sm + (nc & 1)*STAGE_;
            uint4 hi, lo; cvt_split8(v0, v1, hi, lo);
            *(uint4*)(nsm + a_off)       = hi;
            *(uint4*)(nsm + a_off + APL) = lo;
            CP_WAIT0();
        }
        __syncthreads();
    }
}

#define SMEM_M0  (2*(2*128*80 + 2*20480))   // 122880
#define SMEM_HU  (2*(128*80 + 20480))       // 61440
#define SMEM_I3  (4*20480 + 2*40960)        // 163840
#define SMEM_M1F (3*(2*64*80 + 2*20480))    // 153600

// ================= single-pass bf16 GEMM for hU (gate path) ==============
__global__ __launch_bounds__(512, 1)
void hU_gemm(const __half* __restrict__ A, const __nv_bfloat16* __restrict__ Bh,
             __half* __restrict__ Cout)
{
    constexpr int K = HD;
    constexpr uint32_t APL = 10240u, STAGE_ = 30720u;
    extern __shared__ char sm[];
    const int tid = threadIdx.x;
    const int rowBase = (int)blockIdx.x << 7;
    const int lane = tid & 31, wid = tid >> 5;
    const int wm = wid >> 2, wn = wid & 3;
    const int g = lane >> 3, r = lane & 7;
    const int tq = lane >> 2, tr = lane & 3;
    const uint32_t sb = smem_addr(sm);
    const int nch = K >> 5;

    const int a_row = tid >> 2, a_seg = tid & 3;
    const __half* a_src = A + (size_t)(rowBase + a_row)*K + (a_seg << 3);
    const uint32_t a_off = (uint32_t)a_row*80u + (uint32_t)a_seg*16u;

    auto issue_B = [&](uint32_t st, int c){
        #pragma unroll
        for (int i = 0; i < 2; ++i){
            int idx = tid + (i << 9);
            int row = idx >> 2, seg = idx & 3;
            CPA16(st + APL + (uint32_t)row*80u + (uint32_t)seg*16u,
                  Bh + (size_t)row*K + (c << 5) + (seg << 3));
        }
        CP_COMMIT();
    };

    float acc[64];
    #pragma unroll
    for (int i = 0; i < 64; ++i) acc[i] = 0.f;

    {
        uint4 v = *(const uint4*)a_src;
        issue_B(sb, 0);
        *(uint4*)(sm + a_off) = cvt_h8_bf8(v);
        CP_WAIT0();
    }
    __syncthreads();

    for (int c = 0; c < nch; ++c){
        const uint32_t st = sb + (c & 1)*STAGE_;
        const int nc = c + 1;
        uint4 v;
        if (nc < nch){
            v = *(const uint4*)(a_src + (nc << 5));
            issue_B(sb + (nc & 1)*STAGE_, nc);
        }

        #pragma unroll
        for (int ki = 0; ki < 2; ++ki){
            uint32_t ah[2][4];
            {
                int arow = wm*32 + (g & 1)*8 + r;
                uint32_t off = (uint32_t)(arow*PADK + ki*16 + (g >> 1)*8) * 2;
                ldsm4(st + off,             ah[0][0], ah[0][1], ah[0][2], ah[0][3]);
                ldsm4(st + off + 16*PADK*2, ah[1][0], ah[1][1], ah[1][2], ah[1][3]);
            }
            #pragma unroll
            for (int ng = 0; ng < 2; ++ng){
                uint32_t bhf[4][2];
                int nrow = wn*64 + ng*32 + (g >> 1)*8 + r;
                uint32_t off = (uint32_t)(nrow*PADK + ki*16 + (g & 1)*8) * 2;
                ldsm4(st + APL + off,             bhf[0][0], bhf[0][1], bhf[1][0], bhf[1][1]);
                ldsm4(st + APL + off + 16*PADK*2, bhf[2][0], bhf[2][1], bhf[3][0], bhf[3][1]);
                #pragma unroll
                for (int mi = 0; mi < 2; ++mi)
                    #pragma unroll
                    for (int j = 0; j < 4; ++j)
                        mma16816(acc + ((mi*8) + ng*4 + j)*4, ah[mi], bhf[j]);
            }
        }

        if (nc < nch){
            *(uint4*)(sm + (nc & 1)*STAGE_ + a_off) = cvt_h8_bf8(v);
            CP_WAIT0();
        }
        __syncthreads();
    }

    #pragma unroll
    for (int mi = 0; mi < 2; ++mi)
        #pragma unroll
        for (int ni = 0; ni < 8; ++ni){
            const float* a = acc + (mi*8 + ni)*4;
            int gcol = wn*64 + ni*8 + tr*2;
            int r0 = rowBase + wm*32 + mi*16 + tq;
            *(__half2*)&Cout[(size_t)r0*HD + gcol]     = __floats2half2_rn(a[0], a[1]);
            *(__half2*)&Cout[(size_t)(r0+8)*HD + gcol] = __floats2half2_rn(a[2], a[3]);
        }
}

// ================= fused invariants: fz16, fh16(+h16), rx16 ==============
__global__ __launch_bounds__(512, 1)
void inv3_gemm(const float* __restrict__ A,
               const __nv_bfloat16* __restrict__ Wzh, const __nv_bfloat16* __restrict__ Wzl,
               const __nv_bfloat16* __restrict__ Whh, const __nv_bfloat16* __restrict__ Whl,
               const __nv_bfloat16* __restrict__ Wrh, const __nv_bfloat16* __restrict__ Wrl,
               const float* __restrict__ b_z, const float* __restrict__ b_h,
               const float* __restrict__ b_ur,
               __half* __restrict__ fz, __half* __restrict__ fh,
               __half* __restrict__ h16, __half* __restrict__ rx)
{
    constexpr int K = IND;
    constexpr uint32_t B_OFF = 81920u;
    constexpr uint32_t BPL = 20480u, BSTG = 40960u;
    extern __shared__ char sm[];
    const int tid = threadIdx.x;
    const int rowBase = (int)blockIdx.x << 7;
    const int lane = tid & 31, wid = tid >> 5;
    const int wm = wid >> 2, wn = wid & 3;
    const int g = lane >> 3, r = lane & 7;
    const int tq = lane >> 2, tr = lane & 3;
    const uint32_t sb = smem_addr(sm);

    #pragma unroll
    for (int u = 0; u < 4; ++u){
        int idx = tid + (u << 9);
        int row = idx >> 4, gi = idx & 15;
        int t = gi >> 2, seg = gi & 3;
        const float* p = A + (size_t)(rowBase + row)*K + (gi << 3);
        float4 v0 = *(const float4*)p, v1 = *(const float4*)(p + 4);
        uint4 hi, lo; cvt_split8(v0, v1, hi, lo);
        uint32_t off = (uint32_t)t*20480u + (uint32_t)row*80u + (uint32_t)seg*16u;
        *(uint4*)(sm + off)          = hi;
        *(uint4*)(sm + off + 10240u) = lo;
    }
    __syncthreads();

    const __nv_bfloat16* Bhs[3] = {Wzh, Whh, Wrh};
    const __nv_bfloat16* Bls[3] = {Wzl, Whl, Wrl};
    const float* biases[3] = {b_z, b_h, b_ur};

    #pragma unroll
    for (int op = 0; op < 3; ++op){
        const __nv_bfloat16* Bh = Bhs[op];
        const __nv_bfloat16* Bl = Bls[op];

        auto issue_B = [&](uint32_t st, int c){
            #pragma unroll
            for (int i = 0; i < 4; ++i){
                int idx = tid + (i << 9);
                int plane = idx >> 10;
                int rem = idx & 1023;
                int row = rem >> 2, seg = rem & 3;
                const __nv_bfloat16* src = (plane ? Bl : Bh)
                    + (size_t)row*K + (c << 5) + (seg << 3);
                CPA16(st + (uint32_t)plane*BPL + (uint32_t)row*80u + (uint32_t)seg*16u, src);
            }
            CP_COMMIT();
        };

        float acc[64];
        #pragma unroll
        for (int i = 0; i < 64; ++i) acc[i] = 0.f;

        issue_B(sb + B_OFF, 0);
        CP_WAIT0();
        __syncthreads();

        for (int c = 0; c < 4; ++c){
            const uint32_t aBase = sb + (uint32_t)c*20480u;
            const uint32_t bBase = sb + B_OFF + (uint32_t)(c & 1)*BSTG;
            if (c + 1 < 4) issue_B(sb + B_OFF + (uint32_t)((c+1) & 1)*BSTG, c+1);

            #pragma unroll
            for (int ki = 0; ki < 2; ++ki){
                uint32_t ah[2][4], al[2][4];
                {
                    int arow = wm*32 + (g & 1)*8 + r;
                    uint32_t off = (uint32_t)(arow*PADK + ki*16 + (g >> 1)*8) * 2;
                    ldsm4(aBase + off,                  ah[0][0], ah[0][1], ah[0][2], ah[0][3]);
                    ldsm4(aBase + off + 16*PADK*2,      ah[1][0], ah[1][1], ah[1][2], ah[1][3]);
                    ldsm4(aBase + 10240u + off,             al[0][0], al[0][1], al[0][2], al[0][3]);
                    ldsm4(aBase + 10240u + off + 16*PADK*2, al[1][0], al[1][1], al[1][2], al[1][3]);
                }
                #pragma unroll
                for (int ng = 0; ng < 2; ++ng){
                    uint32_t bhf[4][2], blf[4][2];
                    int nrow = wn*64 + ng*32 + (g >> 1)*8 + r;
                    uint32_t off = (uint32_t)(nrow*PADK + ki*16 + (g & 1)*8) * 2;
                    ldsm4(bBase + off,                 bhf[0][0], bhf[0][1], bhf[1][0], bhf[1][1]);
                    ldsm4(bBase + off + 16*PADK*2,     bhf[2][0], bhf[2][1], bhf[3][0], bhf[3][1]);
                    ldsm4(bBase + BPL + off,             blf[0][0], blf[0][1], blf[1][0], blf[1][1]);
                    ldsm4(bBase + BPL + off + 16*PADK*2, blf[2][0], blf[2][1], blf[3][0], blf[3][1]);
                    #pragma unroll
                    for (int mi = 0; mi < 2; ++mi)
                        #pragma unroll
                        for (int j = 0; j < 4; ++j){
                            float* a = acc + ((mi*8) + ng*4 + j)*4;
                            mma16816(a, ah[mi], bhf[j]);
                            mma16816(a, ah[mi], blf[j]);
                            mma16816(a, al[mi], bhf[j]);
                        }
                }
            }
            if (c + 1 < 4) CP_WAIT0();
            __syncthreads();
        }

        #pragma unroll
        for (int mi = 0; mi < 2; ++mi)
            #pragma unroll
            for (int ni = 0; ni < 8; ++ni){
                const float* a = acc + (mi*8 + ni)*4;
                int gcol = wn*64 + ni*8 + tr*2;
                int r0 = rowBase + wm*32 + mi*16 + tq;
                float2 b = *(const float2*)&biases[op][gcol];
                size_t o0 = (size_t)r0*HD + gcol;
                size_t o1 = (size_t)(r0+8)*HD + gcol;
                float2 u0 = make_float2(a[0]+b.x, a[1]+b.y);
                float2 u1 = make_float2(a[2]+b.x, a[3]+b.y);
                if (op == 0) {
                    *(__half2*)&fz[o0] = __floats2half2_rn(u0.x, u0.y);
                    *(__half2*)&fz[o1] = __floats2half2_rn(u1.x, u1.y);
                } else if (op == 1) {
                    *(__half2*)&fh[o0] = __floats2half2_rn(u0.x, u0.y);
                    *(__half2*)&fh[o1] = __floats2half2_rn(u1.x, u1.y);
                    float2 z0 = __half22float2(*(const __half2*)&fz[o0]);
                    float2 z1 = __half22float2(*(const __half2*)&fz[o1]);
                    float2 w0 = make_float2(sigm(z0.x)*tanhf(u0.x), sigm(z0.y)*tanhf(u0.y));
                    float2 w1 = make_float2(sigm(z1.x)*tanhf(u1.x), sigm(z1.y)*tanhf(u1.y));
                    if (r0 == 0) w0 = make_float2(0.f, 0.f);   // null message row
                    *(__half2*)&h16[o0] = __floats2half2_rn(w0.x, w0.y);
                    *(__half2*)&h16[o1] = __floats2half2_rn(w1.x, w1.y);
                } else {
                    *(__half2*)&rx[o0] = __floats2half2_rn(u0.x, u0.y);
                    *(__half2*)&rx[o1] = __floats2half2_rn(u1.x, u1.y);
                }
            }
    }
}

// ================= fp16 single-pass GRU-step dual GEMM ====================
// wr32 != 0: write fp32 C only (final step). wr32 == 0: write fp16 C16 only.
__global__ __launch_bounds__(512, 1)
void mode1f(const __half* __restrict__ A1, const __half* __restrict__ B1,
            const __half* __restrict__ A2, const __half* __restrict__ B2,
            const __half* __restrict__ fz, const __half* __restrict__ fh,
            float* __restrict__ C, __half* __restrict__ C16, int wr32)
{
    constexpr int K = HD;                          // 256, 8 chunks
    constexpr uint32_t APL = 5120u, ABYTES = 10240u;
    constexpr uint32_t BPL = 20480u, STG = 51200u;
    extern __shared__ char sm[];
    const int tid = threadIdx.x;
    const int rowBase = (int)blockIdx.x << 6;      // MT=64
    const int lane = tid & 31, wid = tid >> 5;
    const int wm = wid >> 3, wn = wid & 7;         // 2 x 8 warps
    const int g = lane >> 3, r = lane & 7;
    const int tq = lane >> 2, tr = lane & 3;
    const uint32_t sb = smem_addr(sm);

    const int a_op = tid >> 8, a_rem = tid & 255;
    const int a_row = a_rem >> 2, a_seg = a_rem & 3;
    const __half* a_src = ((a_op == 0) ? A1 : A2)
        + (size_t)(rowBase + a_row)*K + (a_seg << 3);
    const uint32_t a_dst = (uint32_t)a_op*APL + (uint32_t)a_row*80u + (uint32_t)a_seg*16u;

    auto issue = [&](uint32_t st, int c){
        CPA16(st + a_dst, a_src + (c << 5));
        #pragma unroll
        for (int i = 0; i < 4; ++i){
            int idx = tid + (i << 9);
            int op = idx >> 10;
            int rem = idx & 1023;
            int row = rem >> 2, seg = rem & 3;
            const __half* src = ((op == 0) ? B1 : B2)
                + (size_t)row*K + (c << 5) + (seg << 3);
            CPA16(st + ABYTES + (uint32_t)op*BPL + (uint32_t)row*80u + (uint32_t)seg*16u, src);
        }
        CP_COMMIT();
    };

    float acc[64];
    #pragma unroll
    for (int i = 0; i < 64; ++i) acc[i] = 0.f;

    issue(sb, 0);
    issue(sb + STG, 1);

    for (int c = 0; c < 8; ++c){
        if (c + 1 < 8) { CP_WAIT1(); } else { CP_WAIT0(); }
        __syncthreads();
        if (c + 2 < 8) issue(sb + ((c+2)%3)*STG, c+2);
        const uint32_t st = sb + (c%3)*STG;

        #pragma unroll
        for (int op = 0; op < 2; ++op){
            const uint32_t aBase = st + (uint32_t)op*APL;
            const uint32_t bBase = st + ABYTES + (uint32_t)op*BPL;
            #pragma unroll
            for (int ki = 0; ki < 2; ++ki){
                uint32_t ah[2][4];
                {
                    int arow = wm*32 + (g & 1)*8 + r;
                    uint32_t off = (uint32_t)(arow*PADK + ki*16 + (g >> 1)*8) * 2;
                    ldsm4(aBase + off,             ah[0][0], ah[0][1], ah[0][2], ah[0][3]);
                    ldsm4(aBase + off + 16*PADK*2, ah[1][0], ah[1][1], ah[1][2], ah[1][3]);
                }
                uint32_t bf[4][2];
                {
                    int nrow = wn*32 + (g >> 1)*8 + r;
                    uint32_t off = (uint32_t)(nrow*PADK + ki*16 + (g & 1)*8) * 2;
                    ldsm4(bBase + off,             bf[0][0], bf[0][1], bf[1][0], bf[1][1]);
                    ldsm4(bBase + off + 16*PADK*2, bf[2][0], bf[2][1], bf[3][0], bf[3][1]);
                }
                #pragma unroll
                for (int mi = 0; mi < 2; ++mi)
                    #pragma unroll
                    for (int j = 0; j < 4; ++j)
                        mma16816h(acc + ((op*2 + mi)*4 + j)*4, ah[mi], bf[j]);
            }
        }
    }

    #pragma unroll
    for (int mi = 0; mi < 2; ++mi)
        #pragma unroll
        for (int ni = 0; ni < 4; ++ni){
            const float* a1 = acc + ((0*2 + mi)*4 + ni)*4;
            const float* a2 = acc + ((1*2 + mi)*4 + ni)*4;
            int gcol = wn*32 + ni*8 + tr*2;
            int r0 = rowBase + wm*32 + mi*16 + tq;
            size_t o0 = (size_t)r0*HD + gcol;
            size_t o1 = (size_t)(r0+8)*HD + gcol;
            float2 za = __half22float2(*(const __half2*)&fz[o0]);
            float2 zb = __half22float2(*(const __half2*)&fz[o1]);
            float2 ha = __half22float2(*(const __half2*)&fh[o0]);
            float2 hb = __half22float2(*(const __half2*)&fh[o1]);
            float2 sa = __half22float2(*(const __half2*)&A1[o0]);
            float2 sb2 = __half22float2(*(const __half2*)&A1[o1]);
            float z0 = sigm(za.x + a1[0]);
            float z1 = sigm(za.y + a1[1]);
            float z2 = sigm(zb.x + a1[2]);
            float z3 = sigm(zb.y + a1[3]);
            float p0 = tanhf(ha.x + a2[0]);
            float p1 = tanhf(ha.y + a2[1]);
            float p2 = tanhf(hb.x + a2[2]);
            float p3 = tanhf(hb.y + a2[3]);
            float2 u0 = make_float2((1.f - z0)*sa.x + z0*p0, (1.f - z1)*sa.y + z1*p1);
            float2 u1 = make_float2((1.f - z2)*sb2.x + z2*p2, (1.f - z3)*sb2.y + z3*p3);
            if (r0 == 0) u0 = make_float2(0.f, 0.f);
            if (wr32) {
                *(float2*)&C[o0] = u0;
                *(float2*)&C[o1] = u1;
            } else {
                *(__half2*)&C16[o0] = __floats2half2_rn(u0.x, u0.y);
                *(__half2*)&C16[o1] = __floats2half2_rn(u1.x, u1.y);
            }
        }
}

// ================= MODE2 (output layer, bf16 3-pass) ======================
__global__ __launch_bounds__(512, 1)
void mode2_gemm(const float* __restrict__ A1, int K1,
                const __nv_bfloat16* __restrict__ B1h, const __nv_bfloat16* __restrict__ B1l,
                const float* __restrict__ A2, int K2,
                const __nv_bfloat16* __restrict__ B2h, const __nv_bfloat16* __restrict__ B2l,
                int M, const float* __restrict__ bias, const float* __restrict__ maskv,
                float* __restrict__ C)
{
    extern __shared__ char sm[];
    const int tid = threadIdx.x;
    const int rowBase = (int)blockIdx.x << 7;
    const int lane = tid & 31, wid = tid >> 5;
    const int wm = wid >> 2, wn = wid & 3;
    const int tq = lane >> 2, tr = lane & 3;

    float acc[64];
    #pragma unroll
    for (int i = 0; i < 64; ++i) acc[i] = 0.f;

    run_phase<128,1>(A1, nullptr, K1, B1h, B1l, nullptr, nullptr, acc, sm, tid, rowBase, M);
    run_phase<128,1>(A2, nullptr, K2, B2h, B2l, nullptr, nullptr, acc, sm, tid, rowBase, M);

    #pragma unroll
    for (int mi = 0; mi < 2; ++mi)
        #pragma unroll
        for (int ni = 0; ni < 8; ++ni) {
            const float* a = acc + (mi*8 + ni)*4;
            int gcol = wn*64 + ni*8 + tr*2;
            int r0 = rowBase + wm*32 + mi*16 + tq;
            float2 b = *(const float2*)&bias[gcol];
            if (r0 < M) {
                float m = maskv[r0];
                *(float2*)&C[(size_t)r0*HD + gcol] =
                    make_float2(fmaxf(a[0]+b.x, 0.f)*m, fmaxf(a[1]+b.y, 0.f)*m);
            }
            if (r0 + 8 < M) {
                float m = maskv[r0+8];
                *(float2*)&C[(size_t)(r0+8)*HD + gcol] =
                    make_float2(fmaxf(a[2]+b.x, 0.f)*m, fmaxf(a[3]+b.y, 0.f)*m);
            }
        }
}

// ===== one-shot weight prep: all bf16 splits + fp16 transposes ============
__global__ void prep_all(const float* __restrict__ W_z, const float* __restrict__ W_h,
                         const float* __restrict__ W_r, const float* __restrict__ U_r,
                         const float* __restrict__ W_o,
                         __nv_bfloat16* __restrict__ bh, __nv_bfloat16* __restrict__ bl,
                         __half* __restrict__ wz16, __half* __restrict__ wh16)
{
    int b = blockIdx.x, t = threadIdx.x;
    if (b < 512) {
        int job = b >> 7;
        int i = ((b & 127) << 8) + t;
        const float* W = (job == 0) ? W_z : (job == 1) ? W_h : (job == 2) ? W_r : W_o;
        int off = (job == 0) ? OFF_WZT : (job == 1) ? OFF_WHT : (job == 2) ? OFF_WR : OFF_WOT;
        int k = i & 127, n = i >> 7;
        float x = W[(size_t)k*HD + n];
        __nv_bfloat16 h = __float2bfloat16_rn(x);
        bh[off + i] = h;
        bl[off + i] = __float2bfloat16_rn(x - __bfloat162float(h));
    } else if (b < 1024) {
        int job = (b - 512) >> 8;
        int i = (((b - 512) & 255) << 8) + t;
        const float* W = (job == 0) ? U_r : (W_o + (size_t)IND*HD);
        int off = (job == 0) ? OFF_UR : OFF_WOB;
        int k = i & 255, n = i >> 8;
        float x = W[(size_t)k*HD + n];
        __nv_bfloat16 h = __float2bfloat16_rn(x);
        bh[off + i] = h;
        bl[off + i] = __float2bfloat16_rn(x - __bfloat162float(h));
    } else {
        int job = (b - 1024) >> 8;
        int i = (((b - 1024) & 255) << 8) + t;
        const float* W = ((job == 0) ? W_z : W_h) + (size_t)IND*HD;
        __half* o = (job == 0) ? wz16 : wh16;
        int k = i & 255, n = i >> 8;
        o[i] = __float2half_rn(W[(size_t)k*HD + n]);
    }
}

// ===== gather: packed fp16 compute, MUFU.TANH gates, dual partial accum ===
__global__ void gather_msgs(const __half* __restrict__ h16, const __half* __restrict__ hU,
                            const __half* __restrict__ rx, const int* __restrict__ bg,
                            __half* __restrict__ sumh, __half* __restrict__ sumg)
{
    __shared__ int s_nb[4][NBR];
    int e = blockIdx.x * 4 + threadIdx.y;
    if (threadIdx.x < NBR) s_nb[threadIdx.y][threadIdx.x] = bg[e*NBR + threadIdx.x];
    __syncthreads();
    int c = threadIdx.x << 2;
    size_t base = (size_t)e*HD + c;
    uint2 rx4 = *(const uint2*)(rx + base);
    __half2 r0 = *(__half2*)&rx4.x, r1 = *(__half2*)&rx4.y;

    const __half2 zero = __half2half2(__float2half_rn(0.f));
    __half2 shA0 = zero, shA1 = zero, shB0 = zero, shB1 = zero;
    __half2 sgA0 = zero, sgA1 = zero, sgB0 = zero, sgB1 = zero;

    #pragma unroll
    for (int j = 0; j < NBR; ++j) {
        size_t nb = (size_t)s_nb[threadIdx.y][j]*HD + c;
        uint2 hq = *(const uint2*)(h16 + nb);
        uint2 uq = *(const uint2*)(hU + nb);
        __half2 h0 = *(__half2*)&hq.x, h1 = *(__half2*)&hq.y;
        __half2 u0 = *(__half2*)&uq.x, u1 = *(__half2*)&uq.y;
        __half2 z0 = sigm2(__hadd2(r0, u0));
        __half2 z1 = sigm2(__hadd2(r1, u1));
        if (j < 3) {
            shA0 = __hadd2(shA0, h0);  shA1 = __hadd2(shA1, h1);
            sgA0 = __hfma2(z0, h0, sgA0);  sgA1 = __hfma2(z1, h1, sgA1);
        } else {
            shB0 = __hadd2(shB0, h0);  shB1 = __hadd2(shB1, h1);
            sgB0 = __hfma2(z0, h0, sgB0);  sgB1 = __hfma2(z1, h1, sgB1);
        }
    }
    __half2 sh0 = __hadd2(shA0, shB0), sh1 = __hadd2(shA1, shB1);
    __half2 sg0 = __hadd2(sgA0, sgB0), sg1 = __hadd2(sgA1, sgB1);
    *(uint2*)(sumh + base) = make_uint2(h2u(sh0), h2u(sh1));
    *(uint2*)(sumg + base) = make_uint2(h2u(sg0), h2u(sg1));
}

__global__ void gather_nodes(const float* __restrict__ h, const int* __restrict__ ag,
                             float* __restrict__ nei)
{
    __shared__ int s_nb[4][NBR];
    int v = blockIdx.x * 4 + threadIdx.y;
    if (threadIdx.x < NBR) s_nb[threadIdx.y][threadIdx.x] = ag[v*NBR + threadIdx.x];
    __syncthreads();
    int c = threadIdx.x << 2;
    float4 s = make_float4(0.f,0.f,0.f,0.f);
    #pragma unroll
    for (int j = 0; j < NBR; ++j) {
        size_t nb = (size_t)s_nb[threadIdx.y][j]*HD + c;
        float4 hv = *(const float4*)&h[nb];
        s.x += hv.x; s.y += hv.y; s.z += hv.z; s.w += hv.w;
    }
    *(float4*)&nei[(size_t)v*HD + c] = s;
}

extern "C" void kernel_launch(void* const* d_in, const int* in_sizes, int n_in,
                              void* d_out, int out_size)
{
    const float* fnode  = (const float*)d_in[0];
    const float* fmess  = (const float*)d_in[1];
    const int*   agraph = (const int*)  d_in[2];
    const int*   bgraph = (const int*)  d_in[3];
    const float* mask   = (const float*)d_in[4];
    const float* W_z    = (const float*)d_in[5];
    const float* b_z    = (const float*)d_in[6];
    const float* W_r    = (const float*)d_in[7];
    const float* U_r    = (const float*)d_in[8];
    const float* b_ur   = (const float*)d_in[9];
    const float* W_h    = (const float*)d_in[10];
    const float* b_h    = (const float*)d_in[11];
    const float* W_o    = (const float*)d_in[12];
    const float* b_o    = (const float*)d_in[13];

    float* out_node = (float*)d_out;
    float* out_h    = out_node + (size_t)NN*HD;

    float *nei;
    __half *h16, *fz16, *fh16, *sumh16, *sumg16, *hU16, *rx16, *wz16, *wh16;
    __nv_bfloat16 *bh, *bl;
    cudaGetSymbolAddress((void**)&nei,    g_nei);
    cudaGetSymbolAddress((void**)&h16,    g_h16);
    cudaGetSymbolAddress((void**)&fz16,   g_fz16);
    cudaGetSymbolAddress((void**)&fh16,   g_fh16);
    cudaGetSymbolAddress((void**)&sumh16, g_sumh16);
    cudaGetSymbolAddress((void**)&sumg16, g_sumg16);
    cudaGetSymbolAddress((void**)&hU16,   g_hU16);
    cudaGetSymbolAddress((void**)&rx16,   g_rx16);
    cudaGetSymbolAddress((void**)&wz16,   g_wz16);
    cudaGetSymbolAddress((void**)&wh16,   g_wh16);
    cudaGetSymbolAddress((void**)&bh,     g_bh);
    cudaGetSymbolAddress((void**)&bl,     g_bl);

    cudaFuncSetAttribute((const void*)inv3_gemm,
                         cudaFuncAttributeMaxDynamicSharedMemorySize, SMEM_I3);
    cudaFuncSetAttribute((const void*)hU_gemm,
                         cudaFuncAttributeMaxDynamicSharedMemorySize, SMEM_HU);
    cudaFuncSetAttribute((const void*)mode1f,
                         cudaFuncAttributeMaxDynamicSharedMemorySize, SMEM_M1F);
    cudaFuncSetAttribute((const void*)mode2_gemm,
                         cudaFuncAttributeMaxDynamicSharedMemorySize, SMEM_M0);

    const int gE128 = NM / 128;               // 625
    const int gE64  = NM / 64;                // 1250
    const int gV    = NNP / 128;              // 274

    // launch 1: all weight preps in one kernel
    prep_all<<<1536, 256>>>(W_z, W_h, W_r, U_r, W_o, bh, bl, wz16, wh16);

    // launch 2: fused invariants (fz16, fh16, h16 step-1, rx16)
    inv3_gemm<<<gE128, 512, SMEM_I3>>>(fmess,
        bh+OFF_WZT, bl+OFF_WZT, bh+OFF_WHT, bl+OFF_WHT, bh+OFF_WR, bl+OFF_WR,
        b_z, b_h, b_ur, fz16, fh16, h16, rx16);

    // launches 3..14: 4 GRU steps
    for (int d = 1; d < DEPTH; ++d) {
        hU_gemm<<<gE128, 512, SMEM_HU>>>(h16, bh+OFF_UR, hU16);
        gather_msgs<<<NM/4, dim3(64,4)>>>(h16, hU16, rx16, bgraph, sumh16, sumg16);
        mode1f<<<gE64, 512, SMEM_M1F>>>(sumh16, wz16, sumg16, wh16,
                                        fz16, fh16, out_h, h16, (d == DEPTH-1) ? 1 : 0);
    }

    gather_nodes<<<NN/4, dim3(64,4)>>>(out_h, agraph, nei);
    mode2_gemm<<<gV, 512, SMEM_M0>>>(fnode, IND, bh+OFF_WOT, bl+OFF_WOT,
                                     nei, HD, bh+OFF_WOB, bl+OFF_WOB,
                                     NN, b_o, mask, out_node);
}

// round 17
// speedup vs baseline: 1.8331x; 1.0288x over previous
#include <cuda_runtime.h>
#include <cuda_bf16.h>
#include <cuda_fp16.h>
#include <math.h>
#include <cstdint>

#define NN 35000
#define NM 80000
#define NBR 6
#define IND 128
#define HD 256
#define DEPTH 5
#define NNP 35072

// ---------------- scratch (__device__ globals; no allocs) ----------------
__device__ float g_nei [(size_t)NNP*HD];
__device__ __align__(16) __half g_h16  [(size_t)NM*HD];
__device__ __align__(16) __half g_fz16 [(size_t)NM*HD];
__device__ __align__(16) __half g_fh16 [(size_t)NM*HD];
__device__ __align__(16) __half g_sumh16[(size_t)NM*HD];
__device__ __align__(16) __half g_sumg16[(size_t)NM*HD];
__device__ __align__(16) __half g_hU16[(size_t)NM*HD];
__device__ __align__(16) __half g_rx16[(size_t)NM*HD];
__device__ __align__(16) __half g_wz16[65536];
__device__ __align__(16) __half g_wh16[65536];
__device__ __align__(16) __half g_ur16[65536];

#define OFF_WZT 0
#define OFF_WHT 32768
#define OFF_WR  65536
#define OFF_WOT 98304
#define OFF_WOB 131072
__device__ __align__(16) __nv_bfloat16 g_bh[196608];
__device__ __align__(16) __nv_bfloat16 g_bl[196608];

// fast fp32 sigmoid (epilogues): 2 MUFU + ~3 ALU
__device__ __forceinline__ float sigm(float x){
    return __fdividef(1.0f, 1.0f + __expf(-x));
}
// packed fp16 sigmoid via MUFU.TANH.F16x2: sig(x) = 0.5*tanh(x/2) + 0.5
__device__ __forceinline__ __half2 sigm2(__half2 x){
    const __half2 h05 = __half2half2(__float2half_rn(0.5f));
    __half2 t = __hmul2(x, h05);
    uint32_t r;
    asm("tanh.approx.f16x2 %0, %1;" : "=r"(r) : "r"(*(uint32_t*)&t));
    return __hfma2(*(__half2*)&r, h05, h05);
}

// ---------------- mma / ldmatrix / cp.async helpers ----------------------
__device__ __forceinline__ uint32_t smem_addr(const void* p){
    return (uint32_t)__cvta_generic_to_shared(p);
}
__device__ __forceinline__ void ldsm4(uint32_t a, uint32_t& r0, uint32_t& r1,
                                      uint32_t& r2, uint32_t& r3){
    asm volatile("ldmatrix.sync.aligned.m8n8.x4.shared.b16 {%0,%1,%2,%3}, [%4];"
                 : "=r"(r0), "=r"(r1), "=r"(r2), "=r"(r3) : "r"(a));
}
__device__ __forceinline__ void mma16816(float* c, const uint32_t* a, const uint32_t* b){
    asm volatile(
        "mma.sync.aligned.m16n8k16.row.col.f32.bf16.bf16.f32 "
        "{%0,%1,%2,%3}, {%4,%5,%6,%7}, {%8,%9}, {%0,%1,%2,%3};"
        : "+f"(c[0]), "+f"(c[1]), "+f"(c[2]), "+f"(c[3])
        : "r"(a[0]), "r"(a[1]), "r"(a[2]), "r"(a[3]), "r"(b[0]), "r"(b[1]));
}
__device__ __forceinline__ void mma16816h(float* c, const uint32_t* a, const uint32_t* b){
    asm volatile(
        "mma.sync.aligned.m16n8k16.row.col.f32.f16.f16.f32 "
        "{%0,%1,%2,%3}, {%4,%5,%6,%7}, {%8,%9}, {%0,%1,%2,%3};"
        : "+f"(c[0]), "+f"(c[1]), "+f"(c[2]), "+f"(c[3])
        : "r"(a[0]), "r"(a[1]), "r"(a[2]), "r"(a[3]), "r"(b[0]), "r"(b[1]));
}
#define CPA16(dst, src) \
    asm volatile("cp.async.cg.shared.global [%0], [%1], 16;" :: "r"(dst), "l"(src))
#define CP_COMMIT() asm volatile("cp.async.commit_group;" ::: "memory")
#define CP_WAIT0()  asm volatile("cp.async.wait_group 0;" ::: "memory")
#define CP_WAIT1()  asm volatile("cp.async.wait_group 1;" ::: "memory")

__device__ __forceinline__ void cvt_split8(float4 v0, float4 v1, uint4& hi, uint4& lo){
    float f[8] = {v0.x,v0.y,v0.z,v0.w,v1.x,v1.y,v1.z,v1.w};
    uint32_t hh[8], ll[8];
    #pragma unroll
    for (int j = 0; j < 8; ++j) {
        __nv_bfloat16 h = __float2bfloat16_rn(f[j]);
        float hf = __bfloat162float(h);
        __nv_bfloat16 l = __float2bfloat16_rn(f[j] - hf);
        hh[j] = (uint32_t)__bfloat16_as_ushort(h);
        ll[j] = (uint32_t)__bfloat16_as_ushort(l);
    }
    hi = make_uint4(hh[0]|(hh[1]<<16), hh[2]|(hh[3]<<16), hh[4]|(hh[5]<<16), hh[6]|(hh[7]<<16));
    lo = make_uint4(ll[0]|(ll[1]<<16), ll[2]|(ll[3]<<16), ll[4]|(ll[5]<<16), ll[6]|(ll[7]<<16));
}
__device__ __forceinline__ uint32_t h2u(__half2 v){ return *(uint32_t*)&v; }

#define PADK 40

// ================= 3-pass bf16 phase (mode2 only) =========================
template<int MT, int NA>
__device__ __forceinline__ void run_phase(
    const float* __restrict__ A1, const float* __restrict__ A2, int K,
    const __nv_bfloat16* __restrict__ B1h, const __nv_bfloat16* __restrict__ B1l,
    const __nv_bfloat16* __restrict__ B2h, const __nv_bfloat16* __restrict__ B2l,
    float* acc, char* sm, int tid, int rowBase, int M)
{
    constexpr int WM = MT/32;
    constexpr int WN = 16/WM;
    constexpr int NSPAN = 256/WN;
    constexpr int NFR = NSPAN/8;
    constexpr uint32_t APL = MT*80u;
    constexpr uint32_t A_BYTES = NA*2u*APL;
    constexpr uint32_t BPL = 20480u;
    constexpr uint32_t STAGE_ = A_BYTES + NA*2u*BPL;
    constexpr int NB = NA*4;
    const int lane = tid & 31, wid = tid >> 5;
    const int wm = wid / WN, wn = wid % WN;
    const int g = lane >> 3, r = lane & 7;
    const uint32_t sb = smem_addr(sm);
    const int nch = K >> 5;

    const int a_op  = tid / (MT*4);
    const int a_rem = tid % (MT*4);
    const int a_row = a_rem >> 2, a_seg = a_rem & 3;
    const int grow = rowBase + a_row;
    const bool a_ok = (grow < M);
    const float* a_src = ((a_op == 0) ? A1 : A2) + (size_t)grow*K + (a_seg << 3);
    const uint32_t a_off = (uint32_t)a_op*2u*APL + (uint32_t)a_row*80u + (uint32_t)a_seg*16u;

    auto issue_B = [&](uint32_t st, int c){
        #pragma unroll
        for (int i = 0; i < NB; ++i){
            int idx = tid + (i << 9);
            int op = idx >> 11;
            int rem = idx & 2047;
            int plane = rem >> 10;
            int rem2 = rem & 1023;
            int row = rem2 >> 2, seg = rem2 & 3;
            const __nv_bfloat16* Bp = (op == 0) ? (plane ? B1l : B1h)
                                                : (plane ? B2l : B2h);
            const __nv_bfloat16* src = Bp + (size_t)row*K + (c << 5) + (seg << 3);
            uint32_t dst = st + A_BYTES + (uint32_t)op*(2u*BPL) + (uint32_t)plane*BPL
                         + (uint32_t)row*80u + (uint32_t)seg*16u;
            CPA16(dst, src);
        }
        CP_COMMIT();
    };

    {
        float4 v0 = make_float4(0.f,0.f,0.f,0.f), v1 = v0;
        if (a_ok){ v0 = *(const float4*)a_src; v1 = *(const float4*)(a_src + 4); }
        issue_B(sb, 0);
        uint4 hi, lo; cvt_split8(v0, v1, hi, lo);
        *(uint4*)(sm + a_off)       = hi;
        *(uint4*)(sm + a_off + APL) = lo;
        CP_WAIT0();
    }
    __syncthreads();

    for (int c = 0; c < nch; ++c){
        const uint32_t st = sb + (c & 1)*STAGE_;
        const int nc = c + 1;
        float4 v0, v1;
        if (nc < nch){
            v0 = make_float4(0.f,0.f,0.f,0.f); v1 = v0;
            if (a_ok){
                const float* p = a_src + (nc << 5);
                v0 = *(const float4*)p; v1 = *(const float4*)(p + 4);
            }
            issue_B(sb + (nc & 1)*STAGE_, nc);
        }

        #pragma unroll
        for (int op = 0; op < NA; ++op){
            const uint32_t aBase = st + (uint32_t)op*2u*APL;
            const uint32_t bBase = st + A_BYTES + (uint32_t)op*(2u*BPL);
            #pragma unroll
            for (int ki = 0; ki < 2; ++ki){
                uint32_t ah[2][4], al[2][4];
                {
                    int arow = wm*32 + (g & 1)*8 + r;
                    uint32_t off = (uint32_t)(arow*PADK + ki*16 + (g >> 1)*8) * 2;
                    ldsm4(aBase + off,                   ah[0][0], ah[0][1], ah[0][2], ah[0][3]);
                    ldsm4(aBase + off + 16*PADK*2,       ah[1][0], ah[1][1], ah[1][2], ah[1][3]);
                    ldsm4(aBase + APL + off,             al[0][0], al[0][1], al[0][2], al[0][3]);
                    ldsm4(aBase + APL + off + 16*PADK*2, al[1][0], al[1][1], al[1][2], al[1][3]);
                }
                #pragma unroll
                for (int ng = 0; ng < NFR/4; ++ng){
                    uint32_t bhf[4][2], blf[4][2];
                    int nrow = wn*NSPAN + ng*32 + (g >> 1)*8 + r;
                    uint32_t off = (uint32_t)(nrow*PADK + ki*16 + (g & 1)*8) * 2;
                    ldsm4(bBase + off,                 bhf[0][0], bhf[0][1], bhf[1][0], bhf[1][1]);
                    ldsm4(bBase + off + 16*PADK*2,     bhf[2][0], bhf[2][1], bhf[3][0], bhf[3][1]);
                    ldsm4(bBase + BPL + off,             blf[0][0], blf[0][1], blf[1][0], blf[1][1]);
                    ldsm4(bBase + BPL + off + 16*PADK*2, blf[2][0], blf[2][1], blf[3][0], blf[3][1]);
                    #pragma unroll
                    for (int mi = 0; mi < 2; ++mi)
                        #pragma unroll
                        for (int j = 0; j < 4; ++j){
                            float* a = acc + (((op*2 + mi)*NFR) + ng*4 + j)*4;
                            mma16816(a, ah[mi], bhf[j]);
                            mma16816(a, ah[mi], blf[j]);
                            mma16816(a, al[mi], bhf[j]);
                        }
                }
            }
        }

        if (nc < nch){
            char* nsm = sm + (nc & 1)*STAGE_;
            uint4 hi, lo; cvt_split8(v0, v1, hi, lo);
            *(uint4*)(nsm + a_off)       = hi;
            *(uint4*)(nsm + a_off + APL) = lo;
            CP_WAIT0();
        }
        __syncthreads();
    }
}

#define SMEM_M0   (2*(2*128*80 + 2*20480))   // 122880
#define SMEM_I3   (4*20480 + 2*40960)        // 163840
#define SMEM_M1F  (3*(2*64*80 + 2*20480))    // 153600
#define SMEM_HU16 (3*(128*80 + 20480))       // 92160

// ================= fp16 single-pass GEMM for hU (pure cp.async) ==========
// hU = h16 @ U_r16^T ; MT=128, NT=256, 3-stage pipeline, fp16 MMA.
__global__ __launch_bounds__(512, 1)
void hU_gemm(const __half* __restrict__ A, const __half* __restrict__ B,
             __half* __restrict__ Cout)
{
    constexpr int K = HD;                        // 8 chunks
    constexpr uint32_t APL = 10240u;             // 128*80
    constexpr uint32_t BPL = 20480u;             // 256*80
    constexpr uint32_t STG = APL + BPL;          // 30720
    extern __shared__ char sm[];
    const int tid = threadIdx.x;
    const int rowBase = (int)blockIdx.x << 7;
    const int lane = tid & 31, wid = tid >> 5;
    const int wm = wid >> 2, wn = wid & 3;
    const int g = lane >> 3, r = lane & 7;
    const int tq = lane >> 2, tr = lane & 3;
    const uint32_t sb = smem_addr(sm);

    // A fill: 128 rows x 4 segs = 512 units (1/thread)
    const int a_row = tid >> 2, a_seg = tid & 3;
    const __half* a_src = A + (size_t)(rowBase + a_row)*K + (a_seg << 3);
    const uint32_t a_dst = (uint32_t)a_row*80u + (uint32_t)a_seg*16u;

    auto issue = [&](uint32_t st, int c){
        CPA16(st + a_dst, a_src + (c << 5));
        #pragma unroll
        for (int i = 0; i < 2; ++i){
            int idx = tid + (i << 9);
            int row = idx >> 2, seg = idx & 3;
            CPA16(st + APL + (uint32_t)row*80u + (uint32_t)seg*16u,
                  B + (size_t)row*K + (c << 5) + (seg << 3));
        }
        CP_COMMIT();
    };

    float acc[64];
    #pragma unroll
    for (int i = 0; i < 64; ++i) acc[i] = 0.f;

    issue(sb, 0);
    issue(sb + STG, 1);

    for (int c = 0; c < 8; ++c){
        if (c + 1 < 8) { CP_WAIT1(); } else { CP_WAIT0(); }
        __syncthreads();
        if (c + 2 < 8) issue(sb + ((c+2)%3)*STG, c+2);
        const uint32_t st = sb + (c%3)*STG;

        #pragma unroll
        for (int ki = 0; ki < 2; ++ki){
            uint32_t ah[2][4];
            {
                int arow = wm*32 + (g & 1)*8 + r;
                uint32_t off = (uint32_t)(arow*PADK + ki*16 + (g >> 1)*8) * 2;
                ldsm4(st + off,             ah[0][0], ah[0][1], ah[0][2], ah[0][3]);
                ldsm4(st + off + 16*PADK*2, ah[1][0], ah[1][1], ah[1][2], ah[1][3]);
            }
            #pragma unroll
            for (int ng = 0; ng < 2; ++ng){
                uint32_t bf[4][2];
                int nrow = wn*64 + ng*32 + (g >> 1)*8 + r;
                uint32_t off = (uint32_t)(nrow*PADK + ki*16 + (g & 1)*8) * 2;
                ldsm4(st + APL + off,             bf[0][0], bf[0][1], bf[1][0], bf[1][1]);
                ldsm4(st + APL + off + 16*PADK*2, bf[2][0], bf[2][1], bf[3][0], bf[3][1]);
                #pragma unroll
                for (int mi = 0; mi < 2; ++mi)
                    #pragma unroll
                    for (int j = 0; j < 4; ++j)
                        mma16816h(acc + ((mi*8) + ng*4 + j)*4, ah[mi], bf[j]);
            }
        }
    }

    #pragma unroll
    for (int mi = 0; mi < 2; ++mi)
        #pragma unroll
        for (int ni = 0; ni < 8; ++ni){
            const float* a = acc + (mi*8 + ni)*4;
            int gcol = wn*64 + ni*8 + tr*2;
            int r0 = rowBase + wm*32 + mi*16 + tq;
            *(__half2*)&Cout[(size_t)r0*HD + gcol]     = __floats2half2_rn(a[0], a[1]);
            *(__half2*)&Cout[(size_t)(r0+8)*HD + gcol] = __floats2half2_rn(a[2], a[3]);
        }
}

// ================= fused invariants: fz16, fh16(+h16), rx16 ==============
__global__ __launch_bounds__(512, 1)
void inv3_gemm(const float* __restrict__ A,
               const __nv_bfloat16* __restrict__ Wzh, const __nv_bfloat16* __restrict__ Wzl,
               const __nv_bfloat16* __restrict__ Whh, const __nv_bfloat16* __restrict__ Whl,
               const __nv_bfloat16* __restrict__ Wrh, const __nv_bfloat16* __restrict__ Wrl,
               const float* __restrict__ b_z, const float* __restrict__ b_h,
               const float* __restrict__ b_ur,
               __half* __restrict__ fz, __half* __restrict__ fh,
               __half* __restrict__ h16, __half* __restrict__ rx)
{
    constexpr int K = IND;
    constexpr uint32_t B_OFF = 81920u;
    constexpr uint32_t BPL = 20480u, BSTG = 40960u;
    extern __shared__ char sm[];
    const int tid = threadIdx.x;
    const int rowBase = (int)blockIdx.x << 7;
    const int lane = tid & 31, wid = tid >> 5;
    const int wm = wid >> 2, wn = wid & 3;
    const int g = lane >> 3, r = lane & 7;
    const int tq = lane >> 2, tr = lane & 3;
    const uint32_t sb = smem_addr(sm);

    #pragma unroll
    for (int u = 0; u < 4; ++u){
        int idx = tid + (u << 9);
        int row = idx >> 4, gi = idx & 15;
        int t = gi >> 2, seg = gi & 3;
        const float* p = A + (size_t)(rowBase + row)*K + (gi << 3);
        float4 v0 = *(const float4*)p, v1 = *(const float4*)(p + 4);
        uint4 hi, lo; cvt_split8(v0, v1, hi, lo);
        uint32_t off = (uint32_t)t*20480u + (uint32_t)row*80u + (uint32_t)seg*16u;
        *(uint4*)(sm + off)          = hi;
        *(uint4*)(sm + off + 10240u) = lo;
    }
    __syncthreads();

    const __nv_bfloat16* Bhs[3] = {Wzh, Whh, Wrh};
    const __nv_bfloat16* Bls[3] = {Wzl, Whl, Wrl};
    const float* biases[3] = {b_z, b_h, b_ur};

    #pragma unroll
    for (int op = 0; op < 3; ++op){
        const __nv_bfloat16* Bh = Bhs[op];
        const __nv_bfloat16* Bl = Bls[op];

        auto issue_B = [&](uint32_t st, int c){
            #pragma unroll
            for (int i = 0; i < 4; ++i){
                int idx = tid + (i << 9);
                int plane = idx >> 10;
                int rem = idx & 1023;
                int row = rem >> 2, seg = rem & 3;
                const __nv_bfloat16* src = (plane ? Bl : Bh)
                    + (size_t)row*K + (c << 5) + (seg << 3);
                CPA16(st + (uint32_t)plane*BPL + (uint32_t)row*80u + (uint32_t)seg*16u, src);
            }
            CP_COMMIT();
        };

        float acc[64];
        #pragma unroll
        for (int i = 0; i < 64; ++i) acc[i] = 0.f;

        issue_B(sb + B_OFF, 0);
        CP_WAIT0();
        __syncthreads();

        for (int c = 0; c < 4; ++c){
            const uint32_t aBase = sb + (uint32_t)c*20480u;
            const uint32_t bBase = sb + B_OFF + (uint32_t)(c & 1)*BSTG;
            if (c + 1 < 4) issue_B(sb + B_OFF + (uint32_t)((c+1) & 1)*BSTG, c+1);

            #pragma unroll
            for (int ki = 0; ki < 2; ++ki){
                uint32_t ah[2][4], al[2][4];
                {
                    int arow = wm*32 + (g & 1)*8 + r;
                    uint32_t off = (uint32_t)(arow*PADK + ki*16 + (g >> 1)*8) * 2;
                    ldsm4(aBase + off,                  ah[0][0], ah[0][1], ah[0][2], ah[0][3]);
                    ldsm4(aBase + off + 16*PADK*2,      ah[1][0], ah[1][1], ah[1][2], ah[1][3]);
                    ldsm4(aBase + 10240u + off,             al[0][0], al[0][1], al[0][2], al[0][3]);
                    ldsm4(aBase + 10240u + off + 16*PADK*2, al[1][0], al[1][1], al[1][2], al[1][3]);
                }
                #pragma unroll
                for (int ng = 0; ng < 2; ++ng){
                    uint32_t bhf[4][2], blf[4][2];
                    int nrow = wn*64 + ng*32 + (g >> 1)*8 + r;
                    uint32_t off = (uint32_t)(nrow*PADK + ki*16 + (g & 1)*8) * 2;
                    ldsm4(bBase + off,                 bhf[0][0], bhf[0][1], bhf[1][0], bhf[1][1]);
                    ldsm4(bBase + off + 16*PADK*2,     bhf[2][0], bhf[2][1], bhf[3][0], bhf[3][1]);
                    ldsm4(bBase + BPL + off,             blf[0][0], blf[0][1], blf[1][0], blf[1][1]);
                    ldsm4(bBase + BPL + off + 16*PADK*2, blf[2][0], blf[2][1], blf[3][0], blf[3][1]);
                    #pragma unroll
                    for (int mi = 0; mi < 2; ++mi)
                        #pragma unroll
                        for (int j = 0; j < 4; ++j){
                            float* a = acc + ((mi*8) + ng*4 + j)*4;
                            mma16816(a, ah[mi], bhf[j]);
                            mma16816(a, ah[mi], blf[j]);
                            mma16816(a, al[mi], bhf[j]);
                        }
                }
            }
            if (c + 1 < 4) CP_WAIT0();
            __syncthreads();
        }

        #pragma unroll
        for (int mi = 0; mi < 2; ++mi)
            #pragma unroll
            for (int ni = 0; ni < 8; ++ni){
                const float* a = acc + (mi*8 + ni)*4;
                int gcol = wn*64 + ni*8 + tr*2;
                int r0 = rowBase + wm*32 + mi*16 + tq;
                float2 b = *(const float2*)&biases[op][gcol];
                size_t o0 = (size_t)r0*HD + gcol;
                size_t o1 = (size_t)(r0+8)*HD + gcol;
                float2 u0 = make_float2(a[0]+b.x, a[1]+b.y);
                float2 u1 = make_float2(a[2]+b.x, a[3]+b.y);
                if (op == 0) {
                    *(__half2*)&fz[o0] = __floats2half2_rn(u0.x, u0.y);
                    *(__half2*)&fz[o1] = __floats2half2_rn(u1.x, u1.y);
                } else if (op == 1) {
                    *(__half2*)&fh[o0] = __floats2half2_rn(u0.x, u0.y);
                    *(__half2*)&fh[o1] = __floats2half2_rn(u1.x, u1.y);
                    float2 z0 = __half22float2(*(const __half2*)&fz[o0]);
                    float2 z1 = __half22float2(*(const __half2*)&fz[o1]);
                    float2 w0 = make_float2(sigm(z0.x)*tanhf(u0.x), sigm(z0.y)*tanhf(u0.y));
                    float2 w1 = make_float2(sigm(z1.x)*tanhf(u1.x), sigm(z1.y)*tanhf(u1.y));
                    if (r0 == 0) w0 = make_float2(0.f, 0.f);   // null message row
                    *(__half2*)&h16[o0] = __floats2half2_rn(w0.x, w0.y);
                    *(__half2*)&h16[o1] = __floats2half2_rn(w1.x, w1.y);
                } else {
                    *(__half2*)&rx[o0] = __floats2half2_rn(u0.x, u0.y);
                    *(__half2*)&rx[o1] = __floats2half2_rn(u1.x, u1.y);
                }
            }
    }
}

// ================= fp16 single-pass GRU-step dual GEMM ====================
// wr32 != 0: write fp32 C only (final step). wr32 == 0: write fp16 C16 only.
__global__ __launch_bounds__(512, 1)
void mode1f(const __half* __restrict__ A1, const __half* __restrict__ B1,
            const __half* __restrict__ A2, const __half* __restrict__ B2,
            const __half* __restrict__ fz, const __half* __restrict__ fh,
            float* __restrict__ C, __half* __restrict__ C16, int wr32)
{
    constexpr int K = HD;
    constexpr uint32_t APL = 5120u, ABYTES = 10240u;
    constexpr uint32_t BPL = 20480u, STG = 51200u;
    extern __shared__ char sm[];
    const int tid = threadIdx.x;
    const int rowBase = (int)blockIdx.x << 6;      // MT=64
    const int lane = tid & 31, wid = tid >> 5;
    const int wm = wid >> 3, wn = wid & 7;         // 2 x 8 warps
    const int g = lane >> 3, r = lane & 7;
    const int tq = lane >> 2, tr = lane & 3;
    const uint32_t sb = smem_addr(sm);

    const int a_op = tid >> 8, a_rem = tid & 255;
    const int a_row = a_rem >> 2, a_seg = a_rem & 3;
    const __half* a_src = ((a_op == 0) ? A1 : A2)
        + (size_t)(rowBase + a_row)*K + (a_seg << 3);
    const uint32_t a_dst = (uint32_t)a_op*APL + (uint32_t)a_row*80u + (uint32_t)a_seg*16u;

    auto issue = [&](uint32_t st, int c){
        CPA16(st + a_dst, a_src + (c << 5));
        #pragma unroll
        for (int i = 0; i < 4; ++i){
            int idx = tid + (i << 9);
            int op = idx >> 10;
            int rem = idx & 1023;
            int row = rem >> 2, seg = rem & 3;
            const __half* src = ((op == 0) ? B1 : B2)
                + (size_t)row*K + (c << 5) + (seg << 3);
            CPA16(st + ABYTES + (uint32_t)op*BPL + (uint32_t)row*80u + (uint32_t)seg*16u, src);
        }
        CP_COMMIT();
    };

    float acc[64];
    #pragma unroll
    for (int i = 0; i < 64; ++i) acc[i] = 0.f;

    issue(sb, 0);
    issue(sb + STG, 1);

    for (int c = 0; c < 8; ++c){
        if (c + 1 < 8) { CP_WAIT1(); } else { CP_WAIT0(); }
        __syncthreads();
        if (c + 2 < 8) issue(sb + ((c+2)%3)*STG, c+2);
        const uint32_t st = sb + (c%3)*STG;

        #pragma unroll
        for (int op = 0; op < 2; ++op){
            const uint32_t aBase = st + (uint32_t)op*APL;
            const uint32_t bBase = st + ABYTES + (uint32_t)op*BPL;
            #pragma unroll
            for (int ki = 0; ki < 2; ++ki){
                uint32_t ah[2][4];
                {
                    int arow = wm*32 + (g & 1)*8 + r;
                    uint32_t off = (uint32_t)(arow*PADK + ki*16 + (g >> 1)*8) * 2;
                    ldsm4(aBase + off,             ah[0][0], ah[0][1], ah[0][2], ah[0][3]);
                    ldsm4(aBase + off + 16*PADK*2, ah[1][0], ah[1][1], ah[1][2], ah[1][3]);
                }
                uint32_t bf[4][2];
                {
                    int nrow = wn*32 + (g >> 1)*8 + r;
                    uint32_t off = (uint32_t)(nrow*PADK + ki*16 + (g & 1)*8) * 2;
                    ldsm4(bBase + off,             bf[0][0], bf[0][1], bf[1][0], bf[1][1]);
                    ldsm4(bBase + off + 16*PADK*2, bf[2][0], bf[2][1], bf[3][0], bf[3][1]);
                }
                #pragma unroll
                for (int mi = 0; mi < 2; ++mi)
                    #pragma unroll
                    for (int j = 0; j < 4; ++j)
                        mma16816h(acc + ((op*2 + mi)*4 + j)*4, ah[mi], bf[j]);
            }
        }
    }

    #pragma unroll
    for (int mi = 0; mi < 2; ++mi)
        #pragma unroll
        for (int ni = 0; ni < 4; ++ni){
            const float* a1 = acc + ((0*2 + mi)*4 + ni)*4;
            const float* a2 = acc + ((1*2 + mi)*4 + ni)*4;
            int gcol = wn*32 + ni*8 + tr*2;
            int r0 = rowBase + wm*32 + mi*16 + tq;
            size_t o0 = (size_t)r0*HD + gcol;
            size_t o1 = (size_t)(r0+8)*HD + gcol;
            float2 za = __half22float2(*(const __half2*)&fz[o0]);
            float2 zb = __half22float2(*(const __half2*)&fz[o1]);
            float2 ha = __half22float2(*(const __half2*)&fh[o0]);
            float2 hb = __half22float2(*(const __half2*)&fh[o1]);
            float2 sa = __half22float2(*(const __half2*)&A1[o0]);
            float2 sb2 = __half22float2(*(const __half2*)&A1[o1]);
            float z0 = sigm(za.x + a1[0]);
            float z1 = sigm(za.y + a1[1]);
            float z2 = sigm(zb.x + a1[2]);
            float z3 = sigm(zb.y + a1[3]);
            float p0 = tanhf(ha.x + a2[0]);
            float p1 = tanhf(ha.y + a2[1]);
            float p2 = tanhf(hb.x + a2[2]);
            float p3 = tanhf(hb.y + a2[3]);
            float2 u0 = make_float2((1.f - z0)*sa.x + z0*p0, (1.f - z1)*sa.y + z1*p1);
            float2 u1 = make_float2((1.f - z2)*sb2.x + z2*p2, (1.f - z3)*sb2.y + z3*p3);
            if (r0 == 0) u0 = make_float2(0.f, 0.f);
            if (wr32) {
                *(float2*)&C[o0] = u0;
                *(float2*)&C[o1] = u1;
            } else {
                *(__half2*)&C16[o0] = __floats2half2_rn(u0.x, u0.y);
                *(__half2*)&C16[o1] = __floats2half2_rn(u1.x, u1.y);
            }
        }
}

// ================= MODE2 (output layer, bf16 3-pass) ======================
__global__ __launch_bounds__(512, 1)
void mode2_gemm(const float* __restrict__ A1, int K1,
                const __nv_bfloat16* __restrict__ B1h, const __nv_bfloat16* __restrict__ B1l,
                const float* __restrict__ A2, int K2,
                const __nv_bfloat16* __restrict__ B2h, const __nv_bfloat16* __restrict__ B2l,
                int M, const float* __restrict__ bias, const float* __restrict__ maskv,
                float* __restrict__ C)
{
    extern __shared__ char sm[];
    const int tid = threadIdx.x;
    const int rowBase = (int)blockIdx.x << 7;
    const int lane = tid & 31, wid = tid >> 5;
    const int wm = wid >> 2, wn = wid & 3;
    const int tq = lane >> 2, tr = lane & 3;

    float acc[64];
    #pragma unroll
    for (int i = 0; i < 64; ++i) acc[i] = 0.f;

    run_phase<128,1>(A1, nullptr, K1, B1h, B1l, nullptr, nullptr, acc, sm, tid, rowBase, M);
    run_phase<128,1>(A2, nullptr, K2, B2h, B2l, nullptr, nullptr, acc, sm, tid, rowBase, M);

    #pragma unroll
    for (int mi = 0; mi < 2; ++mi)
        #pragma unroll
        for (int ni = 0; ni < 8; ++ni) {
            const float* a = acc + (mi*8 + ni)*4;
            int gcol = wn*64 + ni*8 + tr*2;
            int r0 = rowBase + wm*32 + mi*16 + tq;
            float2 b = *(const float2*)&bias[gcol];
            if (r0 < M) {
                float m = maskv[r0];
                *(float2*)&C[(size_t)r0*HD + gcol] =
                    make_float2(fmaxf(a[0]+b.x, 0.f)*m, fmaxf(a[1]+b.y, 0.f)*m);
            }
            if (r0 + 8 < M) {
                float m = maskv[r0+8];
                *(float2*)&C[(size_t)(r0+8)*HD + gcol] =
                    make_float2(fmaxf(a[2]+b.x, 0.f)*m, fmaxf(a[3]+b.y, 0.f)*m);
            }
        }
}

// ===== one-shot weight prep: bf16 splits + fp16 transposes ================
__global__ void prep_all(const float* __restrict__ W_z, const float* __restrict__ W_h,
                         const float* __restrict__ W_r, const float* __restrict__ U_r,
                         const float* __restrict__ W_o,
                         __nv_bfloat16* __restrict__ bh, __nv_bfloat16* __restrict__ bl,
                         __half* __restrict__ wz16, __half* __restrict__ wh16,
                         __half* __restrict__ ur16)
{
    int b = blockIdx.x, t = threadIdx.x;
    if (b < 512) {
        // bf16 split, K=128: WZT, WHT, WR, WOT
        int job = b >> 7;
        int i = ((b & 127) << 8) + t;
        const float* W = (job == 0) ? W_z : (job == 1) ? W_h : (job == 2) ? W_r : W_o;
        int off = (job == 0) ? OFF_WZT : (job == 1) ? OFF_WHT : (job == 2) ? OFF_WR : OFF_WOT;
        int k = i & 127, n = i >> 7;
        float x = W[(size_t)k*HD + n];
        __nv_bfloat16 h = __float2bfloat16_rn(x);
        bh[off + i] = h;
        bl[off + i] = __float2bfloat16_rn(x - __bfloat162float(h));
    } else if (b < 768) {
        // bf16 split, K=256: WOB
        int i = ((b - 512) << 8) + t;
        const float* W = W_o + (size_t)IND*HD;
        int k = i & 255, n = i >> 8;
        float x = W[(size_t)k*HD + n];
        __nv_bfloat16 h = __float2bfloat16_rn(x);
        bh[OFF_WOB + i] = h;
        bl[OFF_WOB + i] = __float2bfloat16_rn(x - __bfloat162float(h));
    } else {
        // fp16 transpose, K=256: wz16, wh16, ur16
        int job = (b - 768) >> 8;
        int i = (((b - 768) & 255) << 8) + t;
        const float* W = (job == 0) ? (W_z + (size_t)IND*HD)
                       : (job == 1) ? (W_h + (size_t)IND*HD) : U_r;
        __half* o = (job == 0) ? wz16 : (job == 1) ? wh16 : ur16;
        int k = i & 255, n = i >> 8;
        o[i] = __float2half_rn(W[(size_t)k*HD + n]);
    }
}

// ===== gather: packed fp16 compute, MUFU.TANH gates, dual partial accum ===
__global__ void gather_msgs(const __half* __restrict__ h16, const __half* __restrict__ hU,
                            const __half* __restrict__ rx, const int* __restrict__ bg,
                            __half* __restrict__ sumh, __half* __restrict__ sumg)
{
    __shared__ int s_nb[4][NBR];
    int e = blockIdx.x * 4 + threadIdx.y;
    if (threadIdx.x < NBR) s_nb[threadIdx.y][threadIdx.x] = bg[e*NBR + threadIdx.x];
    __syncthreads();
    int c = threadIdx.x << 2;
    size_t base = (size_t)e*HD + c;
    uint2 rx4 = *(const uint2*)(rx + base);
    __half2 r0 = *(__half2*)&rx4.x, r1 = *(__half2*)&rx4.y;

    const __half2 zero = __half2half2(__float2half_rn(0.f));
    __half2 shA0 = zero, shA1 = zero, shB0 = zero, shB1 = zero;
    __half2 sgA0 = zero, sgA1 = zero, sgB0 = zero, sgB1 = zero;

    #pragma unroll
    for (int j = 0; j < NBR; ++j) {
        size_t nb = (size_t)s_nb[threadIdx.y][j]*HD + c;
        uint2 hq = *(const uint2*)(h16 + nb);
        uint2 uq = *(const uint2*)(hU + nb);
        __half2 h0 = *(__half2*)&hq.x, h1 = *(__half2*)&hq.y;
        __half2 u0 = *(__half2*)&uq.x, u1 = *(__half2*)&uq.y;
        __half2 z0 = sigm2(__hadd2(r0, u0));
        __half2 z1 = sigm2(__hadd2(r1, u1));
        if (j < 3) {
            shA0 = __hadd2(shA0, h0);  shA1 = __hadd2(shA1, h1);
            sgA0 = __hfma2(z0, h0, sgA0);  sgA1 = __hfma2(z1, h1, sgA1);
        } else {
            shB0 = __hadd2(shB0, h0);  shB1 = __hadd2(shB1, h1);
            sgB0 = __hfma2(z0, h0, sgB0);  sgB1 = __hfma2(z1, h1, sgB1);
        }
    }
    __half2 sh0 = __hadd2(shA0, shB0), sh1 = __hadd2(shA1, shB1);
    __half2 sg0 = __hadd2(sgA0, sgB0), sg1 = __hadd2(sgA1, sgB1);
    *(uint2*)(sumh + base) = make_uint2(h2u(sh0), h2u(sh1));
    *(uint2*)(sumg + base) = make_uint2(h2u(sg0), h2u(sg1));
}

__global__ void gather_nodes(const float* __restrict__ h, const int* __restrict__ ag,
                             float* __restrict__ nei)
{
    __shared__ int s_nb[4][NBR];
    int v = blockIdx.x * 4 + threadIdx.y;
    if (threadIdx.x < NBR) s_nb[threadIdx.y][threadIdx.x] = ag[v*NBR + threadIdx.x];
    __syncthreads();
    int c = threadIdx.x << 2;
    float4 s = make_float4(0.f,0.f,0.f,0.f);
    #pragma unroll
    for (int j = 0; j < NBR; ++j) {
        size_t nb = (size_t)s_nb[threadIdx.y][j]*HD + c;
        float4 hv = *(const float4*)&h[nb];
        s.x += hv.x; s.y += hv.y; s.z += hv.z; s.w += hv.w;
    }
    *(float4*)&nei[(size_t)v*HD + c] = s;
}

extern "C" void kernel_launch(void* const* d_in, const int* in_sizes, int n_in,
                              void* d_out, int out_size)
{
    const float* fnode  = (const float*)d_in[0];
    const float* fmess  = (const float*)d_in[1];
    const int*   agraph = (const int*)  d_in[2];
    const int*   bgraph = (const int*)  d_in[3];
    const float* mask   = (const float*)d_in[4];
    const float* W_z    = (const float*)d_in[5];
    const float* b_z    = (const float*)d_in[6];
    const float* W_r    = (const float*)d_in[7];
    const float* U_r    = (const float*)d_in[8];
    const float* b_ur   = (const float*)d_in[9];
    const float* W_h    = (const float*)d_in[10];
    const float* b_h    = (const float*)d_in[11];
    const float* W_o    = (const float*)d_in[12];
    const float* b_o    = (const float*)d_in[13];

    float* out_node = (float*)d_out;
    float* out_h    = out_node + (size_t)NN*HD;

    float *nei;
    __half *h16, *fz16, *fh16, *sumh16, *sumg16, *hU16, *rx16, *wz16, *wh16, *ur16;
    __nv_bfloat16 *bh, *bl;
    cudaGetSymbolAddress((void**)&nei,    g_nei);
    cudaGetSymbolAddress((void**)&h16,    g_h16);
    cudaGetSymbolAddress((void**)&fz16,   g_fz16);
    cudaGetSymbolAddress((void**)&fh16,   g_fh16);
    cudaGetSymbolAddress((void**)&sumh16, g_sumh16);
    cudaGetSymbolAddress((void**)&sumg16, g_sumg16);
    cudaGetSymbolAddress((void**)&hU16,   g_hU16);
    cudaGetSymbolAddress((void**)&rx16,   g_rx16);
    cudaGetSymbolAddress((void**)&wz16,   g_wz16);
    cudaGetSymbolAddress((void**)&wh16,   g_wh16);
    cudaGetSymbolAddress((void**)&ur16,   g_ur16);
    cudaGetSymbolAddress((void**)&bh,     g_bh);
    cudaGetSymbolAddress((void**)&bl,     g_bl);

    cudaFuncSetAttribute((const void*)inv3_gemm,
                         cudaFuncAttributeMaxDynamicSharedMemorySize, SMEM_I3);
    cudaFuncSetAttribute((const void*)hU_gemm,
                         cudaFuncAttributeMaxDynamicSharedMemorySize, SMEM_HU16);
    cudaFuncSetAttribute((const void*)mode1f,
                         cudaFuncAttributeMaxDynamicSharedMemorySize, SMEM_M1F);
    cudaFuncSetAttribute((const void*)mode2_gemm,
                         cudaFuncAttributeMaxDynamicSharedMemorySize, SMEM_M0);

    const int gE128 = NM / 128;               // 625
    const int gE64  = NM / 64;                // 1250
    const int gV    = NNP / 128;              // 274

    // launch 1: all weight preps
    prep_all<<<1536, 256>>>(W_z, W_h, W_r, U_r, W_o, bh, bl, wz16, wh16, ur16);

    // launch 2: fused invariants (fz16, fh16, h16 step-1, rx16)
    inv3_gemm<<<gE128, 512, SMEM_I3>>>(fmess,
        bh+OFF_WZT, bl+OFF_WZT, bh+OFF_WHT, bl+OFF_WHT, bh+OFF_WR, bl+OFF_WR,
        b_z, b_h, b_ur, fz16, fh16, h16, rx16);

    // launches 3..14: 4 GRU steps
    for (int d = 1; d < DEPTH; ++d) {
        hU_gemm<<<gE128, 512, SMEM_HU16>>>(h16, ur16, hU16);
        gather_msgs<<<NM/4, dim3(64,4)>>>(h16, hU16, rx16, bgraph, sumh16, sumg16);
        mode1f<<<gE64, 512, SMEM_M1F>>>(sumh16, wz16, sumg16, wh16,
                                        fz16, fh16, out_h, h16, (d == DEPTH-1) ? 1 : 0);
    }

    gather_nodes<<<NN/4, dim3(64,4)>>>(out_h, agraph, nei);
    mode2_gemm<<<gV, 512, SMEM_M0>>>(fnode, IND, bh+OFF_WOT, bl+OFF_WOT,
                                     nei, HD, bh+OFF_WOB, bl+OFF_WOB,
                                     NN, b_o, mask, out_node);
}